// round 4
// baseline (speedup 1.0000x reference)
#include <cuda_runtime.h>
#include <math.h>

// ---------------- problem constants ----------------
#define SEQ   2048
#define HIDN  2048
#define NKH   16
#define NVH   32
#define DKD   128
#define DVD   128
#define CDIM  8192
#define VALD  4096
#define NCH   32      // chunks
#define CHK   64      // chunk size

typedef unsigned long long u64;

// ---------------- scratch (device globals; no cudaMalloc allowed) -------
__device__ float d_mixed[SEQ * CDIM];
__device__ float d_z   [SEQ * VALD];
__device__ float d_ab  [SEQ * 64];
__device__ float d_q   [SEQ * 2048];
__device__ float d_k   [SEQ * 2048];
__device__ float d_v   [SEQ * VALD];
__device__ float d_g   [NVH * SEQ];
__device__ float d_beta[NVH * SEQ];
__device__ float d_egl [NVH * NCH];
__device__ float d_u   [NVH * SEQ * DVD];
__device__ float d_kcd [NVH * SEQ * DKD];
__device__ float d_qg  [NVH * SEQ * DKD];
__device__ float d_kbar[NVH * SEQ * DKD];
__device__ float d_sc  [NVH * NCH * CHK * CHK];
__device__ float d_o   [NVH * SEQ * DVD];
__device__ float d_y   [SEQ * VALD];

// ---------------- packed f32x2 helpers ----------------
__device__ __forceinline__ u64 pack2(float lo, float hi) {
    u64 r; asm("mov.b64 %0,{%1,%2};" : "=l"(r) : "f"(lo), "f"(hi)); return r;
}
__device__ __forceinline__ float2 unpack2(u64 v) {
    float2 r; asm("mov.b64 {%0,%1},%2;" : "=f"(r.x), "=f"(r.y) : "l"(v)); return r;
}
__device__ __forceinline__ void fma2(u64& d, u64 a, u64 b) {
    asm("fma.rn.f32x2 %0,%1,%2,%0;" : "+l"(d) : "l"(a), "l"(b));
}

// ---------------- GEMM: C[M,N] = X[M,K] @ W[N,K]^T (fp32, FFMA2) --------
__global__ void __launch_bounds__(256) gemm_nt(const float* __restrict__ X,
                                               const float* __restrict__ W,
                                               float* __restrict__ C,
                                               int M, int N, int K) {
    __shared__ __align__(16) float As[16][128];
    __shared__ __align__(16) float Bs[16][128];
    const int t = threadIdx.x, bx = blockIdx.x, by = blockIdx.y;
    const int tx = t & 15, ty = t >> 4;
    const float* Xp = X + (size_t)(by * 128) * K;
    const float* Wp = W + (size_t)(bx * 128) * K;
    u64 acc[8][4];
#pragma unroll
    for (int i = 0; i < 8; i++)
#pragma unroll
        for (int j = 0; j < 4; j++) acc[i][j] = 0ull;

    for (int k0 = 0; k0 < K; k0 += 16) {
#pragma unroll
        for (int it = 0; it < 2; it++) {
            int f = t + 256 * it;
            int r = f >> 2, c4 = (f & 3) << 2;
            float4 xv = *(const float4*)(Xp + (size_t)r * K + k0 + c4);
            As[c4][r] = xv.x; As[c4 + 1][r] = xv.y; As[c4 + 2][r] = xv.z; As[c4 + 3][r] = xv.w;
            float4 wv = *(const float4*)(Wp + (size_t)r * K + k0 + c4);
            Bs[c4][r] = wv.x; Bs[c4 + 1][r] = wv.y; Bs[c4 + 2][r] = wv.z; Bs[c4 + 3][r] = wv.w;
        }
        __syncthreads();
#pragma unroll
        for (int kk = 0; kk < 16; kk++) {
            float4 a0 = *(const float4*)&As[kk][ty * 8];
            float4 a1 = *(const float4*)&As[kk][ty * 8 + 4];
            float4 b0 = *(const float4*)&Bs[kk][tx * 8];
            float4 b1 = *(const float4*)&Bs[kk][tx * 8 + 4];
            u64 bp[4] = {pack2(b0.x, b0.y), pack2(b0.z, b0.w),
                         pack2(b1.x, b1.y), pack2(b1.z, b1.w)};
            float av[8] = {a0.x, a0.y, a0.z, a0.w, a1.x, a1.y, a1.z, a1.w};
#pragma unroll
            for (int i = 0; i < 8; i++) {
                u64 ad = pack2(av[i], av[i]);
#pragma unroll
                for (int j = 0; j < 4; j++) fma2(acc[i][j], ad, bp[j]);
            }
        }
        __syncthreads();
    }
#pragma unroll
    for (int i = 0; i < 8; i++) {
        float2 p0 = unpack2(acc[i][0]), p1 = unpack2(acc[i][1]);
        float2 p2 = unpack2(acc[i][2]), p3 = unpack2(acc[i][3]);
        float* Cp = C + (size_t)(by * 128 + ty * 8 + i) * N + bx * 128 + tx * 8;
        *(float4*)Cp       = make_float4(p0.x, p0.y, p1.x, p1.y);
        *(float4*)(Cp + 4) = make_float4(p2.x, p2.y, p3.x, p3.y);
    }
}

// ---------------- a/b projection: d_ab[s][0:32]=x@Wa^T, [32:64]=x@Wb^T --
__global__ void __launch_bounds__(256) ab_gemm(const float* __restrict__ x,
                                               const float* __restrict__ Wa,
                                               const float* __restrict__ Wb) {
    __shared__ float Xs[32][64];
    __shared__ float Ws[32][64];
    const int t = threadIdx.x;
    const int s0 = blockIdx.x * 64;
    const int tx = t & 15, ty = t >> 4;
    float acc[4][4];
#pragma unroll
    for (int i = 0; i < 4; i++)
#pragma unroll
        for (int j = 0; j < 4; j++) acc[i][j] = 0.f;

    for (int k0 = 0; k0 < HIDN; k0 += 32) {
        for (int e = t; e < 2048; e += 256) {
            int r = e >> 5, c = e & 31;
            Xs[c][r] = x[(size_t)(s0 + r) * HIDN + k0 + c];
            const float* Wrow = (r < 32) ? (Wa + (size_t)r * HIDN) : (Wb + (size_t)(r - 32) * HIDN);
            Ws[c][r] = Wrow[k0 + c];
        }
        __syncthreads();
#pragma unroll
        for (int kk = 0; kk < 32; kk++) {
            float a[4], b[4];
#pragma unroll
            for (int i = 0; i < 4; i++) { a[i] = Xs[kk][ty * 4 + i]; b[i] = Ws[kk][tx * 4 + i]; }
#pragma unroll
            for (int i = 0; i < 4; i++)
#pragma unroll
                for (int j = 0; j < 4; j++) acc[i][j] += a[i] * b[j];
        }
        __syncthreads();
    }
#pragma unroll
    for (int i = 0; i < 4; i++)
#pragma unroll
        for (int j = 0; j < 4; j++)
            d_ab[(size_t)(s0 + ty * 4 + i) * 64 + tx * 4 + j] = acc[i][j];
}

// ---------------- causal depthwise conv(K=4) + SiLU + split -------------
__global__ void conv_silu(const float* __restrict__ cw) {
    int c = blockIdx.x * 256 + threadIdx.x;
    int s = blockIdx.y;
    float w0 = cw[c * 4], w1 = cw[c * 4 + 1], w2 = cw[c * 4 + 2], w3 = cw[c * 4 + 3];
    float acc = d_mixed[(size_t)s * CDIM + c] * w3;
    if (s >= 1) acc += d_mixed[(size_t)(s - 1) * CDIM + c] * w2;
    if (s >= 2) acc += d_mixed[(size_t)(s - 2) * CDIM + c] * w1;
    if (s >= 3) acc += d_mixed[(size_t)(s - 3) * CDIM + c] * w0;
    float r = acc / (1.f + expf(-acc));
    if (c < 2048)      d_q[(size_t)s * 2048 + c] = r;
    else if (c < 4096) d_k[(size_t)s * 2048 + (c - 2048)] = r;
    else               d_v[(size_t)s * 4096 + (c - 4096)] = r;
}

// ---------------- l2norm on q (with DK^-0.5) and k -----------------------
__global__ void l2norm_kernel() {
    int b = blockIdx.x, t = threadIdx.x;          // 128 threads per block
    float* buf = (blockIdx.y == 0) ? d_q : d_k;
    size_t idx = (size_t)b * 128 + t;
    float v = buf[idx];
    float ss = v * v;
#pragma unroll
    for (int o = 16; o > 0; o >>= 1) ss += __shfl_xor_sync(~0u, ss, o);
    __shared__ float ws[4];
    if ((t & 31) == 0) ws[t >> 5] = ss;
    __syncthreads();
    ss = (ws[0] + ws[1]) + (ws[2] + ws[3]);
    float sc = rsqrtf(ss + 1e-6f);
    if (blockIdx.y == 0) sc *= 0.08838834764831845f;   // DK^-0.5
    buf[idx] = v * sc;
}

// ---------------- gate: g (chunk-local cumsum), beta, exp(g_last) --------
__global__ void gate_kernel(const float* __restrict__ dt_bias,
                            const float* __restrict__ A_log) {
    int h = blockIdx.x, n = blockIdx.y, i = threadIdx.x;  // 64 threads
    int s = n * CHK + i;
    float a = d_ab[(size_t)s * 64 + h];
    float b = d_ab[(size_t)s * 64 + 32 + h];
    float xx = a + dt_bias[h];
    float sp = fmaxf(xx, 0.f) + log1pf(expf(-fabsf(xx)));
    float gv = -expf(A_log[h]) * sp;
    float beta = 1.f / (1.f + expf(-b));
    int lane = i & 31;
#pragma unroll
    for (int o = 1; o < 32; o <<= 1) {
        float nv = __shfl_up_sync(~0u, gv, o);
        if (lane >= o) gv += nv;
    }
    __shared__ float carry;
    if (i == 31) carry = gv;
    __syncthreads();
    if (i >= 32) gv += carry;
    d_g[(size_t)h * SEQ + s] = gv;
    d_beta[(size_t)h * SEQ + s] = beta;
    if (i == 63) d_egl[h * NCH + n] = expf(gv);
}

// ---------------- intra-chunk: A, UT transform, u, kcd, scores, qg, kbar -
__global__ void __launch_bounds__(256) intra_kernel() {
    extern __shared__ float sm[];
    float* sq  = sm;              // 64*128
    float* sk  = sm + 8192;       // 64*128
    float* sv  = sm + 16384;      // 64*128
    float* sA  = sm + 24576;      // 64*64
    float* sA2 = sm + 28672;      // 64*64
    float* sg  = sm + 32768;      // 64
    float* sb  = sm + 32832;      // 64
    float* scv = sm + 32896;      // 64
    float* sP  = sm + 32960;      // 256

    const int n = blockIdx.x, h = blockIdx.y, kvh = h >> 1, t = threadIdx.x;
    const int sbase = n * CHK;

    for (int e = t; e < 2048; e += 256) {
        int i = e >> 5, d = (e & 31) << 2;
        int s = sbase + i;
        *(float4*)&sq[i * 128 + d] = *(const float4*)&d_q[((size_t)s * NKH + kvh) * 128 + d];
        *(float4*)&sk[i * 128 + d] = *(const float4*)&d_k[((size_t)s * NKH + kvh) * 128 + d];
        *(float4*)&sv[i * 128 + d] = *(const float4*)&d_v[((size_t)s * NVH + h) * 128 + d];
    }
    if (t < 64) {
        sg[t] = d_g[(size_t)h * SEQ + sbase + t];
        sb[t] = d_beta[(size_t)h * SEQ + sbase + t];
    }
    __syncthreads();

    const int i0 = (t >> 4) << 2, j0 = (t & 15) << 2;

    // ---- A[i][j] = -(kb_i . k_j) * exp(g_i - g_j) for i>j ----
    {
        float acc[4][4];
#pragma unroll
        for (int ii = 0; ii < 4; ii++)
#pragma unroll
            for (int jj = 0; jj < 4; jj++) acc[ii][jj] = 0.f;
        for (int kk = 0; kk < 128; kk += 4) {
            float4 ar[4], br[4];
#pragma unroll
            for (int ii = 0; ii < 4; ii++) {
                ar[ii] = *(const float4*)&sk[(i0 + ii) * 128 + kk];
                br[ii] = *(const float4*)&sk[(j0 + ii) * 128 + kk];
            }
#pragma unroll
            for (int ii = 0; ii < 4; ii++)
#pragma unroll
                for (int jj = 0; jj < 4; jj++)
                    acc[ii][jj] += ar[ii].x * br[jj].x + ar[ii].y * br[jj].y +
                                   ar[ii].z * br[jj].z + ar[ii].w * br[jj].w;
        }
#pragma unroll
        for (int ii = 0; ii < 4; ii++)
#pragma unroll
            for (int jj = 0; jj < 4; jj++) {
                int i = i0 + ii, j = j0 + jj;
                sA[i * 64 + j] = (i > j) ? -sb[i] * acc[ii][jj] * expf(sg[i] - sg[j]) : 0.f;
            }
    }
    __syncthreads();

    // ---- UT transform (forward substitution), 4-way partial parallel ----
    {
        int j = t & 63, pt = t >> 6;
        for (int i = 1; i < 64; i++) {
            float p = 0.f;
            if (j < i)
                for (int kk = j + 1 + pt; kk < i; kk += 4)
                    p += sA[i * 64 + kk] * sA[kk * 64 + j];
            sP[t] = p;
            __syncthreads();
            if (t < i) sA[i * 64 + t] += sP[t] + sP[64 + t] + sP[128 + t] + sP[192 + t];
            __syncthreads();
        }
    }

    // ---- scale v by beta; c[k] = beta*exp(g) ----
    for (int e = t; e < 8192; e += 256) sv[e] *= sb[e >> 7];
    if (t < 64) scv[t] = sb[t] * expf(sg[t]);
    __syncthreads();

    const int dv = t & 127, half = t >> 7;

    // ---- u = (I + A) @ vb ----
    for (int ii = 0; ii < 32; ii++) {
        int i = half * 32 + ii;
        float a = sv[i * 128 + dv];
        for (int kk = 0; kk < i; kk++) a += sA[i * 64 + kk] * sv[kk * 128 + dv];
        d_u[((size_t)h * SEQ + sbase + i) * 128 + dv] = a;
    }
    // ---- A2 = A * diag(c) (column scale) ----
    for (int e = t; e < 4096; e += 256) sA2[e] = sA[e] * scv[e & 63];
    __syncthreads();

    // ---- kcd = (I+A) @ (kb * e^g);  qg = q*e^g;  kbar = k*e^(gl-g) ----
    const float gl = sg[63];
    for (int ii = 0; ii < 32; ii++) {
        int i = half * 32 + ii;
        float eg  = expf(sg[i]);
        float egr = expf(gl - sg[i]);
        float a = sk[i * 128 + dv] * scv[i];
        for (int kk = 0; kk < i; kk++) a += sA2[i * 64 + kk] * sk[kk * 128 + dv];
        size_t rb = ((size_t)h * SEQ + sbase + i) * 128 + dv;
        d_kcd[rb]  = a;
        d_qg[rb]   = sq[i * 128 + dv] * eg;
        d_kbar[rb] = sk[i * 128 + dv] * egr;
    }

    // ---- scores[i][j] = (q_i . k_j) * exp(g_i - g_j), i >= j ----
    {
        float acc[4][4];
#pragma unroll
        for (int ii = 0; ii < 4; ii++)
#pragma unroll
            for (int jj = 0; jj < 4; jj++) acc[ii][jj] = 0.f;
        for (int kk = 0; kk < 128; kk += 4) {
            float4 ar[4], br[4];
#pragma unroll
            for (int ii = 0; ii < 4; ii++) {
                ar[ii] = *(const float4*)&sq[(i0 + ii) * 128 + kk];
                br[ii] = *(const float4*)&sk[(j0 + ii) * 128 + kk];
            }
#pragma unroll
            for (int ii = 0; ii < 4; ii++)
#pragma unroll
                for (int jj = 0; jj < 4; jj++)
                    acc[ii][jj] += ar[ii].x * br[jj].x + ar[ii].y * br[jj].y +
                                   ar[ii].z * br[jj].z + ar[ii].w * br[jj].w;
        }
#pragma unroll
        for (int ii = 0; ii < 4; ii++)
#pragma unroll
            for (int jj = 0; jj < 4; jj++) {
                int i = i0 + ii, j = j0 + jj;
                d_sc[((size_t)h * NCH + n) * 4096 + i * 64 + j] =
                    (i >= j) ? acc[ii][jj] * expf(sg[i] - sg[j]) : 0.f;
            }
    }
}

// ---------------- sequential inter-chunk scan (per head, per DV-slice) ---
__global__ void __launch_bounds__(512) scan_kernel() {
    extern __shared__ float sm[];
    float* st  = sm;           // 128*32 state slice
    float* skc = sm + 4096;    // 64*128 kcd
    float* sqg = sm + 12288;   // 64*128 qg
    float* skb = sm + 20480;   // 64*128 kbar
    float* ssc = sm + 28672;   // 64*64 scores
    float* svn = sm + 32768;   // 64*32 v_new
    float* su  = sm + 34816;   // 64*32 u slice

    const int h = blockIdx.x >> 2, sl = blockIdx.x & 3, t = threadIdx.x;
    const int dv0 = sl * 32;

    for (int e = t; e < 4096; e += 512) st[e] = 0.f;

    for (int n = 0; n < NCH; n++) {
        const size_t rb = ((size_t)h * SEQ + n * CHK) * 128;
        for (int e = t; e < 2048; e += 512) {
            ((float4*)skc)[e] = ((const float4*)(d_kcd + rb))[e];
            ((float4*)sqg)[e] = ((const float4*)(d_qg + rb))[e];
            ((float4*)skb)[e] = ((const float4*)(d_kbar + rb))[e];
        }
        const size_t scb = ((size_t)h * NCH + n) * 4096;
        for (int e = t; e < 1024; e += 512)
            ((float4*)ssc)[e] = ((const float4*)(d_sc + scb))[e];
        {
            int e = t;  // exactly 512 float4s
            int i = e >> 3, q4 = e & 7;
            ((float4*)su)[e] = *(const float4*)&d_u[rb + (size_t)i * 128 + dv0 + q4 * 4];
        }
        __syncthreads();

        const float egl = d_egl[h * NCH + n];

        // v_new = u - kcd @ state
#pragma unroll
        for (int r = 0; r < 2; r++) {
            int idx = t + 512 * r;
            int i = idx >> 4, dp = (idx & 15) << 1;
            u64 a = *(u64*)&su[i * 32 + dp];
            for (int dk = 0; dk < 128; dk++) {
                float kv = -skc[i * 128 + dk];
                fma2(a, pack2(kv, kv), *(u64*)&st[dk * 32 + dp]);
            }
            *(u64*)&svn[i * 32 + dp] = a;
        }
        __syncthreads();

        // o = qg @ state + scores @ v_new
#pragma unroll
        for (int r = 0; r < 2; r++) {
            int idx = t + 512 * r;
            int i = idx >> 4, dp = (idx & 15) << 1;
            u64 a = 0ull;
            for (int dk = 0; dk < 128; dk++) {
                float qv = sqg[i * 128 + dk];
                fma2(a, pack2(qv, qv), *(u64*)&st[dk * 32 + dp]);
            }
            for (int j = 0; j <= i; j++) {
                float sv_ = ssc[i * 64 + j];
                fma2(a, pack2(sv_, sv_), *(u64*)&svn[j * 32 + dp]);
            }
            float2 p = unpack2(a);
            *(float2*)&d_o[rb + (size_t)i * 128 + dv0 + dp] = p;
        }
        __syncthreads();

        // state = state*egl + kbar^T @ v_new
#pragma unroll
        for (int r = 0; r < 4; r++) {
            int idx = t + 512 * r;
            int dk = idx >> 4, dp = (idx & 15) << 1;
            u64 a = pack2(st[dk * 32 + dp] * egl, st[dk * 32 + dp + 1] * egl);
            for (int i = 0; i < 64; i++) {
                float kb = skb[i * 128 + dk];
                fma2(a, pack2(kb, kb), *(u64*)&svn[i * 32 + dp]);
            }
            float2 p = unpack2(a);
            st[dk * 32 + dp] = p.x;
            st[dk * 32 + dp + 1] = p.y;
        }
        __syncthreads();
    }
}

// ---------------- RMSNorm + z-gate epilogue ------------------------------
__global__ void rms_kernel(const float* __restrict__ norm_w) {
    int b = blockIdx.x;
    int s = b >> 5, h = b & 31, t = threadIdx.x;   // 128 threads
    float v = d_o[((size_t)h * SEQ + s) * 128 + t];
    float ss = v * v;
#pragma unroll
    for (int o = 16; o > 0; o >>= 1) ss += __shfl_xor_sync(~0u, ss, o);
    __shared__ float ws[4];
    if ((t & 31) == 0) ws[t >> 5] = ss;
    __syncthreads();
    ss = (ws[0] + ws[1]) + (ws[2] + ws[3]);
    float r = rsqrtf(ss * (1.f / 128.f) + 1e-6f);
    float z = d_z[(size_t)s * VALD + h * 128 + t];
    float sz = z / (1.f + expf(-z));
    d_y[(size_t)s * VALD + h * 128 + t] = v * r * norm_w[t] * sz;
}

// ---------------- launch ---------------------------------------------------
extern "C" void kernel_launch(void* const* d_in, const int* in_sizes, int n_in,
                              void* d_out, int out_size) {
    const float* x       = (const float*)d_in[0];
    const float* W_qkv   = (const float*)d_in[1];
    const float* W_z     = (const float*)d_in[2];
    const float* W_a     = (const float*)d_in[3];
    const float* W_b     = (const float*)d_in[4];
    const float* conv_w  = (const float*)d_in[5];
    const float* dt_bias = (const float*)d_in[6];
    const float* A_log   = (const float*)d_in[7];
    const float* norm_w  = (const float*)d_in[8];
    const float* W_out   = (const float*)d_in[9];
    float* out = (float*)d_out;

    void *p_mixed, *p_z, *p_y;
    cudaGetSymbolAddress(&p_mixed, d_mixed);
    cudaGetSymbolAddress(&p_z, d_z);
    cudaGetSymbolAddress(&p_y, d_y);

    const int INTRA_SMEM = 33216 * 4;
    const int SCAN_SMEM  = 36864 * 4;
    cudaFuncSetAttribute(intra_kernel, cudaFuncAttributeMaxDynamicSharedMemorySize, INTRA_SMEM);
    cudaFuncSetAttribute(scan_kernel,  cudaFuncAttributeMaxDynamicSharedMemorySize, SCAN_SMEM);

    // projections
    gemm_nt<<<dim3(CDIM / 128, SEQ / 128), 256>>>(x, W_qkv, (float*)p_mixed, SEQ, CDIM, HIDN);
    gemm_nt<<<dim3(VALD / 128, SEQ / 128), 256>>>(x, W_z,   (float*)p_z,    SEQ, VALD, HIDN);
    ab_gemm<<<SEQ / 64, 256>>>(x, W_a, W_b);

    // conv + silu + split
    conv_silu<<<dim3(CDIM / 256, SEQ), 256>>>(conv_w);

    // l2norm q (scaled) and k
    l2norm_kernel<<<dim3(SEQ * NKH, 2), 128>>>();

    // gates
    gate_kernel<<<dim3(NVH, NCH), 64>>>(dt_bias, A_log);

    // intra-chunk precompute
    intra_kernel<<<dim3(NCH, NVH), 256, INTRA_SMEM>>>();

    // sequential inter-chunk scan (32 heads x 4 DV-slices)
    scan_kernel<<<NVH * 4, 512, SCAN_SMEM>>>();

    // rmsnorm + gate epilogue
    rms_kernel<<<SEQ * NVH, 128>>>(norm_w);

    // output projection
    gemm_nt<<<dim3(HIDN / 128, SEQ / 128), 256>>>((const float*)p_y, W_out, out, SEQ, HIDN, VALD);
}

// round 8
// speedup vs baseline: 1.6063x; 1.6063x over previous
#include <cuda_runtime.h>
#include <cuda_bf16.h>
#include <math.h>

// ---------------- problem constants ----------------
#define SEQ   2048
#define HIDN  2048
#define NKH   16
#define NVH   32
#define DKD   128
#define DVD   128
#define CDIM  8192
#define VALD  4096
#define NCH   32      // chunks
#define CHK   64      // chunk size

typedef unsigned long long u64;
typedef unsigned int u32;

// single dynamic smem symbol shared by all kernels
extern __shared__ __align__(16) char dyn_smem[];

// ---------------- scratch (device globals; no cudaMalloc allowed) -------
__device__ float d_mixed[SEQ * CDIM];
__device__ float d_z   [SEQ * VALD];
__device__ float d_ab  [SEQ * 64];
__device__ float d_q   [SEQ * 2048];
__device__ float d_k   [SEQ * 2048];
__device__ float d_v   [SEQ * VALD];
__device__ float d_g   [NVH * SEQ];
__device__ float d_beta[NVH * SEQ];
__device__ float d_egl [NVH * NCH];
__device__ float d_u   [NVH * SEQ * DVD];
__device__ float d_kcd [NVH * SEQ * DKD];
__device__ float d_qg  [NVH * SEQ * DKD];
__device__ float d_kbar[NVH * SEQ * DKD];
__device__ float d_sc  [NVH * NCH * CHK * CHK];
__device__ float d_o   [NVH * SEQ * DVD];

// bf16 split buffers for tensor-core GEMMs
__device__ __nv_bfloat16 g_xh  [SEQ * HIDN],  g_xl  [SEQ * HIDN];
__device__ __nv_bfloat16 g_qkh [CDIM * HIDN], g_qkl [CDIM * HIDN];
__device__ __nv_bfloat16 g_wzh [VALD * HIDN], g_wzl [VALD * HIDN];
__device__ __nv_bfloat16 g_woh [HIDN * VALD], g_wol [HIDN * VALD];
__device__ __nv_bfloat16 g_yh  [SEQ * VALD],  g_yl  [SEQ * VALD];

// ---------------- packed f32x2 helpers ----------------
__device__ __forceinline__ u64 pack2(float lo, float hi) {
    u64 r; asm("mov.b64 %0,{%1,%2};" : "=l"(r) : "f"(lo), "f"(hi)); return r;
}
__device__ __forceinline__ float2 unpack2(u64 v) {
    float2 r; asm("mov.b64 {%0,%1},%2;" : "=f"(r.x), "=f"(r.y) : "l"(v)); return r;
}
__device__ __forceinline__ void fma2(u64& d, u64 a, u64 b) {
    asm("fma.rn.f32x2 %0,%1,%2,%0;" : "+l"(d) : "l"(a), "l"(b));
}

// ---------------- fp32 -> bf16 hi/lo split ----------------
__global__ void __launch_bounds__(256) cvt_split(const float* __restrict__ s,
                                                 __nv_bfloat16* __restrict__ h,
                                                 __nv_bfloat16* __restrict__ l,
                                                 int n4) {
    int i = blockIdx.x * 256 + threadIdx.x;
    if (i >= n4) return;
    float4 v = ((const float4*)s)[i];
    __nv_bfloat16 h0 = __float2bfloat16(v.x);
    __nv_bfloat16 h1 = __float2bfloat16(v.y);
    __nv_bfloat16 h2 = __float2bfloat16(v.z);
    __nv_bfloat16 h3 = __float2bfloat16(v.w);
    __nv_bfloat162* hp = (__nv_bfloat162*)h;
    __nv_bfloat162* lp = (__nv_bfloat162*)l;
    hp[2 * i]     = __nv_bfloat162(h0, h1);
    hp[2 * i + 1] = __nv_bfloat162(h2, h3);
    lp[2 * i]     = __nv_bfloat162(__float2bfloat16(v.x - __bfloat162float(h0)),
                                   __float2bfloat16(v.y - __bfloat162float(h1)));
    lp[2 * i + 1] = __nv_bfloat162(__float2bfloat16(v.z - __bfloat162float(h2)),
                                   __float2bfloat16(v.w - __bfloat162float(h3)));
}

// ---------------- warp-MMA bf16 GEMM: C[M,N] = A[M,K] @ B[N,K]^T --------
// Split-bf16 3-term: C = Ah*Bh + Ah*Bl + Al*Bh, fp32 accum.
// CTA tile 128x128, 8 warps (4M x 2N), warp tile 32x64 (m16n8k16).
// BK=32 double-buffered cp.async pipeline; smem rows padded to 40 bf16.
#define BKC   32
#define SROW  40                         // bf16 elems per smem row (80B)
#define TILE_W (128 * SROW)              // bf16 elems per tile
#define STAGE_W (4 * TILE_W)             // 4 tiles (Ah,Al,Bh,Bl)
#define GEMM_SMEM_BYTES (2 * STAGE_W * 2)

__device__ __forceinline__ void mma_bf16(float* c, const u32* a, const u32* b) {
    asm volatile(
        "mma.sync.aligned.m16n8k16.row.col.f32.bf16.bf16.f32 "
        "{%0,%1,%2,%3}, {%4,%5,%6,%7}, {%8,%9}, {%0,%1,%2,%3};"
        : "+f"(c[0]), "+f"(c[1]), "+f"(c[2]), "+f"(c[3])
        : "r"(a[0]), "r"(a[1]), "r"(a[2]), "r"(a[3]), "r"(b[0]), "r"(b[1]));
}

__global__ void __launch_bounds__(256, 1)
tc_gemm(const __nv_bfloat16* __restrict__ Ah, const __nv_bfloat16* __restrict__ Al,
        const __nv_bfloat16* __restrict__ Bh, const __nv_bfloat16* __restrict__ Bl,
        float* __restrict__ C, int N, int K) {
    __nv_bfloat16* sm = (__nv_bfloat16*)dyn_smem;

    const int t = threadIdx.x, lane = t & 31, wid = t >> 5;
    const int wm = wid & 3, wn = wid >> 2;          // 4 M-warps x 2 N-warps
    const int bx = blockIdx.x, by = blockIdx.y;
    const int NCHUNK = K / BKC;

    const __nv_bfloat16* srcs[4] = {
        Ah + (size_t)by * 128 * K, Al + (size_t)by * 128 * K,
        Bh + (size_t)bx * 128 * K, Bl + (size_t)bx * 128 * K};

    auto load_chunk = [&](int n, int s) {
#pragma unroll
        for (int tile = 0; tile < 4; tile++) {
#pragma unroll
            for (int j = 0; j < 2; j++) {
                int f = t + 256 * j;                 // 0..511
                int row = f >> 2, c = f & 3;         // 128 rows x 4 x 16B
                const __nv_bfloat16* g = srcs[tile] + (size_t)row * K + n * BKC + c * 8;
                u32 d;
                asm("{ .reg .u64 tt; cvta.to.shared.u64 tt, %1; cvt.u32.u64 %0, tt; }"
                    : "=r"(d)
                    : "l"(sm + s * STAGE_W + tile * TILE_W + row * SROW + c * 8));
                asm volatile("cp.async.cg.shared.global [%0], [%1], 16;"
                             :: "r"(d), "l"(g));
            }
        }
        asm volatile("cp.async.commit_group;" ::: "memory");
    };

    float acc[2][8][4];
#pragma unroll
    for (int mt = 0; mt < 2; mt++)
#pragma unroll
        for (int nt = 0; nt < 8; nt++)
#pragma unroll
            for (int e = 0; e < 4; e++) acc[mt][nt][e] = 0.f;

    const int gid = lane >> 2, tig = lane & 3;

    load_chunk(0, 0);

    for (int n = 0; n < NCHUNK; n++) {
        int s = n & 1;
        asm volatile("cp.async.wait_group 0;" ::: "memory");
        __syncthreads();
        if (n + 1 < NCHUNK) load_chunk(n + 1, 1 - s);

        const __nv_bfloat16* sAh = sm + s * STAGE_W;
        const __nv_bfloat16* sAl = sAh + TILE_W;
        const __nv_bfloat16* sBh = sAh + 2 * TILE_W;
        const __nv_bfloat16* sBl = sAh + 3 * TILE_W;

#pragma unroll
        for (int k16 = 0; k16 < 2; k16++) {
            const int k0 = k16 * 16;
            u32 ah[2][4], al[2][4], bh[8][2], bl[8][2];
#pragma unroll
            for (int mt = 0; mt < 2; mt++) {
                int r0 = wm * 32 + mt * 16 + gid;
                const __nv_bfloat16* p = sAh + r0 * SROW + k0 + tig * 2;
                ah[mt][0] = *(const u32*)p;
                ah[mt][1] = *(const u32*)(p + 8 * SROW);
                ah[mt][2] = *(const u32*)(p + 8);
                ah[mt][3] = *(const u32*)(p + 8 * SROW + 8);
                const __nv_bfloat16* q = sAl + r0 * SROW + k0 + tig * 2;
                al[mt][0] = *(const u32*)q;
                al[mt][1] = *(const u32*)(q + 8 * SROW);
                al[mt][2] = *(const u32*)(q + 8);
                al[mt][3] = *(const u32*)(q + 8 * SROW + 8);
            }
#pragma unroll
            for (int nt = 0; nt < 8; nt++) {
                int c0 = wn * 64 + nt * 8 + gid;
                const __nv_bfloat16* p = sBh + c0 * SROW + k0 + tig * 2;
                bh[nt][0] = *(const u32*)p;
                bh[nt][1] = *(const u32*)(p + 8);
                const __nv_bfloat16* q = sBl + c0 * SROW + k0 + tig * 2;
                bl[nt][0] = *(const u32*)q;
                bl[nt][1] = *(const u32*)(q + 8);
            }
#pragma unroll
            for (int mt = 0; mt < 2; mt++)
#pragma unroll
                for (int nt = 0; nt < 8; nt++) {
                    mma_bf16(acc[mt][nt], ah[mt], bh[nt]);
                    mma_bf16(acc[mt][nt], ah[mt], bl[nt]);
                    mma_bf16(acc[mt][nt], al[mt], bh[nt]);
                }
        }
        __syncthreads();
    }

    // epilogue: c0,c1 at (row=gid, col=2*tig..+1); c2,c3 at row gid+8
#pragma unroll
    for (int mt = 0; mt < 2; mt++) {
        int rbase = by * 128 + wm * 32 + mt * 16;
#pragma unroll
        for (int nt = 0; nt < 8; nt++) {
            int cbase = bx * 128 + wn * 64 + nt * 8 + tig * 2;
            float* p0 = C + (size_t)(rbase + gid) * N + cbase;
            float* p1 = C + (size_t)(rbase + gid + 8) * N + cbase;
            p0[0] = acc[mt][nt][0]; p0[1] = acc[mt][nt][1];
            p1[0] = acc[mt][nt][2]; p1[1] = acc[mt][nt][3];
        }
    }
}

// ---------------- a/b projection: d_ab[s][0:32]=x@Wa^T, [32:64]=x@Wb^T --
__global__ void __launch_bounds__(256) ab_gemm(const float* __restrict__ x,
                                               const float* __restrict__ Wa,
                                               const float* __restrict__ Wb) {
    __shared__ float Xs[32][64];
    __shared__ float Ws[32][64];
    const int t = threadIdx.x;
    const int s0 = blockIdx.x * 64;
    const int tx = t & 15, ty = t >> 4;
    float acc[4][4];
#pragma unroll
    for (int i = 0; i < 4; i++)
#pragma unroll
        for (int j = 0; j < 4; j++) acc[i][j] = 0.f;

    for (int k0 = 0; k0 < HIDN; k0 += 32) {
        for (int e = t; e < 2048; e += 256) {
            int r = e >> 5, c = e & 31;
            Xs[c][r] = x[(size_t)(s0 + r) * HIDN + k0 + c];
            const float* Wrow = (r < 32) ? (Wa + (size_t)r * HIDN) : (Wb + (size_t)(r - 32) * HIDN);
            Ws[c][r] = Wrow[k0 + c];
        }
        __syncthreads();
#pragma unroll
        for (int kk = 0; kk < 32; kk++) {
            float a[4], b[4];
#pragma unroll
            for (int i = 0; i < 4; i++) { a[i] = Xs[kk][ty * 4 + i]; b[i] = Ws[kk][tx * 4 + i]; }
#pragma unroll
            for (int i = 0; i < 4; i++)
#pragma unroll
                for (int j = 0; j < 4; j++) acc[i][j] += a[i] * b[j];
        }
        __syncthreads();
    }
#pragma unroll
    for (int i = 0; i < 4; i++)
#pragma unroll
        for (int j = 0; j < 4; j++)
            d_ab[(size_t)(s0 + ty * 4 + i) * 64 + tx * 4 + j] = acc[i][j];
}

// ---------------- causal depthwise conv(K=4) + SiLU + split (sliding) ---
__global__ void __launch_bounds__(256) conv_silu(const float* __restrict__ cw) {
    int c   = blockIdx.x * 256 + threadIdx.x;   // channel
    int seg = blockIdx.y;                       // 8 segments of 256
    float w0 = cw[c * 4], w1 = cw[c * 4 + 1], w2 = cw[c * 4 + 2], w3 = cw[c * 4 + 3];
    int s0 = seg * 256;
    float xm3 = (s0 >= 3) ? d_mixed[(size_t)(s0 - 3) * CDIM + c] : 0.f;
    float xm2 = (s0 >= 2) ? d_mixed[(size_t)(s0 - 2) * CDIM + c] : 0.f;
    float xm1 = (s0 >= 1) ? d_mixed[(size_t)(s0 - 1) * CDIM + c] : 0.f;
    for (int i = 0; i < 256; i++) {
        int s = s0 + i;
        float xs = d_mixed[(size_t)s * CDIM + c];
        float acc = w0 * xm3 + w1 * xm2 + w2 * xm1 + w3 * xs;
        float r = acc / (1.f + expf(-acc));
        if (c < 2048)      d_q[(size_t)s * 2048 + c] = r;
        else if (c < 4096) d_k[(size_t)s * 2048 + (c - 2048)] = r;
        else               d_v[(size_t)s * 4096 + (c - 4096)] = r;
        xm3 = xm2; xm2 = xm1; xm1 = xs;
    }
}

// ---------------- l2norm on q (with DK^-0.5) and k -----------------------
__global__ void l2norm_kernel() {
    int b = blockIdx.x, t = threadIdx.x;          // 128 threads per block
    float* buf = (blockIdx.y == 0) ? d_q : d_k;
    size_t idx = (size_t)b * 128 + t;
    float v = buf[idx];
    float ss = v * v;
#pragma unroll
    for (int o = 16; o > 0; o >>= 1) ss += __shfl_xor_sync(~0u, ss, o);
    __shared__ float ws[4];
    if ((t & 31) == 0) ws[t >> 5] = ss;
    __syncthreads();
    ss = (ws[0] + ws[1]) + (ws[2] + ws[3]);
    float sc = rsqrtf(ss + 1e-6f);
    if (blockIdx.y == 0) sc *= 0.08838834764831845f;   // DK^-0.5
    buf[idx] = v * sc;
}

// ---------------- gate: g (chunk-local cumsum), beta, exp(g_last) --------
__global__ void gate_kernel(const float* __restrict__ dt_bias,
                            const float* __restrict__ A_log) {
    int h = blockIdx.x, n = blockIdx.y, i = threadIdx.x;  // 64 threads
    int s = n * CHK + i;
    float a = d_ab[(size_t)s * 64 + h];
    float b = d_ab[(size_t)s * 64 + 32 + h];
    float xx = a + dt_bias[h];
    float sp = fmaxf(xx, 0.f) + log1pf(expf(-fabsf(xx)));
    float gv = -expf(A_log[h]) * sp;
    float beta = 1.f / (1.f + expf(-b));
    int lane = i & 31;
#pragma unroll
    for (int o = 1; o < 32; o <<= 1) {
        float nv = __shfl_up_sync(~0u, gv, o);
        if (lane >= o) gv += nv;
    }
    __shared__ float carry;
    if (i == 31) carry = gv;
    __syncthreads();
    if (i >= 32) gv += carry;
    d_g[(size_t)h * SEQ + s] = gv;
    d_beta[(size_t)h * SEQ + s] = beta;
    if (i == 63) d_egl[h * NCH + n] = expf(gv);
}

// ---------------- intra-chunk: A, UT transform, u, kcd, scores, qg, kbar -
__global__ void __launch_bounds__(256) intra_kernel() {
    float* sm = (float*)dyn_smem;
    float* sq  = sm;              // 64*128
    float* sk  = sm + 8192;       // 64*128
    float* sv  = sm + 16384;      // 64*128
    float* sA  = sm + 24576;      // 64*64
    float* sA2 = sm + 28672;      // 64*64
    float* sg  = sm + 32768;      // 64
    float* sb  = sm + 32832;      // 64
    float* scv = sm + 32896;      // 64
    float* sP  = sm + 32960;      // 256

    const int n = blockIdx.x, h = blockIdx.y, kvh = h >> 1, t = threadIdx.x;
    const int sbase = n * CHK;

    for (int e = t; e < 2048; e += 256) {
        int i = e >> 5, d = (e & 31) << 2;
        int s = sbase + i;
        *(float4*)&sq[i * 128 + d] = *(const float4*)&d_q[((size_t)s * NKH + kvh) * 128 + d];
        *(float4*)&sk[i * 128 + d] = *(const float4*)&d_k[((size_t)s * NKH + kvh) * 128 + d];
        *(float4*)&sv[i * 128 + d] = *(const float4*)&d_v[((size_t)s * NVH + h) * 128 + d];
    }
    if (t < 64) {
        sg[t] = d_g[(size_t)h * SEQ + sbase + t];
        sb[t] = d_beta[(size_t)h * SEQ + sbase + t];
    }
    __syncthreads();

    const int i0 = (t >> 4) << 2, j0 = (t & 15) << 2;

    // ---- A[i][j] = -(kb_i . k_j) * exp(g_i - g_j) for i>j ----
    {
        float acc[4][4];
#pragma unroll
        for (int ii = 0; ii < 4; ii++)
#pragma unroll
            for (int jj = 0; jj < 4; jj++) acc[ii][jj] = 0.f;
        for (int kk = 0; kk < 128; kk += 4) {
            float4 ar[4], br[4];
#pragma unroll
            for (int ii = 0; ii < 4; ii++) {
                ar[ii] = *(const float4*)&sk[(i0 + ii) * 128 + kk];
                br[ii] = *(const float4*)&sk[(j0 + ii) * 128 + kk];
            }
#pragma unroll
            for (int ii = 0; ii < 4; ii++)
#pragma unroll
                for (int jj = 0; jj < 4; jj++)
                    acc[ii][jj] += ar[ii].x * br[jj].x + ar[ii].y * br[jj].y +
                                   ar[ii].z * br[jj].z + ar[ii].w * br[jj].w;
        }
#pragma unroll
        for (int ii = 0; ii < 4; ii++)
#pragma unroll
            for (int jj = 0; jj < 4; jj++) {
                int i = i0 + ii, j = j0 + jj;
                sA[i * 64 + j] = (i > j) ? -sb[i] * acc[ii][jj] * expf(sg[i] - sg[j]) : 0.f;
            }
    }
    __syncthreads();

    // ---- UT transform (forward substitution), 4-way partial parallel ----
    {
        int j = t & 63, pt = t >> 6;
        for (int i = 1; i < 64; i++) {
            float p = 0.f;
            if (j < i)
                for (int kk = j + 1 + pt; kk < i; kk += 4)
                    p += sA[i * 64 + kk] * sA[kk * 64 + j];
            sP[t] = p;
            __syncthreads();
            if (t < i) sA[i * 64 + t] += sP[t] + sP[64 + t] + sP[128 + t] + sP[192 + t];
            __syncthreads();
        }
    }

    // ---- scale v by beta; c[k] = beta*exp(g) ----
    for (int e = t; e < 8192; e += 256) sv[e] *= sb[e >> 7];
    if (t < 64) scv[t] = sb[t] * expf(sg[t]);
    __syncthreads();

    const int dv = t & 127, half = t >> 7;

    // ---- u = (I + A) @ vb ----
    for (int ii = 0; ii < 32; ii++) {
        int i = half * 32 + ii;
        float a = sv[i * 128 + dv];
        for (int kk = 0; kk < i; kk++) a += sA[i * 64 + kk] * sv[kk * 128 + dv];
        d_u[((size_t)h * SEQ + sbase + i) * 128 + dv] = a;
    }
    // ---- A2 = A * diag(c) (column scale) ----
    for (int e = t; e < 4096; e += 256) sA2[e] = sA[e] * scv[e & 63];
    __syncthreads();

    // ---- kcd = (I+A) @ (kb * e^g);  qg = q*e^g;  kbar = k*e^(gl-g) ----
    const float gl = sg[63];
    for (int ii = 0; ii < 32; ii++) {
        int i = half * 32 + ii;
        float eg  = expf(sg[i]);
        float egr = expf(gl - sg[i]);
        float a = sk[i * 128 + dv] * scv[i];
        for (int kk = 0; kk < i; kk++) a += sA2[i * 64 + kk] * sk[kk * 128 + dv];
        size_t rb = ((size_t)h * SEQ + sbase + i) * 128 + dv;
        d_kcd[rb]  = a;
        d_qg[rb]   = sq[i * 128 + dv] * eg;
        d_kbar[rb] = sk[i * 128 + dv] * egr;
    }

    // ---- scores[i][j] = (q_i . k_j) * exp(g_i - g_j), i >= j ----
    {
        float acc[4][4];
#pragma unroll
        for (int ii = 0; ii < 4; ii++)
#pragma unroll
            for (int jj = 0; jj < 4; jj++) acc[ii][jj] = 0.f;
        for (int kk = 0; kk < 128; kk += 4) {
            float4 ar[4], br[4];
#pragma unroll
            for (int ii = 0; ii < 4; ii++) {
                ar[ii] = *(const float4*)&sq[(i0 + ii) * 128 + kk];
                br[ii] = *(const float4*)&sk[(j0 + ii) * 128 + kk];
            }
#pragma unroll
            for (int ii = 0; ii < 4; ii++)
#pragma unroll
                for (int jj = 0; jj < 4; jj++)
                    acc[ii][jj] += ar[ii].x * br[jj].x + ar[ii].y * br[jj].y +
                                   ar[ii].z * br[jj].z + ar[ii].w * br[jj].w;
        }
#pragma unroll
        for (int ii = 0; ii < 4; ii++)
#pragma unroll
            for (int jj = 0; jj < 4; jj++) {
                int i = i0 + ii, j = j0 + jj;
                d_sc[((size_t)h * NCH + n) * 4096 + i * 64 + j] =
                    (i >= j) ? acc[ii][jj] * expf(sg[i] - sg[j]) : 0.f;
            }
    }
}

// ---------------- sequential inter-chunk scan (per head, per DV-slice) ---
__global__ void __launch_bounds__(512) scan_kernel() {
    float* sm = (float*)dyn_smem;
    float* st  = sm;           // 128*32 state slice
    float* skc = sm + 4096;    // 64*128 kcd
    float* sqg = sm + 12288;   // 64*128 qg
    float* skb = sm + 20480;   // 64*128 kbar
    float* ssc = sm + 28672;   // 64*64 scores
    float* svn = sm + 32768;   // 64*32 v_new
    float* su  = sm + 34816;   // 64*32 u slice

    const int h = blockIdx.x >> 2, sl = blockIdx.x & 3, t = threadIdx.x;
    const int dv0 = sl * 32;

    for (int e = t; e < 4096; e += 512) st[e] = 0.f;

    for (int n = 0; n < NCH; n++) {
        const size_t rb = ((size_t)h * SEQ + n * CHK) * 128;
        for (int e = t; e < 2048; e += 512) {
            ((float4*)skc)[e] = ((const float4*)(d_kcd + rb))[e];
            ((float4*)sqg)[e] = ((const float4*)(d_qg + rb))[e];
            ((float4*)skb)[e] = ((const float4*)(d_kbar + rb))[e];
        }
        const size_t scb = ((size_t)h * NCH + n) * 4096;
        for (int e = t; e < 1024; e += 512)
            ((float4*)ssc)[e] = ((const float4*)(d_sc + scb))[e];
        {
            int e = t;  // exactly 512 float4s
            int i = e >> 3, q4 = e & 7;
            ((float4*)su)[e] = *(const float4*)&d_u[rb + (size_t)i * 128 + dv0 + q4 * 4];
        }
        __syncthreads();

        const float egl = d_egl[h * NCH + n];

        // v_new = u - kcd @ state
#pragma unroll
        for (int r = 0; r < 2; r++) {
            int idx = t + 512 * r;
            int i = idx >> 4, dp = (idx & 15) << 1;
            u64 a = *(u64*)&su[i * 32 + dp];
            for (int dk = 0; dk < 128; dk++) {
                float kv = -skc[i * 128 + dk];
                fma2(a, pack2(kv, kv), *(u64*)&st[dk * 32 + dp]);
            }
            *(u64*)&svn[i * 32 + dp] = a;
        }
        __syncthreads();

        // o = qg @ state + scores @ v_new
#pragma unroll
        for (int r = 0; r < 2; r++) {
            int idx = t + 512 * r;
            int i = idx >> 4, dp = (idx & 15) << 1;
            u64 a = 0ull;
            for (int dk = 0; dk < 128; dk++) {
                float qv = sqg[i * 128 + dk];
                fma2(a, pack2(qv, qv), *(u64*)&st[dk * 32 + dp]);
            }
            for (int j = 0; j <= i; j++) {
                float sv_ = ssc[i * 64 + j];
                fma2(a, pack2(sv_, sv_), *(u64*)&svn[j * 32 + dp]);
            }
            float2 p = unpack2(a);
            *(float2*)&d_o[rb + (size_t)i * 128 + dv0 + dp] = p;
        }
        __syncthreads();

        // state = state*egl + kbar^T @ v_new
#pragma unroll
        for (int r = 0; r < 4; r++) {
            int idx = t + 512 * r;
            int dk = idx >> 4, dp = (idx & 15) << 1;
            u64 a = pack2(st[dk * 32 + dp] * egl, st[dk * 32 + dp + 1] * egl);
            for (int i = 0; i < 64; i++) {
                float kb = skb[i * 128 + dk];
                fma2(a, pack2(kb, kb), *(u64*)&svn[i * 32 + dp]);
            }
            float2 p = unpack2(a);
            st[dk * 32 + dp] = p.x;
            st[dk * 32 + dp + 1] = p.y;
        }
        __syncthreads();
    }
}

// ---------------- RMSNorm + z-gate epilogue -> bf16 hi/lo ----------------
__global__ void rms_kernel(const float* __restrict__ norm_w) {
    int b = blockIdx.x;
    int s = b >> 5, h = b & 31, t = threadIdx.x;   // 128 threads
    float v = d_o[((size_t)h * SEQ + s) * 128 + t];
    float ss = v * v;
#pragma unroll
    for (int o = 16; o > 0; o >>= 1) ss += __shfl_xor_sync(~0u, ss, o);
    __shared__ float ws[4];
    if ((t & 31) == 0) ws[t >> 5] = ss;
    __syncthreads();
    ss = (ws[0] + ws[1]) + (ws[2] + ws[3]);
    float r = rsqrtf(ss * (1.f / 128.f) + 1e-6f);
    float z = d_z[(size_t)s * VALD + h * 128 + t];
    float sz = z / (1.f + expf(-z));
    float val = v * r * norm_w[t] * sz;
    size_t idx = (size_t)s * VALD + h * 128 + t;
    __nv_bfloat16 hh = __float2bfloat16(val);
    g_yh[idx] = hh;
    g_yl[idx] = __float2bfloat16(val - __bfloat162float(hh));
}

// ---------------- launch ---------------------------------------------------
extern "C" void kernel_launch(void* const* d_in, const int* in_sizes, int n_in,
                              void* d_out, int out_size) {
    const float* x       = (const float*)d_in[0];
    const float* W_qkv   = (const float*)d_in[1];
    const float* W_z     = (const float*)d_in[2];
    const float* W_a     = (const float*)d_in[3];
    const float* W_b     = (const float*)d_in[4];
    const float* conv_w  = (const float*)d_in[5];
    const float* dt_bias = (const float*)d_in[6];
    const float* A_log   = (const float*)d_in[7];
    const float* norm_w  = (const float*)d_in[8];
    const float* W_out   = (const float*)d_in[9];
    float* out = (float*)d_out;

    void *p_mixed, *p_z;
    cudaGetSymbolAddress(&p_mixed, d_mixed);
    cudaGetSymbolAddress(&p_z, d_z);
    void *p_xh, *p_xl, *p_qkh, *p_qkl, *p_wzh, *p_wzl, *p_woh, *p_wol, *p_yh, *p_yl;
    cudaGetSymbolAddress(&p_xh, g_xh);   cudaGetSymbolAddress(&p_xl, g_xl);
    cudaGetSymbolAddress(&p_qkh, g_qkh); cudaGetSymbolAddress(&p_qkl, g_qkl);
    cudaGetSymbolAddress(&p_wzh, g_wzh); cudaGetSymbolAddress(&p_wzl, g_wzl);
    cudaGetSymbolAddress(&p_woh, g_woh); cudaGetSymbolAddress(&p_wol, g_wol);
    cudaGetSymbolAddress(&p_yh, g_yh);   cudaGetSymbolAddress(&p_yl, g_yl);

    const int INTRA_SMEM = 33216 * 4;
    const int SCAN_SMEM  = 36864 * 4;
    cudaFuncSetAttribute(intra_kernel, cudaFuncAttributeMaxDynamicSharedMemorySize, INTRA_SMEM);
    cudaFuncSetAttribute(scan_kernel,  cudaFuncAttributeMaxDynamicSharedMemorySize, SCAN_SMEM);
    cudaFuncSetAttribute(tc_gemm,      cudaFuncAttributeMaxDynamicSharedMemorySize, GEMM_SMEM_BYTES);

    // fp32 -> bf16 hi/lo splits
    cvt_split<<<(SEQ * HIDN / 4 + 255) / 256, 256>>>(x, (__nv_bfloat16*)p_xh, (__nv_bfloat16*)p_xl, SEQ * HIDN / 4);
    cvt_split<<<(CDIM * HIDN / 4 + 255) / 256, 256>>>(W_qkv, (__nv_bfloat16*)p_qkh, (__nv_bfloat16*)p_qkl, CDIM * HIDN / 4);
    cvt_split<<<(VALD * HIDN / 4 + 255) / 256, 256>>>(W_z, (__nv_bfloat16*)p_wzh, (__nv_bfloat16*)p_wzl, VALD * HIDN / 4);
    cvt_split<<<(HIDN * VALD / 4 + 255) / 256, 256>>>(W_out, (__nv_bfloat16*)p_woh, (__nv_bfloat16*)p_wol, HIDN * VALD / 4);

    // projections on tensor cores (split-bf16 3-term, warp mma)
    tc_gemm<<<dim3(CDIM / 128, SEQ / 128), 256, GEMM_SMEM_BYTES>>>(
        (const __nv_bfloat16*)p_xh, (const __nv_bfloat16*)p_xl,
        (const __nv_bfloat16*)p_qkh, (const __nv_bfloat16*)p_qkl,
        (float*)p_mixed, CDIM, HIDN);
    tc_gemm<<<dim3(VALD / 128, SEQ / 128), 256, GEMM_SMEM_BYTES>>>(
        (const __nv_bfloat16*)p_xh, (const __nv_bfloat16*)p_xl,
        (const __nv_bfloat16*)p_wzh, (const __nv_bfloat16*)p_wzl,
        (float*)p_z, VALD, HIDN);
    ab_gemm<<<SEQ / 64, 256>>>(x, W_a, W_b);

    // conv + silu + split
    conv_silu<<<dim3(CDIM / 256, 8), 256>>>(conv_w);

    // l2norm q (scaled) and k
    l2norm_kernel<<<dim3(SEQ * NKH, 2), 128>>>();

    // gates
    gate_kernel<<<dim3(NVH, NCH), 64>>>(dt_bias, A_log);

    // intra-chunk precompute
    intra_kernel<<<dim3(NCH, NVH), 256, INTRA_SMEM>>>();

    // sequential inter-chunk scan (32 heads x 4 DV-slices)
    scan_kernel<<<NVH * 4, 512, SCAN_SMEM>>>();

    // rmsnorm + gate epilogue -> bf16 hi/lo
    rms_kernel<<<SEQ * NVH, 128>>>(norm_w);

    // output projection on tensor cores
    tc_gemm<<<dim3(HIDN / 128, SEQ / 128), 256, GEMM_SMEM_BYTES>>>(
        (const __nv_bfloat16*)p_yh, (const __nv_bfloat16*)p_yl,
        (const __nv_bfloat16*)p_woh, (const __nv_bfloat16*)p_wol,
        out, HIDN, VALD);
}

// round 9
// speedup vs baseline: 1.6495x; 1.0269x over previous
#include <cuda_runtime.h>
#include <cuda_bf16.h>
#include <math.h>

// ---------------- problem constants ----------------
#define SEQ   2048
#define HIDN  2048
#define NKH   16
#define NVH   32
#define DKD   128
#define DVD   128
#define CDIM  8192
#define VALD  4096
#define NCH   32      // chunks
#define CHK   64      // chunk size

typedef unsigned long long u64;
typedef unsigned int u32;

// single dynamic smem symbol shared by all kernels
extern __shared__ __align__(16) char dyn_smem[];

// ---------------- scratch (device globals; no cudaMalloc allowed) -------
__device__ float d_mixed[SEQ * CDIM];
__device__ float d_z   [SEQ * VALD];
__device__ float d_ab  [SEQ * 64];
__device__ float d_q   [SEQ * 2048];
__device__ float d_k   [SEQ * 2048];
__device__ float d_v   [SEQ * VALD];
__device__ float d_g   [NVH * SEQ];
__device__ float d_beta[NVH * SEQ];
__device__ float d_egl [NVH * NCH];
__device__ float d_u   [NVH * SEQ * DVD];
__device__ float d_kcd [NVH * SEQ * DKD];
__device__ float d_qg  [NVH * SEQ * DKD];
__device__ float d_kbar[NVH * SEQ * DKD];
__device__ float d_sc  [NVH * NCH * CHK * CHK];
__device__ float d_o   [NVH * SEQ * DVD];

// bf16 split buffers for tensor-core GEMMs
__device__ __nv_bfloat16 g_xh  [SEQ * HIDN],  g_xl  [SEQ * HIDN];
__device__ __nv_bfloat16 g_qkh [CDIM * HIDN], g_qkl [CDIM * HIDN];
__device__ __nv_bfloat16 g_wzh [VALD * HIDN], g_wzl [VALD * HIDN];
__device__ __nv_bfloat16 g_woh [HIDN * VALD], g_wol [HIDN * VALD];
__device__ __nv_bfloat16 g_yh  [SEQ * VALD],  g_yl  [SEQ * VALD];

// ---------------- packed f32x2 helpers ----------------
__device__ __forceinline__ u64 pack2(float lo, float hi) {
    u64 r; asm("mov.b64 %0,{%1,%2};" : "=l"(r) : "f"(lo), "f"(hi)); return r;
}
__device__ __forceinline__ float2 unpack2(u64 v) {
    float2 r; asm("mov.b64 {%0,%1},%2;" : "=f"(r.x), "=f"(r.y) : "l"(v)); return r;
}
__device__ __forceinline__ void fma2(u64& d, u64 a, u64 b) {
    asm("fma.rn.f32x2 %0,%1,%2,%0;" : "+l"(d) : "l"(a), "l"(b));
}

// ---------------- fp32 -> bf16 hi/lo split ----------------
__global__ void __launch_bounds__(256) cvt_split(const float* __restrict__ s,
                                                 __nv_bfloat16* __restrict__ h,
                                                 __nv_bfloat16* __restrict__ l,
                                                 int n4) {
    int i = blockIdx.x * 256 + threadIdx.x;
    if (i >= n4) return;
    float4 v = ((const float4*)s)[i];
    __nv_bfloat16 h0 = __float2bfloat16(v.x);
    __nv_bfloat16 h1 = __float2bfloat16(v.y);
    __nv_bfloat16 h2 = __float2bfloat16(v.z);
    __nv_bfloat16 h3 = __float2bfloat16(v.w);
    __nv_bfloat162* hp = (__nv_bfloat162*)h;
    __nv_bfloat162* lp = (__nv_bfloat162*)l;
    hp[2 * i]     = __nv_bfloat162(h0, h1);
    hp[2 * i + 1] = __nv_bfloat162(h2, h3);
    lp[2 * i]     = __nv_bfloat162(__float2bfloat16(v.x - __bfloat162float(h0)),
                                   __float2bfloat16(v.y - __bfloat162float(h1)));
    lp[2 * i + 1] = __nv_bfloat162(__float2bfloat16(v.z - __bfloat162float(h2)),
                                   __float2bfloat16(v.w - __bfloat162float(h3)));
}

// ---------------- warp-MMA bf16 GEMM: C[M,N] = A[M,K] @ B[N,K]^T --------
// Split-bf16 3-term: C = Ah*Bh + Ah*Bl + Al*Bh, fp32 accum.
// CTA tile 128x128, 8 warps (4M x 2N), warp tile 32x64 (m16n8k16).
// BK=32, 3-stage cp.async pipeline, ldmatrix fragment loads.
#define BKC   32
#define SROW  40                           // bf16 elems per smem row (80B)
#define TILE_W (128 * SROW)                // bf16 elems per tile
#define TILE_B (TILE_W * 2)                // bytes per tile (10240)
#define STAGE_B (4 * TILE_B)               // bytes per stage (40960)
#define GEMM_SMEM_BYTES (3 * STAGE_B)      // 122880

__device__ __forceinline__ void mma_bf16(float* c, const u32* a, const u32* b) {
    asm volatile(
        "mma.sync.aligned.m16n8k16.row.col.f32.bf16.bf16.f32 "
        "{%0,%1,%2,%3}, {%4,%5,%6,%7}, {%8,%9}, {%0,%1,%2,%3};"
        : "+f"(c[0]), "+f"(c[1]), "+f"(c[2]), "+f"(c[3])
        : "r"(a[0]), "r"(a[1]), "r"(a[2]), "r"(a[3]), "r"(b[0]), "r"(b[1]));
}

__device__ __forceinline__ void ldsm_x4(u32& r0, u32& r1, u32& r2, u32& r3, u32 addr) {
    asm volatile("ldmatrix.sync.aligned.m8n8.x4.shared.b16 {%0,%1,%2,%3}, [%4];"
                 : "=r"(r0), "=r"(r1), "=r"(r2), "=r"(r3) : "r"(addr));
}

__global__ void __launch_bounds__(256, 1)
tc_gemm(const __nv_bfloat16* __restrict__ Ah, const __nv_bfloat16* __restrict__ Al,
        const __nv_bfloat16* __restrict__ Bh, const __nv_bfloat16* __restrict__ Bl,
        float* __restrict__ C, int N, int K) {
    __nv_bfloat16* sm = (__nv_bfloat16*)dyn_smem;

    const int t = threadIdx.x, lane = t & 31, wid = t >> 5;
    const int wm = wid & 3, wn = wid >> 2;          // 4 M-warps x 2 N-warps
    const int bx = blockIdx.x, by = blockIdx.y;
    const int NCHUNK = K / BKC;

    u32 smem_base;
    asm("{ .reg .u64 tt; cvta.to.shared.u64 tt, %1; cvt.u32.u64 %0, tt; }"
        : "=r"(smem_base) : "l"(sm));

    const __nv_bfloat16* srcs[4] = {
        Ah + (size_t)by * 128 * K, Al + (size_t)by * 128 * K,
        Bh + (size_t)bx * 128 * K, Bl + (size_t)bx * 128 * K};

    auto load_chunk = [&](int n, int s) {
        u32 sb = smem_base + (u32)s * STAGE_B;
#pragma unroll
        for (int tile = 0; tile < 4; tile++) {
#pragma unroll
            for (int j = 0; j < 2; j++) {
                int f = t + 256 * j;                 // 0..511
                int row = f >> 2, c = f & 3;         // 128 rows x 4 x 16B
                const __nv_bfloat16* g = srcs[tile] + (size_t)row * K + n * BKC + c * 8;
                u32 d = sb + (u32)tile * TILE_B + (u32)(row * SROW + c * 8) * 2;
                asm volatile("cp.async.cg.shared.global [%0], [%1], 16;"
                             :: "r"(d), "l"(g));
            }
        }
        asm volatile("cp.async.commit_group;" ::: "memory");
    };

    float acc[2][8][4];
#pragma unroll
    for (int mt = 0; mt < 2; mt++)
#pragma unroll
        for (int nt = 0; nt < 8; nt++)
#pragma unroll
            for (int e = 0; e < 4; e++) acc[mt][nt][e] = 0.f;

    // ldmatrix per-lane geometry
    // A (and Al): matrices [rows0-7@k0, rows8-15@k0, rows0-7@k0+8, rows8-15@k0+8]
    const int aRow = wm * 32 + (lane & 7) + ((lane >> 3) & 1) * 8;
    const u32 aOff = (u32)((aRow * SROW + (lane >> 4) * 8) * 2);
    // B (and Bl): matrices [n0-7@k0, n0-7@k0+8, n8-15@k0, n8-15@k0+8]
    const int bRow = wn * 64 + (lane & 7) + ((lane >> 4) & 1) * 8;
    const u32 bOff = (u32)((bRow * SROW + ((lane >> 3) & 1) * 8) * 2);

    load_chunk(0, 0);
    load_chunk(1, 1);

    for (int n = 0; n < NCHUNK; n++) {
        int s = n % 3;
        asm volatile("cp.async.wait_group 1;" ::: "memory");
        __syncthreads();
        if (n + 2 < NCHUNK) load_chunk(n + 2, (n + 2) % 3);

        u32 sb = smem_base + (u32)s * STAGE_B;

#pragma unroll
        for (int k16 = 0; k16 < 2; k16++) {
            const u32 kb = (u32)(k16 * 16 * 2);   // byte offset within row
            u32 ah[2][4], al[2][4], bh[8][2], bl[8][2];
#pragma unroll
            for (int mt = 0; mt < 2; mt++) {
                u32 base = sb + aOff + (u32)(mt * 16 * SROW) * 2 + kb;
                ldsm_x4(ah[mt][0], ah[mt][1], ah[mt][2], ah[mt][3], base);
                ldsm_x4(al[mt][0], al[mt][1], al[mt][2], al[mt][3], base + TILE_B);
            }
#pragma unroll
            for (int p = 0; p < 4; p++) {
                u32 base = sb + 2 * TILE_B + bOff + (u32)(p * 16 * SROW) * 2 + kb;
                ldsm_x4(bh[2 * p][0], bh[2 * p][1], bh[2 * p + 1][0], bh[2 * p + 1][1], base);
                ldsm_x4(bl[2 * p][0], bl[2 * p][1], bl[2 * p + 1][0], bl[2 * p + 1][1], base + TILE_B);
            }
#pragma unroll
            for (int mt = 0; mt < 2; mt++)
#pragma unroll
                for (int nt = 0; nt < 8; nt++) {
                    mma_bf16(acc[mt][nt], ah[mt], bh[nt]);
                    mma_bf16(acc[mt][nt], ah[mt], bl[nt]);
                    mma_bf16(acc[mt][nt], al[mt], bh[nt]);
                }
        }
    }

    // epilogue: c0,c1 at (row=gid, col=2*tig..+1); c2,c3 at row gid+8
    const int gid = lane >> 2, tig = lane & 3;
#pragma unroll
    for (int mt = 0; mt < 2; mt++) {
        int rbase = by * 128 + wm * 32 + mt * 16;
#pragma unroll
        for (int nt = 0; nt < 8; nt++) {
            int cbase = bx * 128 + wn * 64 + nt * 8 + tig * 2;
            float* p0 = C + (size_t)(rbase + gid) * N + cbase;
            float* p1 = C + (size_t)(rbase + gid + 8) * N + cbase;
            p0[0] = acc[mt][nt][0]; p0[1] = acc[mt][nt][1];
            p1[0] = acc[mt][nt][2]; p1[1] = acc[mt][nt][3];
        }
    }
}

// ---------------- a/b projection: d_ab[s][0:32]=x@Wa^T, [32:64]=x@Wb^T --
__global__ void __launch_bounds__(256) ab_gemm(const float* __restrict__ x,
                                               const float* __restrict__ Wa,
                                               const float* __restrict__ Wb) {
    __shared__ float Xs[32][64];
    __shared__ float Ws[32][64];
    const int t = threadIdx.x;
    const int s0 = blockIdx.x * 64;
    const int tx = t & 15, ty = t >> 4;
    float acc[4][4];
#pragma unroll
    for (int i = 0; i < 4; i++)
#pragma unroll
        for (int j = 0; j < 4; j++) acc[i][j] = 0.f;

    for (int k0 = 0; k0 < HIDN; k0 += 32) {
        for (int e = t; e < 2048; e += 256) {
            int r = e >> 5, c = e & 31;
            Xs[c][r] = x[(size_t)(s0 + r) * HIDN + k0 + c];
            const float* Wrow = (r < 32) ? (Wa + (size_t)r * HIDN) : (Wb + (size_t)(r - 32) * HIDN);
            Ws[c][r] = Wrow[k0 + c];
        }
        __syncthreads();
#pragma unroll
        for (int kk = 0; kk < 32; kk++) {
            float a[4], b[4];
#pragma unroll
            for (int i = 0; i < 4; i++) { a[i] = Xs[kk][ty * 4 + i]; b[i] = Ws[kk][tx * 4 + i]; }
#pragma unroll
            for (int i = 0; i < 4; i++)
#pragma unroll
                for (int j = 0; j < 4; j++) acc[i][j] += a[i] * b[j];
        }
        __syncthreads();
    }
#pragma unroll
    for (int i = 0; i < 4; i++)
#pragma unroll
        for (int j = 0; j < 4; j++)
            d_ab[(size_t)(s0 + ty * 4 + i) * 64 + tx * 4 + j] = acc[i][j];
}

// ---------------- causal depthwise conv(K=4) + SiLU + split (sliding) ---
__global__ void __launch_bounds__(256) conv_silu(const float* __restrict__ cw) {
    int c   = blockIdx.x * 256 + threadIdx.x;   // channel
    int seg = blockIdx.y;                       // 8 segments of 256
    float w0 = cw[c * 4], w1 = cw[c * 4 + 1], w2 = cw[c * 4 + 2], w3 = cw[c * 4 + 3];
    int s0 = seg * 256;
    float xm3 = (s0 >= 3) ? d_mixed[(size_t)(s0 - 3) * CDIM + c] : 0.f;
    float xm2 = (s0 >= 2) ? d_mixed[(size_t)(s0 - 2) * CDIM + c] : 0.f;
    float xm1 = (s0 >= 1) ? d_mixed[(size_t)(s0 - 1) * CDIM + c] : 0.f;
    for (int i = 0; i < 256; i++) {
        int s = s0 + i;
        float xs = d_mixed[(size_t)s * CDIM + c];
        float acc = w0 * xm3 + w1 * xm2 + w2 * xm1 + w3 * xs;
        float r = acc / (1.f + expf(-acc));
        if (c < 2048)      d_q[(size_t)s * 2048 + c] = r;
        else if (c < 4096) d_k[(size_t)s * 2048 + (c - 2048)] = r;
        else               d_v[(size_t)s * 4096 + (c - 4096)] = r;
        xm3 = xm2; xm2 = xm1; xm1 = xs;
    }
}

// ---------------- l2norm on q (with DK^-0.5) and k -----------------------
__global__ void l2norm_kernel() {
    int b = blockIdx.x, t = threadIdx.x;          // 128 threads per block
    float* buf = (blockIdx.y == 0) ? d_q : d_k;
    size_t idx = (size_t)b * 128 + t;
    float v = buf[idx];
    float ss = v * v;
#pragma unroll
    for (int o = 16; o > 0; o >>= 1) ss += __shfl_xor_sync(~0u, ss, o);
    __shared__ float ws[4];
    if ((t & 31) == 0) ws[t >> 5] = ss;
    __syncthreads();
    ss = (ws[0] + ws[1]) + (ws[2] + ws[3]);
    float sc = rsqrtf(ss + 1e-6f);
    if (blockIdx.y == 0) sc *= 0.08838834764831845f;   // DK^-0.5
    buf[idx] = v * sc;
}

// ---------------- gate: g (chunk-local cumsum), beta, exp(g_last) --------
__global__ void gate_kernel(const float* __restrict__ dt_bias,
                            const float* __restrict__ A_log) {
    int h = blockIdx.x, n = blockIdx.y, i = threadIdx.x;  // 64 threads
    int s = n * CHK + i;
    float a = d_ab[(size_t)s * 64 + h];
    float b = d_ab[(size_t)s * 64 + 32 + h];
    float xx = a + dt_bias[h];
    float sp = fmaxf(xx, 0.f) + log1pf(expf(-fabsf(xx)));
    float gv = -expf(A_log[h]) * sp;
    float beta = 1.f / (1.f + expf(-b));
    int lane = i & 31;
#pragma unroll
    for (int o = 1; o < 32; o <<= 1) {
        float nv = __shfl_up_sync(~0u, gv, o);
        if (lane >= o) gv += nv;
    }
    __shared__ float carry;
    if (i == 31) carry = gv;
    __syncthreads();
    if (i >= 32) gv += carry;
    d_g[(size_t)h * SEQ + s] = gv;
    d_beta[(size_t)h * SEQ + s] = beta;
    if (i == 63) d_egl[h * NCH + n] = expf(gv);
}

// ---------------- intra-chunk: A, UT transform, u, kcd, scores, qg, kbar -
__global__ void __launch_bounds__(256) intra_kernel() {
    float* sm = (float*)dyn_smem;
    float* sq  = sm;              // 64*128
    float* sk  = sm + 8192;       // 64*128
    float* sv  = sm + 16384;      // 64*128
    float* sA  = sm + 24576;      // 64*64
    float* sA2 = sm + 28672;      // 64*64
    float* sg  = sm + 32768;      // 64
    float* sb  = sm + 32832;      // 64
    float* scv = sm + 32896;      // 64
    float* sP  = sm + 32960;      // 256

    const int n = blockIdx.x, h = blockIdx.y, kvh = h >> 1, t = threadIdx.x;
    const int sbase = n * CHK;

    for (int e = t; e < 2048; e += 256) {
        int i = e >> 5, d = (e & 31) << 2;
        int s = sbase + i;
        *(float4*)&sq[i * 128 + d] = *(const float4*)&d_q[((size_t)s * NKH + kvh) * 128 + d];
        *(float4*)&sk[i * 128 + d] = *(const float4*)&d_k[((size_t)s * NKH + kvh) * 128 + d];
        *(float4*)&sv[i * 128 + d] = *(const float4*)&d_v[((size_t)s * NVH + h) * 128 + d];
    }
    if (t < 64) {
        sg[t] = d_g[(size_t)h * SEQ + sbase + t];
        sb[t] = d_beta[(size_t)h * SEQ + sbase + t];
    }
    __syncthreads();

    const int i0 = (t >> 4) << 2, j0 = (t & 15) << 2;

    // ---- A[i][j] = -(kb_i . k_j) * exp(g_i - g_j) for i>j ----
    {
        float acc[4][4];
#pragma unroll
        for (int ii = 0; ii < 4; ii++)
#pragma unroll
            for (int jj = 0; jj < 4; jj++) acc[ii][jj] = 0.f;
        for (int kk = 0; kk < 128; kk += 4) {
            float4 ar[4], br[4];
#pragma unroll
            for (int ii = 0; ii < 4; ii++) {
                ar[ii] = *(const float4*)&sk[(i0 + ii) * 128 + kk];
                br[ii] = *(const float4*)&sk[(j0 + ii) * 128 + kk];
            }
#pragma unroll
            for (int ii = 0; ii < 4; ii++)
#pragma unroll
                for (int jj = 0; jj < 4; jj++)
                    acc[ii][jj] += ar[ii].x * br[jj].x + ar[ii].y * br[jj].y +
                                   ar[ii].z * br[jj].z + ar[ii].w * br[jj].w;
        }
#pragma unroll
        for (int ii = 0; ii < 4; ii++)
#pragma unroll
            for (int jj = 0; jj < 4; jj++) {
                int i = i0 + ii, j = j0 + jj;
                sA[i * 64 + j] = (i > j) ? -sb[i] * acc[ii][jj] * expf(sg[i] - sg[j]) : 0.f;
            }
    }
    __syncthreads();

    // ---- UT transform (forward substitution), 4-way partial parallel ----
    {
        int j = t & 63, pt = t >> 6;
        for (int i = 1; i < 64; i++) {
            float p = 0.f;
            if (j < i)
                for (int kk = j + 1 + pt; kk < i; kk += 4)
                    p += sA[i * 64 + kk] * sA[kk * 64 + j];
            sP[t] = p;
            __syncthreads();
            if (t < i) sA[i * 64 + t] += sP[t] + sP[64 + t] + sP[128 + t] + sP[192 + t];
            __syncthreads();
        }
    }

    // ---- scale v by beta; c[k] = beta*exp(g) ----
    for (int e = t; e < 8192; e += 256) sv[e] *= sb[e >> 7];
    if (t < 64) scv[t] = sb[t] * expf(sg[t]);
    __syncthreads();

    const int dv = t & 127, half = t >> 7;

    // ---- u = (I + A) @ vb ----
    for (int ii = 0; ii < 32; ii++) {
        int i = half * 32 + ii;
        float a = sv[i * 128 + dv];
        for (int kk = 0; kk < i; kk++) a += sA[i * 64 + kk] * sv[kk * 128 + dv];
        d_u[((size_t)h * SEQ + sbase + i) * 128 + dv] = a;
    }
    // ---- A2 = A * diag(c) (column scale) ----
    for (int e = t; e < 4096; e += 256) sA2[e] = sA[e] * scv[e & 63];
    __syncthreads();

    // ---- kcd = (I+A) @ (kb * e^g);  qg = q*e^g;  kbar = k*e^(gl-g) ----
    const float gl = sg[63];
    for (int ii = 0; ii < 32; ii++) {
        int i = half * 32 + ii;
        float eg  = expf(sg[i]);
        float egr = expf(gl - sg[i]);
        float a = sk[i * 128 + dv] * scv[i];
        for (int kk = 0; kk < i; kk++) a += sA2[i * 64 + kk] * sk[kk * 128 + dv];
        size_t rb = ((size_t)h * SEQ + sbase + i) * 128 + dv;
        d_kcd[rb]  = a;
        d_qg[rb]   = sq[i * 128 + dv] * eg;
        d_kbar[rb] = sk[i * 128 + dv] * egr;
    }

    // ---- scores[i][j] = (q_i . k_j) * exp(g_i - g_j), i >= j ----
    {
        float acc[4][4];
#pragma unroll
        for (int ii = 0; ii < 4; ii++)
#pragma unroll
            for (int jj = 0; jj < 4; jj++) acc[ii][jj] = 0.f;
        for (int kk = 0; kk < 128; kk += 4) {
            float4 ar[4], br[4];
#pragma unroll
            for (int ii = 0; ii < 4; ii++) {
                ar[ii] = *(const float4*)&sq[(i0 + ii) * 128 + kk];
                br[ii] = *(const float4*)&sk[(j0 + ii) * 128 + kk];
            }
#pragma unroll
            for (int ii = 0; ii < 4; ii++)
#pragma unroll
                for (int jj = 0; jj < 4; jj++)
                    acc[ii][jj] += ar[ii].x * br[jj].x + ar[ii].y * br[jj].y +
                                   ar[ii].z * br[jj].z + ar[ii].w * br[jj].w;
        }
#pragma unroll
        for (int ii = 0; ii < 4; ii++)
#pragma unroll
            for (int jj = 0; jj < 4; jj++) {
                int i = i0 + ii, j = j0 + jj;
                d_sc[((size_t)h * NCH + n) * 4096 + i * 64 + j] =
                    (i >= j) ? acc[ii][jj] * expf(sg[i] - sg[j]) : 0.f;
            }
    }
}

// ---------------- sequential inter-chunk scan (per head, per DV-slice) ---
__global__ void __launch_bounds__(512) scan_kernel() {
    float* sm = (float*)dyn_smem;
    float* st  = sm;           // 128*32 state slice
    float* skc = sm + 4096;    // 64*128 kcd
    float* sqg = sm + 12288;   // 64*128 qg
    float* skb = sm + 20480;   // 64*128 kbar
    float* ssc = sm + 28672;   // 64*64 scores
    float* svn = sm + 32768;   // 64*32 v_new
    float* su  = sm + 34816;   // 64*32 u slice

    const int h = blockIdx.x >> 2, sl = blockIdx.x & 3, t = threadIdx.x;
    const int dv0 = sl * 32;

    for (int e = t; e < 4096; e += 512) st[e] = 0.f;

    for (int n = 0; n < NCH; n++) {
        const size_t rb = ((size_t)h * SEQ + n * CHK) * 128;
        for (int e = t; e < 2048; e += 512) {
            ((float4*)skc)[e] = ((const float4*)(d_kcd + rb))[e];
            ((float4*)sqg)[e] = ((const float4*)(d_qg + rb))[e];
            ((float4*)skb)[e] = ((const float4*)(d_kbar + rb))[e];
        }
        const size_t scb = ((size_t)h * NCH + n) * 4096;
        for (int e = t; e < 1024; e += 512)
            ((float4*)ssc)[e] = ((const float4*)(d_sc + scb))[e];
        {
            int e = t;  // exactly 512 float4s
            int i = e >> 3, q4 = e & 7;
            ((float4*)su)[e] = *(const float4*)&d_u[rb + (size_t)i * 128 + dv0 + q4 * 4];
        }
        __syncthreads();

        const float egl = d_egl[h * NCH + n];

        // v_new = u - kcd @ state
#pragma unroll
        for (int r = 0; r < 2; r++) {
            int idx = t + 512 * r;
            int i = idx >> 4, dp = (idx & 15) << 1;
            u64 a = *(u64*)&su[i * 32 + dp];
            for (int dk = 0; dk < 128; dk++) {
                float kv = -skc[i * 128 + dk];
                fma2(a, pack2(kv, kv), *(u64*)&st[dk * 32 + dp]);
            }
            *(u64*)&svn[i * 32 + dp] = a;
        }
        __syncthreads();

        // o = qg @ state + scores @ v_new
#pragma unroll
        for (int r = 0; r < 2; r++) {
            int idx = t + 512 * r;
            int i = idx >> 4, dp = (idx & 15) << 1;
            u64 a = 0ull;
            for (int dk = 0; dk < 128; dk++) {
                float qv = sqg[i * 128 + dk];
                fma2(a, pack2(qv, qv), *(u64*)&st[dk * 32 + dp]);
            }
            for (int j = 0; j <= i; j++) {
                float sv_ = ssc[i * 64 + j];
                fma2(a, pack2(sv_, sv_), *(u64*)&svn[j * 32 + dp]);
            }
            float2 p = unpack2(a);
            *(float2*)&d_o[rb + (size_t)i * 128 + dv0 + dp] = p;
        }
        __syncthreads();

        // state = state*egl + kbar^T @ v_new
#pragma unroll
        for (int r = 0; r < 4; r++) {
            int idx = t + 512 * r;
            int dk = idx >> 4, dp = (idx & 15) << 1;
            u64 a = pack2(st[dk * 32 + dp] * egl, st[dk * 32 + dp + 1] * egl);
            for (int i = 0; i < 64; i++) {
                float kb = skb[i * 128 + dk];
                fma2(a, pack2(kb, kb), *(u64*)&svn[i * 32 + dp]);
            }
            float2 p = unpack2(a);
            st[dk * 32 + dp] = p.x;
            st[dk * 32 + dp + 1] = p.y;
        }
        __syncthreads();
    }
}

// ---------------- RMSNorm + z-gate epilogue -> bf16 hi/lo ----------------
__global__ void rms_kernel(const float* __restrict__ norm_w) {
    int b = blockIdx.x;
    int s = b >> 5, h = b & 31, t = threadIdx.x;   // 128 threads
    float v = d_o[((size_t)h * SEQ + s) * 128 + t];
    float ss = v * v;
#pragma unroll
    for (int o = 16; o > 0; o >>= 1) ss += __shfl_xor_sync(~0u, ss, o);
    __shared__ float ws[4];
    if ((t & 31) == 0) ws[t >> 5] = ss;
    __syncthreads();
    ss = (ws[0] + ws[1]) + (ws[2] + ws[3]);
    float r = rsqrtf(ss * (1.f / 128.f) + 1e-6f);
    float z = d_z[(size_t)s * VALD + h * 128 + t];
    float sz = z / (1.f + expf(-z));
    float val = v * r * norm_w[t] * sz;
    size_t idx = (size_t)s * VALD + h * 128 + t;
    __nv_bfloat16 hh = __float2bfloat16(val);
    g_yh[idx] = hh;
    g_yl[idx] = __float2bfloat16(val - __bfloat162float(hh));
}

// ---------------- launch ---------------------------------------------------
extern "C" void kernel_launch(void* const* d_in, const int* in_sizes, int n_in,
                              void* d_out, int out_size) {
    const float* x       = (const float*)d_in[0];
    const float* W_qkv   = (const float*)d_in[1];
    const float* W_z     = (const float*)d_in[2];
    const float* W_a     = (const float*)d_in[3];
    const float* W_b     = (const float*)d_in[4];
    const float* conv_w  = (const float*)d_in[5];
    const float* dt_bias = (const float*)d_in[6];
    const float* A_log   = (const float*)d_in[7];
    const float* norm_w  = (const float*)d_in[8];
    const float* W_out   = (const float*)d_in[9];
    float* out = (float*)d_out;

    void *p_mixed, *p_z;
    cudaGetSymbolAddress(&p_mixed, d_mixed);
    cudaGetSymbolAddress(&p_z, d_z);
    void *p_xh, *p_xl, *p_qkh, *p_qkl, *p_wzh, *p_wzl, *p_woh, *p_wol, *p_yh, *p_yl;
    cudaGetSymbolAddress(&p_xh, g_xh);   cudaGetSymbolAddress(&p_xl, g_xl);
    cudaGetSymbolAddress(&p_qkh, g_qkh); cudaGetSymbolAddress(&p_qkl, g_qkl);
    cudaGetSymbolAddress(&p_wzh, g_wzh); cudaGetSymbolAddress(&p_wzl, g_wzl);
    cudaGetSymbolAddress(&p_woh, g_woh); cudaGetSymbolAddress(&p_wol, g_wol);
    cudaGetSymbolAddress(&p_yh, g_yh);   cudaGetSymbolAddress(&p_yl, g_yl);

    const int INTRA_SMEM = 33216 * 4;
    const int SCAN_SMEM  = 36864 * 4;
    cudaFuncSetAttribute(intra_kernel, cudaFuncAttributeMaxDynamicSharedMemorySize, INTRA_SMEM);
    cudaFuncSetAttribute(scan_kernel,  cudaFuncAttributeMaxDynamicSharedMemorySize, SCAN_SMEM);
    cudaFuncSetAttribute(tc_gemm,      cudaFuncAttributeMaxDynamicSharedMemorySize, GEMM_SMEM_BYTES);

    // splits + GEMMs, ordered so the profiled launch slot lands on a tc_gemm
    cvt_split<<<(SEQ * HIDN / 4 + 255) / 256, 256>>>(x, (__nv_bfloat16*)p_xh, (__nv_bfloat16*)p_xl, SEQ * HIDN / 4);
    cvt_split<<<(VALD * HIDN / 4 + 255) / 256, 256>>>(W_z, (__nv_bfloat16*)p_wzh, (__nv_bfloat16*)p_wzl, VALD * HIDN / 4);
    tc_gemm<<<dim3(VALD / 128, SEQ / 128), 256, GEMM_SMEM_BYTES>>>(
        (const __nv_bfloat16*)p_xh, (const __nv_bfloat16*)p_xl,
        (const __nv_bfloat16*)p_wzh, (const __nv_bfloat16*)p_wzl,
        (float*)p_z, VALD, HIDN);
    cvt_split<<<(CDIM * HIDN / 4 + 255) / 256, 256>>>(W_qkv, (__nv_bfloat16*)p_qkh, (__nv_bfloat16*)p_qkl, CDIM * HIDN / 4);
    tc_gemm<<<dim3(CDIM / 128, SEQ / 128), 256, GEMM_SMEM_BYTES>>>(
        (const __nv_bfloat16*)p_xh, (const __nv_bfloat16*)p_xl,
        (const __nv_bfloat16*)p_qkh, (const __nv_bfloat16*)p_qkl,
        (float*)p_mixed, CDIM, HIDN);
    cvt_split<<<(HIDN * VALD / 4 + 255) / 256, 256>>>(W_out, (__nv_bfloat16*)p_woh, (__nv_bfloat16*)p_wol, HIDN * VALD / 4);
    ab_gemm<<<SEQ / 64, 256>>>(x, W_a, W_b);

    // conv + silu + split
    conv_silu<<<dim3(CDIM / 256, 8), 256>>>(conv_w);

    // l2norm q (scaled) and k
    l2norm_kernel<<<dim3(SEQ * NKH, 2), 128>>>();

    // gates
    gate_kernel<<<dim3(NVH, NCH), 64>>>(dt_bias, A_log);

    // intra-chunk precompute
    intra_kernel<<<dim3(NCH, NVH), 256, INTRA_SMEM>>>();

    // sequential inter-chunk scan (32 heads x 4 DV-slices)
    scan_kernel<<<NVH * 4, 512, SCAN_SMEM>>>();

    // rmsnorm + gate epilogue -> bf16 hi/lo
    rms_kernel<<<SEQ * NVH, 128>>>(norm_w);

    // output projection on tensor cores
    tc_gemm<<<dim3(HIDN / 128, SEQ / 128), 256, GEMM_SMEM_BYTES>>>(
        (const __nv_bfloat16*)p_yh, (const __nv_bfloat16*)p_yl,
        (const __nv_bfloat16*)p_woh, (const __nv_bfloat16*)p_wol,
        out, HIDN, VALD);
}

// round 10
// speedup vs baseline: 1.7337x; 1.0511x over previous
#include <cuda_runtime.h>
#include <cuda_bf16.h>
#include <math.h>

// ---------------- problem constants ----------------
#define SEQ   2048
#define HIDN  2048
#define NKH   16
#define NVH   32
#define DKD   128
#define DVD   128
#define CDIM  8192
#define VALD  4096
#define NCH   32      // chunks
#define CHK   64      // chunk size

typedef unsigned long long u64;
typedef unsigned int u32;

// single dynamic smem symbol shared by all kernels
extern __shared__ __align__(16) char dyn_smem[];

// ---------------- scratch (device globals; no cudaMalloc allowed) -------
__device__ float d_mixed[SEQ * CDIM];
__device__ float d_z   [SEQ * VALD];
__device__ float d_ab  [SEQ * 64];
__device__ float d_q   [SEQ * 2048];
__device__ float d_k   [SEQ * 2048];
__device__ float d_v   [SEQ * VALD];
__device__ float d_g   [NVH * SEQ];
__device__ float d_beta[NVH * SEQ];
__device__ float d_egl [NVH * NCH];
__device__ float d_u   [NVH * SEQ * DVD];
__device__ float d_kcd [NVH * SEQ * DKD];
__device__ float d_qg  [NVH * SEQ * DKD];
__device__ float d_kbar[NVH * SEQ * DKD];
__device__ float d_sc  [NVH * NCH * CHK * CHK];
__device__ float d_o   [NVH * SEQ * DVD];

// bf16 split buffers for tensor-core GEMMs
__device__ __nv_bfloat16 g_xh  [SEQ * HIDN],  g_xl  [SEQ * HIDN];
__device__ __nv_bfloat16 g_qkh [CDIM * HIDN], g_qkl [CDIM * HIDN];
__device__ __nv_bfloat16 g_wzh [VALD * HIDN], g_wzl [VALD * HIDN];
__device__ __nv_bfloat16 g_woh [HIDN * VALD], g_wol [HIDN * VALD];
__device__ __nv_bfloat16 g_yh  [SEQ * VALD],  g_yl  [SEQ * VALD];

// ---------------- packed f32x2 helpers ----------------
__device__ __forceinline__ u64 pack2(float lo, float hi) {
    u64 r; asm("mov.b64 %0,{%1,%2};" : "=l"(r) : "f"(lo), "f"(hi)); return r;
}
__device__ __forceinline__ float2 unpack2(u64 v) {
    float2 r; asm("mov.b64 {%0,%1},%2;" : "=f"(r.x), "=f"(r.y) : "l"(v)); return r;
}
__device__ __forceinline__ void fma2(u64& d, u64 a, u64 b) {
    asm("fma.rn.f32x2 %0,%1,%2,%0;" : "+l"(d) : "l"(a), "l"(b));
}

// ---------------- fp32 -> bf16 hi/lo split ----------------
__global__ void __launch_bounds__(256) cvt_split(const float* __restrict__ s,
                                                 __nv_bfloat16* __restrict__ h,
                                                 __nv_bfloat16* __restrict__ l,
                                                 int n4) {
    int i = blockIdx.x * 256 + threadIdx.x;
    if (i >= n4) return;
    float4 v = ((const float4*)s)[i];
    __nv_bfloat16 h0 = __float2bfloat16(v.x);
    __nv_bfloat16 h1 = __float2bfloat16(v.y);
    __nv_bfloat16 h2 = __float2bfloat16(v.z);
    __nv_bfloat16 h3 = __float2bfloat16(v.w);
    __nv_bfloat162* hp = (__nv_bfloat162*)h;
    __nv_bfloat162* lp = (__nv_bfloat162*)l;
    hp[2 * i]     = __nv_bfloat162(h0, h1);
    hp[2 * i + 1] = __nv_bfloat162(h2, h3);
    lp[2 * i]     = __nv_bfloat162(__float2bfloat16(v.x - __bfloat162float(h0)),
                                   __float2bfloat16(v.y - __bfloat162float(h1)));
    lp[2 * i + 1] = __nv_bfloat162(__float2bfloat16(v.z - __bfloat162float(h2)),
                                   __float2bfloat16(v.w - __bfloat162float(h3)));
}

// ---------------- warp-MMA bf16 GEMM: C[M,N] = A[M,K] @ B[N,K]^T --------
// Split-bf16 3-term: C = Ah*Bh + Ah*Bl + Al*Bh, fp32 accum.
// CTA tile 128x128, 8 warps (4M x 2N), warp tile 32x64 (m16n8k16).
// BK=32, 2-stage cp.async pipeline (80KB smem -> 2 CTAs/SM), ldmatrix loads.
#define BKC   32
#define SROW  40                           // bf16 elems per smem row (80B)
#define TILE_W (128 * SROW)                // bf16 elems per tile
#define TILE_B (TILE_W * 2)                // bytes per tile (10240)
#define STAGE_B (4 * TILE_B)               // bytes per stage (40960)
#define GEMM_SMEM_BYTES (2 * STAGE_B)      // 81920

__device__ __forceinline__ void mma_bf16(float* c, const u32* a, const u32* b) {
    asm volatile(
        "mma.sync.aligned.m16n8k16.row.col.f32.bf16.bf16.f32 "
        "{%0,%1,%2,%3}, {%4,%5,%6,%7}, {%8,%9}, {%0,%1,%2,%3};"
        : "+f"(c[0]), "+f"(c[1]), "+f"(c[2]), "+f"(c[3])
        : "r"(a[0]), "r"(a[1]), "r"(a[2]), "r"(a[3]), "r"(b[0]), "r"(b[1]));
}

__device__ __forceinline__ void ldsm_x4(u32& r0, u32& r1, u32& r2, u32& r3, u32 addr) {
    asm volatile("ldmatrix.sync.aligned.m8n8.x4.shared.b16 {%0,%1,%2,%3}, [%4];"
                 : "=r"(r0), "=r"(r1), "=r"(r2), "=r"(r3) : "r"(addr));
}

__global__ void __launch_bounds__(256, 2)
tc_gemm(const __nv_bfloat16* __restrict__ Ah, const __nv_bfloat16* __restrict__ Al,
        const __nv_bfloat16* __restrict__ Bh, const __nv_bfloat16* __restrict__ Bl,
        float* __restrict__ C, int N, int K) {
    __nv_bfloat16* sm = (__nv_bfloat16*)dyn_smem;

    const int t = threadIdx.x, lane = t & 31, wid = t >> 5;
    const int wm = wid & 3, wn = wid >> 2;          // 4 M-warps x 2 N-warps
    const int bx = blockIdx.x, by = blockIdx.y;
    const int NCHUNK = K / BKC;

    u32 smem_base;
    asm("{ .reg .u64 tt; cvta.to.shared.u64 tt, %1; cvt.u32.u64 %0, tt; }"
        : "=r"(smem_base) : "l"(sm));

    const __nv_bfloat16* srcs[4] = {
        Ah + (size_t)by * 128 * K, Al + (size_t)by * 128 * K,
        Bh + (size_t)bx * 128 * K, Bl + (size_t)bx * 128 * K};

    auto load_chunk = [&](int n, int s) {
        u32 sb = smem_base + (u32)s * STAGE_B;
#pragma unroll
        for (int tile = 0; tile < 4; tile++) {
#pragma unroll
            for (int j = 0; j < 2; j++) {
                int f = t + 256 * j;                 // 0..511
                int row = f >> 2, c = f & 3;         // 128 rows x 4 x 16B
                const __nv_bfloat16* g = srcs[tile] + (size_t)row * K + n * BKC + c * 8;
                u32 d = sb + (u32)tile * TILE_B + (u32)(row * SROW + c * 8) * 2;
                asm volatile("cp.async.cg.shared.global [%0], [%1], 16;"
                             :: "r"(d), "l"(g));
            }
        }
        asm volatile("cp.async.commit_group;" ::: "memory");
    };

    float acc[2][8][4];
#pragma unroll
    for (int mt = 0; mt < 2; mt++)
#pragma unroll
        for (int nt = 0; nt < 8; nt++)
#pragma unroll
            for (int e = 0; e < 4; e++) acc[mt][nt][e] = 0.f;

    // ldmatrix per-lane geometry
    const int aRow = wm * 32 + (lane & 7) + ((lane >> 3) & 1) * 8;
    const u32 aOff = (u32)((aRow * SROW + (lane >> 4) * 8) * 2);
    const int bRow = wn * 64 + (lane & 7) + ((lane >> 4) & 1) * 8;
    const u32 bOff = (u32)((bRow * SROW + ((lane >> 3) & 1) * 8) * 2);

    load_chunk(0, 0);

    for (int n = 0; n < NCHUNK; n++) {
        int s = n & 1;
        asm volatile("cp.async.wait_group 0;" ::: "memory");
        __syncthreads();
        if (n + 1 < NCHUNK) load_chunk(n + 1, 1 - s);

        u32 sb = smem_base + (u32)s * STAGE_B;

#pragma unroll
        for (int k16 = 0; k16 < 2; k16++) {
            const u32 kb = (u32)(k16 * 16 * 2);
            u32 bh[8][2], bl[8][2];
#pragma unroll
            for (int p = 0; p < 4; p++) {
                u32 base = sb + 2 * TILE_B + bOff + (u32)(p * 16 * SROW) * 2 + kb;
                ldsm_x4(bh[2 * p][0], bh[2 * p][1], bh[2 * p + 1][0], bh[2 * p + 1][1], base);
                ldsm_x4(bl[2 * p][0], bl[2 * p][1], bl[2 * p + 1][0], bl[2 * p + 1][1], base + TILE_B);
            }
#pragma unroll
            for (int mt = 0; mt < 2; mt++) {
                u32 ah[4], al[4];
                u32 base = sb + aOff + (u32)(mt * 16 * SROW) * 2 + kb;
                ldsm_x4(ah[0], ah[1], ah[2], ah[3], base);
                ldsm_x4(al[0], al[1], al[2], al[3], base + TILE_B);
#pragma unroll
                for (int nt = 0; nt < 8; nt++) {
                    mma_bf16(acc[mt][nt], ah, bh[nt]);
                    mma_bf16(acc[mt][nt], ah, bl[nt]);
                    mma_bf16(acc[mt][nt], al, bh[nt]);
                }
            }
        }
    }

    // epilogue
    const int gid = lane >> 2, tig = lane & 3;
#pragma unroll
    for (int mt = 0; mt < 2; mt++) {
        int rbase = by * 128 + wm * 32 + mt * 16;
#pragma unroll
        for (int nt = 0; nt < 8; nt++) {
            int cbase = bx * 128 + wn * 64 + nt * 8 + tig * 2;
            float* p0 = C + (size_t)(rbase + gid) * N + cbase;
            float* p1 = C + (size_t)(rbase + gid + 8) * N + cbase;
            p0[0] = acc[mt][nt][0]; p0[1] = acc[mt][nt][1];
            p1[0] = acc[mt][nt][2]; p1[1] = acc[mt][nt][3];
        }
    }
}

// ---------------- a/b projection: d_ab[s][0:32]=x@Wa^T, [32:64]=x@Wb^T --
__global__ void __launch_bounds__(256) ab_gemm(const float* __restrict__ x,
                                               const float* __restrict__ Wa,
                                               const float* __restrict__ Wb) {
    __shared__ float Xs[32][64];
    __shared__ float Ws[32][64];
    const int t = threadIdx.x;
    const int s0 = blockIdx.x * 64;
    const int tx = t & 15, ty = t >> 4;
    float acc[4][4];
#pragma unroll
    for (int i = 0; i < 4; i++)
#pragma unroll
        for (int j = 0; j < 4; j++) acc[i][j] = 0.f;

    for (int k0 = 0; k0 < HIDN; k0 += 32) {
        for (int e = t; e < 2048; e += 256) {
            int r = e >> 5, c = e & 31;
            Xs[c][r] = x[(size_t)(s0 + r) * HIDN + k0 + c];
            const float* Wrow = (r < 32) ? (Wa + (size_t)r * HIDN) : (Wb + (size_t)(r - 32) * HIDN);
            Ws[c][r] = Wrow[k0 + c];
        }
        __syncthreads();
#pragma unroll
        for (int kk = 0; kk < 32; kk++) {
            float a[4], b[4];
#pragma unroll
            for (int i = 0; i < 4; i++) { a[i] = Xs[kk][ty * 4 + i]; b[i] = Ws[kk][tx * 4 + i]; }
#pragma unroll
            for (int i = 0; i < 4; i++)
#pragma unroll
                for (int j = 0; j < 4; j++) acc[i][j] += a[i] * b[j];
        }
        __syncthreads();
    }
#pragma unroll
    for (int i = 0; i < 4; i++)
#pragma unroll
        for (int j = 0; j < 4; j++)
            d_ab[(size_t)(s0 + ty * 4 + i) * 64 + tx * 4 + j] = acc[i][j];
}

// ---------------- causal depthwise conv(K=4) + SiLU + split (sliding) ---
__global__ void __launch_bounds__(256) conv_silu(const float* __restrict__ cw) {
    int c   = blockIdx.x * 256 + threadIdx.x;   // channel
    int seg = blockIdx.y;                       // 8 segments of 256
    float w0 = cw[c * 4], w1 = cw[c * 4 + 1], w2 = cw[c * 4 + 2], w3 = cw[c * 4 + 3];
    int s0 = seg * 256;
    float xm3 = (s0 >= 3) ? d_mixed[(size_t)(s0 - 3) * CDIM + c] : 0.f;
    float xm2 = (s0 >= 2) ? d_mixed[(size_t)(s0 - 2) * CDIM + c] : 0.f;
    float xm1 = (s0 >= 1) ? d_mixed[(size_t)(s0 - 1) * CDIM + c] : 0.f;
    for (int i = 0; i < 256; i++) {
        int s = s0 + i;
        float xs = d_mixed[(size_t)s * CDIM + c];
        float acc = w0 * xm3 + w1 * xm2 + w2 * xm1 + w3 * xs;
        float r = acc / (1.f + expf(-acc));
        if (c < 2048)      d_q[(size_t)s * 2048 + c] = r;
        else if (c < 4096) d_k[(size_t)s * 2048 + (c - 2048)] = r;
        else               d_v[(size_t)s * 4096 + (c - 4096)] = r;
        xm3 = xm2; xm2 = xm1; xm1 = xs;
    }
}

// ---------------- l2norm on q (with DK^-0.5) and k -----------------------
__global__ void l2norm_kernel() {
    int b = blockIdx.x, t = threadIdx.x;          // 128 threads per block
    float* buf = (blockIdx.y == 0) ? d_q : d_k;
    size_t idx = (size_t)b * 128 + t;
    float v = buf[idx];
    float ss = v * v;
#pragma unroll
    for (int o = 16; o > 0; o >>= 1) ss += __shfl_xor_sync(~0u, ss, o);
    __shared__ float ws[4];
    if ((t & 31) == 0) ws[t >> 5] = ss;
    __syncthreads();
    ss = (ws[0] + ws[1]) + (ws[2] + ws[3]);
    float sc = rsqrtf(ss + 1e-6f);
    if (blockIdx.y == 0) sc *= 0.08838834764831845f;   // DK^-0.5
    buf[idx] = v * sc;
}

// ---------------- gate: g (chunk-local cumsum), beta, exp(g_last) --------
__global__ void gate_kernel(const float* __restrict__ dt_bias,
                            const float* __restrict__ A_log) {
    int h = blockIdx.x, n = blockIdx.y, i = threadIdx.x;  // 64 threads
    int s = n * CHK + i;
    float a = d_ab[(size_t)s * 64 + h];
    float b = d_ab[(size_t)s * 64 + 32 + h];
    float xx = a + dt_bias[h];
    float sp = fmaxf(xx, 0.f) + log1pf(expf(-fabsf(xx)));
    float gv = -expf(A_log[h]) * sp;
    float beta = 1.f / (1.f + expf(-b));
    int lane = i & 31;
#pragma unroll
    for (int o = 1; o < 32; o <<= 1) {
        float nv = __shfl_up_sync(~0u, gv, o);
        if (lane >= o) gv += nv;
    }
    __shared__ float carry;
    if (i == 31) carry = gv;
    __syncthreads();
    if (i >= 32) gv += carry;
    d_g[(size_t)h * SEQ + s] = gv;
    d_beta[(size_t)h * SEQ + s] = beta;
    if (i == 63) d_egl[h * NCH + n] = expf(gv);
}

// ---------------- intra-chunk: A, UT transform, u, kcd, scores, qg, kbar -
__global__ void __launch_bounds__(256) intra_kernel() {
    float* sm = (float*)dyn_smem;
    float* sq  = sm;              // 64*128
    float* sk  = sm + 8192;       // 64*128
    float* sv  = sm + 16384;      // 64*128
    float* sA  = sm + 24576;      // 64*64
    float* sA2 = sm + 28672;      // 64*64
    float* sg  = sm + 32768;      // 64
    float* sb  = sm + 32832;      // 64
    float* scv = sm + 32896;      // 64
    float* sP  = sm + 32960;      // 256

    const int n = blockIdx.x, h = blockIdx.y, kvh = h >> 1, t = threadIdx.x;
    const int sbase = n * CHK;

    for (int e = t; e < 2048; e += 256) {
        int i = e >> 5, d = (e & 31) << 2;
        int s = sbase + i;
        *(float4*)&sq[i * 128 + d] = *(const float4*)&d_q[((size_t)s * NKH + kvh) * 128 + d];
        *(float4*)&sk[i * 128 + d] = *(const float4*)&d_k[((size_t)s * NKH + kvh) * 128 + d];
        *(float4*)&sv[i * 128 + d] = *(const float4*)&d_v[((size_t)s * NVH + h) * 128 + d];
    }
    if (t < 64) {
        sg[t] = d_g[(size_t)h * SEQ + sbase + t];
        sb[t] = d_beta[(size_t)h * SEQ + sbase + t];
    }
    __syncthreads();

    const int i0 = (t >> 4) << 2, j0 = (t & 15) << 2;

    // ---- A[i][j] = -(kb_i . k_j) * exp(g_i - g_j) for i>j ----
    {
        float acc[4][4];
#pragma unroll
        for (int ii = 0; ii < 4; ii++)
#pragma unroll
            for (int jj = 0; jj < 4; jj++) acc[ii][jj] = 0.f;
        for (int kk = 0; kk < 128; kk += 4) {
            float4 ar[4], br[4];
#pragma unroll
            for (int ii = 0; ii < 4; ii++) {
                ar[ii] = *(const float4*)&sk[(i0 + ii) * 128 + kk];
                br[ii] = *(const float4*)&sk[(j0 + ii) * 128 + kk];
            }
#pragma unroll
            for (int ii = 0; ii < 4; ii++)
#pragma unroll
                for (int jj = 0; jj < 4; jj++)
                    acc[ii][jj] += ar[ii].x * br[jj].x + ar[ii].y * br[jj].y +
                                   ar[ii].z * br[jj].z + ar[ii].w * br[jj].w;
        }
#pragma unroll
        for (int ii = 0; ii < 4; ii++)
#pragma unroll
            for (int jj = 0; jj < 4; jj++) {
                int i = i0 + ii, j = j0 + jj;
                sA[i * 64 + j] = (i > j) ? -sb[i] * acc[ii][jj] * expf(sg[i] - sg[j]) : 0.f;
            }
    }
    __syncthreads();

    // ---- UT transform (forward substitution), 4-way partial parallel ----
    {
        int j = t & 63, pt = t >> 6;
        for (int i = 1; i < 64; i++) {
            float p = 0.f;
            if (j < i)
                for (int kk = j + 1 + pt; kk < i; kk += 4)
                    p += sA[i * 64 + kk] * sA[kk * 64 + j];
            sP[t] = p;
            __syncthreads();
            if (t < i) sA[i * 64 + t] += sP[t] + sP[64 + t] + sP[128 + t] + sP[192 + t];
            __syncthreads();
        }
    }

    // ---- scale v by beta; c[k] = beta*exp(g) ----
    for (int e = t; e < 8192; e += 256) sv[e] *= sb[e >> 7];
    if (t < 64) scv[t] = sb[t] * expf(sg[t]);
    __syncthreads();

    const int dv = t & 127, half = t >> 7;

    // ---- u = (I + A) @ vb ----
    for (int ii = 0; ii < 32; ii++) {
        int i = half * 32 + ii;
        float a = sv[i * 128 + dv];
        for (int kk = 0; kk < i; kk++) a += sA[i * 64 + kk] * sv[kk * 128 + dv];
        d_u[((size_t)h * SEQ + sbase + i) * 128 + dv] = a;
    }
    // ---- A2 = A * diag(c) (column scale) ----
    for (int e = t; e < 4096; e += 256) sA2[e] = sA[e] * scv[e & 63];
    __syncthreads();

    // ---- kcd = (I+A) @ (kb * e^g);  qg = q*e^g;  kbar = k*e^(gl-g) ----
    const float gl = sg[63];
    for (int ii = 0; ii < 32; ii++) {
        int i = half * 32 + ii;
        float eg  = expf(sg[i]);
        float egr = expf(gl - sg[i]);
        float a = sk[i * 128 + dv] * scv[i];
        for (int kk = 0; kk < i; kk++) a += sA2[i * 64 + kk] * sk[kk * 128 + dv];
        size_t rb = ((size_t)h * SEQ + sbase + i) * 128 + dv;
        d_kcd[rb]  = a;
        d_qg[rb]   = sq[i * 128 + dv] * eg;
        d_kbar[rb] = sk[i * 128 + dv] * egr;
    }

    // ---- scores[i][j] = (q_i . k_j) * exp(g_i - g_j), i >= j ----
    {
        float acc[4][4];
#pragma unroll
        for (int ii = 0; ii < 4; ii++)
#pragma unroll
            for (int jj = 0; jj < 4; jj++) acc[ii][jj] = 0.f;
        for (int kk = 0; kk < 128; kk += 4) {
            float4 ar[4], br[4];
#pragma unroll
            for (int ii = 0; ii < 4; ii++) {
                ar[ii] = *(const float4*)&sq[(i0 + ii) * 128 + kk];
                br[ii] = *(const float4*)&sk[(j0 + ii) * 128 + kk];
            }
#pragma unroll
            for (int ii = 0; ii < 4; ii++)
#pragma unroll
                for (int jj = 0; jj < 4; jj++)
                    acc[ii][jj] += ar[ii].x * br[jj].x + ar[ii].y * br[jj].y +
                                   ar[ii].z * br[jj].z + ar[ii].w * br[jj].w;
        }
#pragma unroll
        for (int ii = 0; ii < 4; ii++)
#pragma unroll
            for (int jj = 0; jj < 4; jj++) {
                int i = i0 + ii, j = j0 + jj;
                d_sc[((size_t)h * NCH + n) * 4096 + i * 64 + j] =
                    (i >= j) ? acc[ii][jj] * expf(sg[i] - sg[j]) : 0.f;
            }
    }
}

// ---------------- sequential inter-chunk scan (per head, per DV-slice) ---
__global__ void __launch_bounds__(512) scan_kernel() {
    float* sm = (float*)dyn_smem;
    float* st  = sm;           // 128*32 state slice
    float* skc = sm + 4096;    // 64*128 kcd
    float* sqg = sm + 12288;   // 64*128 qg
    float* skb = sm + 20480;   // 64*128 kbar
    float* ssc = sm + 28672;   // 64*64 scores
    float* svn = sm + 32768;   // 64*32 v_new
    float* su  = sm + 34816;   // 64*32 u slice

    const int h = blockIdx.x >> 2, sl = blockIdx.x & 3, t = threadIdx.x;
    const int dv0 = sl * 32;

    for (int e = t; e < 4096; e += 512) st[e] = 0.f;

    for (int n = 0; n < NCH; n++) {
        const size_t rb = ((size_t)h * SEQ + n * CHK) * 128;
        for (int e = t; e < 2048; e += 512) {
            ((float4*)skc)[e] = ((const float4*)(d_kcd + rb))[e];
            ((float4*)sqg)[e] = ((const float4*)(d_qg + rb))[e];
            ((float4*)skb)[e] = ((const float4*)(d_kbar + rb))[e];
        }
        const size_t scb = ((size_t)h * NCH + n) * 4096;
        for (int e = t; e < 1024; e += 512)
            ((float4*)ssc)[e] = ((const float4*)(d_sc + scb))[e];
        {
            int e = t;  // exactly 512 float4s
            int i = e >> 3, q4 = e & 7;
            ((float4*)su)[e] = *(const float4*)&d_u[rb + (size_t)i * 128 + dv0 + q4 * 4];
        }
        __syncthreads();

        const float egl = d_egl[h * NCH + n];

        // v_new = u - kcd @ state
#pragma unroll
        for (int r = 0; r < 2; r++) {
            int idx = t + 512 * r;
            int i = idx >> 4, dp = (idx & 15) << 1;
            u64 a = *(u64*)&su[i * 32 + dp];
            for (int dk = 0; dk < 128; dk++) {
                float kv = -skc[i * 128 + dk];
                fma2(a, pack2(kv, kv), *(u64*)&st[dk * 32 + dp]);
            }
            *(u64*)&svn[i * 32 + dp] = a;
        }
        __syncthreads();

        // o = qg @ state + scores @ v_new
#pragma unroll
        for (int r = 0; r < 2; r++) {
            int idx = t + 512 * r;
            int i = idx >> 4, dp = (idx & 15) << 1;
            u64 a = 0ull;
            for (int dk = 0; dk < 128; dk++) {
                float qv = sqg[i * 128 + dk];
                fma2(a, pack2(qv, qv), *(u64*)&st[dk * 32 + dp]);
            }
            for (int j = 0; j <= i; j++) {
                float sv_ = ssc[i * 64 + j];
                fma2(a, pack2(sv_, sv_), *(u64*)&svn[j * 32 + dp]);
            }
            float2 p = unpack2(a);
            *(float2*)&d_o[rb + (size_t)i * 128 + dv0 + dp] = p;
        }
        __syncthreads();

        // state = state*egl + kbar^T @ v_new
#pragma unroll
        for (int r = 0; r < 4; r++) {
            int idx = t + 512 * r;
            int dk = idx >> 4, dp = (idx & 15) << 1;
            u64 a = pack2(st[dk * 32 + dp] * egl, st[dk * 32 + dp + 1] * egl);
            for (int i = 0; i < 64; i++) {
                float kb = skb[i * 128 + dk];
                fma2(a, pack2(kb, kb), *(u64*)&svn[i * 32 + dp]);
            }
            float2 p = unpack2(a);
            st[dk * 32 + dp] = p.x;
            st[dk * 32 + dp + 1] = p.y;
        }
        __syncthreads();
    }
}

// ---------------- RMSNorm + z-gate epilogue -> bf16 hi/lo ----------------
__global__ void rms_kernel(const float* __restrict__ norm_w) {
    int b = blockIdx.x;
    int s = b >> 5, h = b & 31, t = threadIdx.x;   // 128 threads
    float v = d_o[((size_t)h * SEQ + s) * 128 + t];
    float ss = v * v;
#pragma unroll
    for (int o = 16; o > 0; o >>= 1) ss += __shfl_xor_sync(~0u, ss, o);
    __shared__ float ws[4];
    if ((t & 31) == 0) ws[t >> 5] = ss;
    __syncthreads();
    ss = (ws[0] + ws[1]) + (ws[2] + ws[3]);
    float r = rsqrtf(ss * (1.f / 128.f) + 1e-6f);
    float z = d_z[(size_t)s * VALD + h * 128 + t];
    float sz = z / (1.f + expf(-z));
    float val = v * r * norm_w[t] * sz;
    size_t idx = (size_t)s * VALD + h * 128 + t;
    __nv_bfloat16 hh = __float2bfloat16(val);
    g_yh[idx] = hh;
    g_yl[idx] = __float2bfloat16(val - __bfloat162float(hh));
}

// ---------------- launch ---------------------------------------------------
extern "C" void kernel_launch(void* const* d_in, const int* in_sizes, int n_in,
                              void* d_out, int out_size) {
    const float* x       = (const float*)d_in[0];
    const float* W_qkv   = (const float*)d_in[1];
    const float* W_z     = (const float*)d_in[2];
    const float* W_a     = (const float*)d_in[3];
    const float* W_b     = (const float*)d_in[4];
    const float* conv_w  = (const float*)d_in[5];
    const float* dt_bias = (const float*)d_in[6];
    const float* A_log   = (const float*)d_in[7];
    const float* norm_w  = (const float*)d_in[8];
    const float* W_out   = (const float*)d_in[9];
    float* out = (float*)d_out;

    void *p_mixed, *p_z;
    cudaGetSymbolAddress(&p_mixed, d_mixed);
    cudaGetSymbolAddress(&p_z, d_z);
    void *p_xh, *p_xl, *p_qkh, *p_qkl, *p_wzh, *p_wzl, *p_woh, *p_wol, *p_yh, *p_yl;
    cudaGetSymbolAddress(&p_xh, g_xh);   cudaGetSymbolAddress(&p_xl, g_xl);
    cudaGetSymbolAddress(&p_qkh, g_qkh); cudaGetSymbolAddress(&p_qkl, g_qkl);
    cudaGetSymbolAddress(&p_wzh, g_wzh); cudaGetSymbolAddress(&p_wzl, g_wzl);
    cudaGetSymbolAddress(&p_woh, g_woh); cudaGetSymbolAddress(&p_wol, g_wol);
    cudaGetSymbolAddress(&p_yh, g_yh);   cudaGetSymbolAddress(&p_yl, g_yl);

    const int INTRA_SMEM = 33216 * 4;
    const int SCAN_SMEM  = 36864 * 4;
    cudaFuncSetAttribute(intra_kernel, cudaFuncAttributeMaxDynamicSharedMemorySize, INTRA_SMEM);
    cudaFuncSetAttribute(scan_kernel,  cudaFuncAttributeMaxDynamicSharedMemorySize, SCAN_SMEM);
    cudaFuncSetAttribute(tc_gemm,      cudaFuncAttributeMaxDynamicSharedMemorySize, GEMM_SMEM_BYTES);

    // launches 1-5: all converts + ab so launch #6 (ncu -s 5 -c 1) is tc_gemm(qkv)
    cvt_split<<<(SEQ * HIDN / 4 + 255) / 256, 256>>>(x, (__nv_bfloat16*)p_xh, (__nv_bfloat16*)p_xl, SEQ * HIDN / 4);
    cvt_split<<<(CDIM * HIDN / 4 + 255) / 256, 256>>>(W_qkv, (__nv_bfloat16*)p_qkh, (__nv_bfloat16*)p_qkl, CDIM * HIDN / 4);
    cvt_split<<<(VALD * HIDN / 4 + 255) / 256, 256>>>(W_z, (__nv_bfloat16*)p_wzh, (__nv_bfloat16*)p_wzl, VALD * HIDN / 4);
    cvt_split<<<(HIDN * VALD / 4 + 255) / 256, 256>>>(W_out, (__nv_bfloat16*)p_woh, (__nv_bfloat16*)p_wol, HIDN * VALD / 4);
    ab_gemm<<<SEQ / 64, 256>>>(x, W_a, W_b);

    // launch #6: the dominant GEMM (profiled)
    tc_gemm<<<dim3(CDIM / 128, SEQ / 128), 256, GEMM_SMEM_BYTES>>>(
        (const __nv_bfloat16*)p_xh, (const __nv_bfloat16*)p_xl,
        (const __nv_bfloat16*)p_qkh, (const __nv_bfloat16*)p_qkl,
        (float*)p_mixed, CDIM, HIDN);
    tc_gemm<<<dim3(VALD / 128, SEQ / 128), 256, GEMM_SMEM_BYTES>>>(
        (const __nv_bfloat16*)p_xh, (const __nv_bfloat16*)p_xl,
        (const __nv_bfloat16*)p_wzh, (const __nv_bfloat16*)p_wzl,
        (float*)p_z, VALD, HIDN);

    // conv + silu + split
    conv_silu<<<dim3(CDIM / 256, 8), 256>>>(conv_w);

    // l2norm q (scaled) and k
    l2norm_kernel<<<dim3(SEQ * NKH, 2), 128>>>();

    // gates
    gate_kernel<<<dim3(NVH, NCH), 64>>>(dt_bias, A_log);

    // intra-chunk precompute
    intra_kernel<<<dim3(NCH, NVH), 256, INTRA_SMEM>>>();

    // sequential inter-chunk scan (32 heads x 4 DV-slices)
    scan_kernel<<<NVH * 4, 512, SCAN_SMEM>>>();

    // rmsnorm + gate epilogue -> bf16 hi/lo
    rms_kernel<<<SEQ * NVH, 128>>>(norm_w);

    // output projection on tensor cores
    tc_gemm<<<dim3(HIDN / 128, SEQ / 128), 256, GEMM_SMEM_BYTES>>>(
        (const __nv_bfloat16*)p_yh, (const __nv_bfloat16*)p_yl,
        (const __nv_bfloat16*)p_woh, (const __nv_bfloat16*)p_wol,
        out, HIDN, VALD);
}

// round 11
// speedup vs baseline: 1.9279x; 1.1120x over previous
#include <cuda_runtime.h>
#include <cuda_fp16.h>
#include <math.h>

// ---------------- problem constants ----------------
#define SEQ   2048
#define HIDN  2048
#define NKH   16
#define NVH   32
#define DKD   128
#define DVD   128
#define CDIM  8192
#define VALD  4096
#define NCH   32      // chunks
#define CHK   64      // chunk size

typedef unsigned long long u64;
typedef unsigned int u32;

// single dynamic smem symbol shared by all kernels
extern __shared__ __align__(16) char dyn_smem[];

// ---------------- scratch (device globals; no cudaMalloc allowed) -------
__device__ float d_mixed[SEQ * CDIM];
__device__ float d_z   [SEQ * VALD];
__device__ float d_ab  [SEQ * 64];
__device__ float d_q   [SEQ * 2048];
__device__ float d_k   [SEQ * 2048];
__device__ float d_v   [SEQ * VALD];
__device__ float d_g   [NVH * SEQ];
__device__ float d_beta[NVH * SEQ];
__device__ float d_egl [NVH * NCH];
__device__ float d_u   [NVH * SEQ * DVD];
__device__ float d_kcd [NVH * SEQ * DKD];
__device__ float d_qg  [NVH * SEQ * DKD];
__device__ float d_kbar[NVH * SEQ * DKD];
__device__ float d_sc  [NVH * NCH * CHK * CHK];
__device__ float d_o   [NVH * SEQ * DVD];

// fp16 split buffers for tensor-core GEMMs
__device__ __half g_xh  [SEQ * HIDN],  g_xl  [SEQ * HIDN];
__device__ __half g_qkh [CDIM * HIDN], g_qkl [CDIM * HIDN];
__device__ __half g_wzh [VALD * HIDN], g_wzl [VALD * HIDN];
__device__ __half g_woh [HIDN * VALD], g_wol [HIDN * VALD];
__device__ __half g_yh  [SEQ * VALD],  g_yl  [SEQ * VALD];

// ---------------- packed f32x2 helpers ----------------
__device__ __forceinline__ u64 pack2(float lo, float hi) {
    u64 r; asm("mov.b64 %0,{%1,%2};" : "=l"(r) : "f"(lo), "f"(hi)); return r;
}
__device__ __forceinline__ float2 unpack2(u64 v) {
    float2 r; asm("mov.b64 {%0,%1},%2;" : "=f"(r.x), "=f"(r.y) : "l"(v)); return r;
}
__device__ __forceinline__ void fma2(u64& d, u64 a, u64 b) {
    asm("fma.rn.f32x2 %0,%1,%2,%0;" : "+l"(d) : "l"(a), "l"(b));
}

// ---------------- fp32 -> fp16 hi/lo split ----------------
__global__ void __launch_bounds__(256) cvt_split(const float* __restrict__ s,
                                                 __half* __restrict__ h,
                                                 __half* __restrict__ l,
                                                 int n4) {
    int i = blockIdx.x * 256 + threadIdx.x;
    if (i >= n4) return;
    float4 v = ((const float4*)s)[i];
    __half h0 = __float2half_rn(v.x);
    __half h1 = __float2half_rn(v.y);
    __half h2 = __float2half_rn(v.z);
    __half h3 = __float2half_rn(v.w);
    __half2* hp = (__half2*)h;
    __half2* lp = (__half2*)l;
    hp[2 * i]     = __half2(h0, h1);
    hp[2 * i + 1] = __half2(h2, h3);
    lp[2 * i]     = __half2(__float2half_rn(v.x - __half2float(h0)),
                            __float2half_rn(v.y - __half2float(h1)));
    lp[2 * i + 1] = __half2(__float2half_rn(v.z - __half2float(h2)),
                            __float2half_rn(v.w - __half2float(h3)));
}

// ---------------- warp-MMA fp16 GEMM: C[M,N] = A[M,K] @ B[N,K]^T --------
// TERMS=2: C = Ah*Bh + Al*Bh (B truncated to fp16, 3 smem tiles)
// TERMS=3: C = Ah*Bh + Al*Bh + Ah*Bl (4 smem tiles)
// CTA tile 128x128, 8 warps (4M x 2N), warp tile 32x64 (m16n8k16),
// BK=32, 2-stage cp.async pipeline, ldmatrix fragment loads.
#define BKC   32
#define SROW  40                           // fp16 elems per smem row (80B)
#define TILE_W (128 * SROW)
#define TILE_B (TILE_W * 2)                // 10240 bytes per tile
#define GEMM_SMEM2 (2 * 3 * TILE_B)        // 61440
#define GEMM_SMEM3 (2 * 4 * TILE_B)        // 81920

__device__ __forceinline__ void mma_f16(float* c, const u32* a, const u32* b) {
    asm volatile(
        "mma.sync.aligned.m16n8k16.row.col.f32.f16.f16.f32 "
        "{%0,%1,%2,%3}, {%4,%5,%6,%7}, {%8,%9}, {%0,%1,%2,%3};"
        : "+f"(c[0]), "+f"(c[1]), "+f"(c[2]), "+f"(c[3])
        : "r"(a[0]), "r"(a[1]), "r"(a[2]), "r"(a[3]), "r"(b[0]), "r"(b[1]));
}

__device__ __forceinline__ void ldsm_x4(u32& r0, u32& r1, u32& r2, u32& r3, u32 addr) {
    asm volatile("ldmatrix.sync.aligned.m8n8.x4.shared.b16 {%0,%1,%2,%3}, [%4];"
                 : "=r"(r0), "=r"(r1), "=r"(r2), "=r"(r3) : "r"(addr));
}

template <int TERMS>
__global__ void __launch_bounds__(256, 2)
tc_gemm(const __half* __restrict__ Ah, const __half* __restrict__ Al,
        const __half* __restrict__ Bh, const __half* __restrict__ Bl,
        float* __restrict__ C, int N, int K) {
    constexpr int NT = (TERMS == 2) ? 3 : 4;       // tiles per stage
    constexpr u32 STG = NT * TILE_B;

    __half* sm = (__half*)dyn_smem;

    const int t = threadIdx.x, lane = t & 31, wid = t >> 5;
    const int wm = wid & 3, wn = wid >> 2;          // 4 M-warps x 2 N-warps
    const int bx = blockIdx.x, by = blockIdx.y;
    const int NCHUNK = K / BKC;

    u32 smem_base;
    asm("{ .reg .u64 tt; cvta.to.shared.u64 tt, %1; cvt.u32.u64 %0, tt; }"
        : "=r"(smem_base) : "l"(sm));

    const __half* srcs[4] = {
        Ah + (size_t)by * 128 * K, Al + (size_t)by * 128 * K,
        Bh + (size_t)bx * 128 * K, Bl + (size_t)bx * 128 * K};

    auto load_chunk = [&](int n, int s) {
        u32 sb = smem_base + (u32)s * STG;
#pragma unroll
        for (int tile = 0; tile < NT; tile++) {
#pragma unroll
            for (int j = 0; j < 2; j++) {
                int f = t + 256 * j;                 // 0..511
                int row = f >> 2, c = f & 3;         // 128 rows x 4 x 16B
                const __half* g = srcs[tile] + (size_t)row * K + n * BKC + c * 8;
                u32 d = sb + (u32)tile * TILE_B + (u32)(row * SROW + c * 8) * 2;
                asm volatile("cp.async.cg.shared.global [%0], [%1], 16;"
                             :: "r"(d), "l"(g));
            }
        }
        asm volatile("cp.async.commit_group;" ::: "memory");
    };

    float acc[2][8][4];
#pragma unroll
    for (int mt = 0; mt < 2; mt++)
#pragma unroll
        for (int nt = 0; nt < 8; nt++)
#pragma unroll
            for (int e = 0; e < 4; e++) acc[mt][nt][e] = 0.f;

    // ldmatrix per-lane geometry
    const int aRow = wm * 32 + (lane & 7) + ((lane >> 3) & 1) * 8;
    const u32 aOff = (u32)((aRow * SROW + (lane >> 4) * 8) * 2);
    const int bRow = wn * 64 + (lane & 7) + ((lane >> 4) & 1) * 8;
    const u32 bOff = (u32)((bRow * SROW + ((lane >> 3) & 1) * 8) * 2);

    load_chunk(0, 0);

    for (int n = 0; n < NCHUNK; n++) {
        int s = n & 1;
        asm volatile("cp.async.wait_group 0;" ::: "memory");
        __syncthreads();
        if (n + 1 < NCHUNK) load_chunk(n + 1, 1 - s);

        u32 sb = smem_base + (u32)s * STG;

#pragma unroll
        for (int k16 = 0; k16 < 2; k16++) {
            const u32 kb = (u32)(k16 * 16 * 2);
            u32 bh[8][2], bl[8][2];
#pragma unroll
            for (int p = 0; p < 4; p++) {
                u32 base = sb + 2 * TILE_B + bOff + (u32)(p * 16 * SROW) * 2 + kb;
                ldsm_x4(bh[2 * p][0], bh[2 * p][1], bh[2 * p + 1][0], bh[2 * p + 1][1], base);
                if (TERMS == 3)
                    ldsm_x4(bl[2 * p][0], bl[2 * p][1], bl[2 * p + 1][0], bl[2 * p + 1][1],
                            base + TILE_B);
            }
#pragma unroll
            for (int mt = 0; mt < 2; mt++) {
                u32 ah[4], al[4];
                u32 base = sb + aOff + (u32)(mt * 16 * SROW) * 2 + kb;
                ldsm_x4(ah[0], ah[1], ah[2], ah[3], base);
                ldsm_x4(al[0], al[1], al[2], al[3], base + TILE_B);
#pragma unroll
                for (int nt = 0; nt < 8; nt++) {
                    mma_f16(acc[mt][nt], ah, bh[nt]);
                    mma_f16(acc[mt][nt], al, bh[nt]);
                    if (TERMS == 3) mma_f16(acc[mt][nt], ah, bl[nt]);
                }
            }
        }
    }

    // epilogue
    const int gid = lane >> 2, tig = lane & 3;
#pragma unroll
    for (int mt = 0; mt < 2; mt++) {
        int rbase = by * 128 + wm * 32 + mt * 16;
#pragma unroll
        for (int nt = 0; nt < 8; nt++) {
            int cbase = bx * 128 + wn * 64 + nt * 8 + tig * 2;
            float* p0 = C + (size_t)(rbase + gid) * N + cbase;
            float* p1 = C + (size_t)(rbase + gid + 8) * N + cbase;
            p0[0] = acc[mt][nt][0]; p0[1] = acc[mt][nt][1];
            p1[0] = acc[mt][nt][2]; p1[1] = acc[mt][nt][3];
        }
    }
}

// ---------------- a/b projection: d_ab[s][0:32]=x@Wa^T, [32:64]=x@Wb^T --
__global__ void __launch_bounds__(256) ab_gemm(const float* __restrict__ x,
                                               const float* __restrict__ Wa,
                                               const float* __restrict__ Wb) {
    __shared__ float Xs[32][64];
    __shared__ float Ws[32][64];
    const int t = threadIdx.x;
    const int s0 = blockIdx.x * 64;
    const int tx = t & 15, ty = t >> 4;
    float acc[4][4];
#pragma unroll
    for (int i = 0; i < 4; i++)
#pragma unroll
        for (int j = 0; j < 4; j++) acc[i][j] = 0.f;

    for (int k0 = 0; k0 < HIDN; k0 += 32) {
        for (int e = t; e < 2048; e += 256) {
            int r = e >> 5, c = e & 31;
            Xs[c][r] = x[(size_t)(s0 + r) * HIDN + k0 + c];
            const float* Wrow = (r < 32) ? (Wa + (size_t)r * HIDN) : (Wb + (size_t)(r - 32) * HIDN);
            Ws[c][r] = Wrow[k0 + c];
        }
        __syncthreads();
#pragma unroll
        for (int kk = 0; kk < 32; kk++) {
            float a[4], b[4];
#pragma unroll
            for (int i = 0; i < 4; i++) { a[i] = Xs[kk][ty * 4 + i]; b[i] = Ws[kk][tx * 4 + i]; }
#pragma unroll
            for (int i = 0; i < 4; i++)
#pragma unroll
                for (int j = 0; j < 4; j++) acc[i][j] += a[i] * b[j];
        }
        __syncthreads();
    }
#pragma unroll
    for (int i = 0; i < 4; i++)
#pragma unroll
        for (int j = 0; j < 4; j++)
            d_ab[(size_t)(s0 + ty * 4 + i) * 64 + tx * 4 + j] = acc[i][j];
}

// ---------------- causal depthwise conv(K=4) + SiLU + split (sliding) ---
__global__ void __launch_bounds__(256) conv_silu(const float* __restrict__ cw) {
    int c   = blockIdx.x * 256 + threadIdx.x;   // channel
    int seg = blockIdx.y;                       // 8 segments of 256
    float w0 = cw[c * 4], w1 = cw[c * 4 + 1], w2 = cw[c * 4 + 2], w3 = cw[c * 4 + 3];
    int s0 = seg * 256;
    float xm3 = (s0 >= 3) ? d_mixed[(size_t)(s0 - 3) * CDIM + c] : 0.f;
    float xm2 = (s0 >= 2) ? d_mixed[(size_t)(s0 - 2) * CDIM + c] : 0.f;
    float xm1 = (s0 >= 1) ? d_mixed[(size_t)(s0 - 1) * CDIM + c] : 0.f;
    for (int i = 0; i < 256; i++) {
        int s = s0 + i;
        float xs = d_mixed[(size_t)s * CDIM + c];
        float acc = w0 * xm3 + w1 * xm2 + w2 * xm1 + w3 * xs;
        float r = acc / (1.f + expf(-acc));
        if (c < 2048)      d_q[(size_t)s * 2048 + c] = r;
        else if (c < 4096) d_k[(size_t)s * 2048 + (c - 2048)] = r;
        else               d_v[(size_t)s * 4096 + (c - 4096)] = r;
        xm3 = xm2; xm2 = xm1; xm1 = xs;
    }
}

// ---------------- l2norm on q (with DK^-0.5) and k -----------------------
__global__ void l2norm_kernel() {
    int b = blockIdx.x, t = threadIdx.x;          // 128 threads per block
    float* buf = (blockIdx.y == 0) ? d_q : d_k;
    size_t idx = (size_t)b * 128 + t;
    float v = buf[idx];
    float ss = v * v;
#pragma unroll
    for (int o = 16; o > 0; o >>= 1) ss += __shfl_xor_sync(~0u, ss, o);
    __shared__ float ws[4];
    if ((t & 31) == 0) ws[t >> 5] = ss;
    __syncthreads();
    ss = (ws[0] + ws[1]) + (ws[2] + ws[3]);
    float sc = rsqrtf(ss + 1e-6f);
    if (blockIdx.y == 0) sc *= 0.08838834764831845f;   // DK^-0.5
    buf[idx] = v * sc;
}

// ---------------- gate: g (chunk-local cumsum), beta, exp(g_last) --------
__global__ void gate_kernel(const float* __restrict__ dt_bias,
                            const float* __restrict__ A_log) {
    int h = blockIdx.x, n = blockIdx.y, i = threadIdx.x;  // 64 threads
    int s = n * CHK + i;
    float a = d_ab[(size_t)s * 64 + h];
    float b = d_ab[(size_t)s * 64 + 32 + h];
    float xx = a + dt_bias[h];
    float sp = fmaxf(xx, 0.f) + log1pf(expf(-fabsf(xx)));
    float gv = -expf(A_log[h]) * sp;
    float beta = 1.f / (1.f + expf(-b));
    int lane = i & 31;
#pragma unroll
    for (int o = 1; o < 32; o <<= 1) {
        float nv = __shfl_up_sync(~0u, gv, o);
        if (lane >= o) gv += nv;
    }
    __shared__ float carry;
    if (i == 31) carry = gv;
    __syncthreads();
    if (i >= 32) gv += carry;
    d_g[(size_t)h * SEQ + s] = gv;
    d_beta[(size_t)h * SEQ + s] = beta;
    if (i == 63) d_egl[h * NCH + n] = expf(gv);
}

// ---------------- intra-chunk: A, UT transform, u, kcd, scores, qg, kbar -
__global__ void __launch_bounds__(256) intra_kernel() {
    float* sm = (float*)dyn_smem;
    float* sq  = sm;              // 64*128
    float* sk  = sm + 8192;       // 64*128
    float* sv  = sm + 16384;      // 64*128
    float* sA  = sm + 24576;      // 64*64
    float* sA2 = sm + 28672;      // 64*64
    float* sg  = sm + 32768;      // 64
    float* sb  = sm + 32832;      // 64
    float* scv = sm + 32896;      // 64
    float* sP  = sm + 32960;      // 256

    const int n = blockIdx.x, h = blockIdx.y, kvh = h >> 1, t = threadIdx.x;
    const int sbase = n * CHK;

    for (int e = t; e < 2048; e += 256) {
        int i = e >> 5, d = (e & 31) << 2;
        int s = sbase + i;
        *(float4*)&sq[i * 128 + d] = *(const float4*)&d_q[((size_t)s * NKH + kvh) * 128 + d];
        *(float4*)&sk[i * 128 + d] = *(const float4*)&d_k[((size_t)s * NKH + kvh) * 128 + d];
        *(float4*)&sv[i * 128 + d] = *(const float4*)&d_v[((size_t)s * NVH + h) * 128 + d];
    }
    if (t < 64) {
        sg[t] = d_g[(size_t)h * SEQ + sbase + t];
        sb[t] = d_beta[(size_t)h * SEQ + sbase + t];
    }
    __syncthreads();

    const int i0 = (t >> 4) << 2, j0 = (t & 15) << 2;

    // ---- A[i][j] = -(kb_i . k_j) * exp(g_i - g_j) for i>j ----
    {
        float acc[4][4];
#pragma unroll
        for (int ii = 0; ii < 4; ii++)
#pragma unroll
            for (int jj = 0; jj < 4; jj++) acc[ii][jj] = 0.f;
        for (int kk = 0; kk < 128; kk += 4) {
            float4 ar[4], br[4];
#pragma unroll
            for (int ii = 0; ii < 4; ii++) {
                ar[ii] = *(const float4*)&sk[(i0 + ii) * 128 + kk];
                br[ii] = *(const float4*)&sk[(j0 + ii) * 128 + kk];
            }
#pragma unroll
            for (int ii = 0; ii < 4; ii++)
#pragma unroll
                for (int jj = 0; jj < 4; jj++)
                    acc[ii][jj] += ar[ii].x * br[jj].x + ar[ii].y * br[jj].y +
                                   ar[ii].z * br[jj].z + ar[ii].w * br[jj].w;
        }
#pragma unroll
        for (int ii = 0; ii < 4; ii++)
#pragma unroll
            for (int jj = 0; jj < 4; jj++) {
                int i = i0 + ii, j = j0 + jj;
                sA[i * 64 + j] = (i > j) ? -sb[i] * acc[ii][jj] * expf(sg[i] - sg[j]) : 0.f;
            }
    }
    __syncthreads();

    // ---- UT transform (forward substitution), 4-way partial parallel ----
    {
        int j = t & 63, pt = t >> 6;
        for (int i = 1; i < 64; i++) {
            float p = 0.f;
            if (j < i)
                for (int kk = j + 1 + pt; kk < i; kk += 4)
                    p += sA[i * 64 + kk] * sA[kk * 64 + j];
            sP[t] = p;
            __syncthreads();
            if (t < i) sA[i * 64 + t] += sP[t] + sP[64 + t] + sP[128 + t] + sP[192 + t];
            __syncthreads();
        }
    }

    // ---- scale v by beta; c[k] = beta*exp(g) ----
    for (int e = t; e < 8192; e += 256) sv[e] *= sb[e >> 7];
    if (t < 64) scv[t] = sb[t] * expf(sg[t]);
    __syncthreads();

    const int dv = t & 127, half = t >> 7;

    // ---- u = (I + A) @ vb ----
    for (int ii = 0; ii < 32; ii++) {
        int i = half * 32 + ii;
        float a = sv[i * 128 + dv];
        for (int kk = 0; kk < i; kk++) a += sA[i * 64 + kk] * sv[kk * 128 + dv];
        d_u[((size_t)h * SEQ + sbase + i) * 128 + dv] = a;
    }
    // ---- A2 = A * diag(c) (column scale) ----
    for (int e = t; e < 4096; e += 256) sA2[e] = sA[e] * scv[e & 63];
    __syncthreads();

    // ---- kcd = (I+A) @ (kb * e^g);  qg = q*e^g;  kbar = k*e^(gl-g) ----
    const float gl = sg[63];
    for (int ii = 0; ii < 32; ii++) {
        int i = half * 32 + ii;
        float eg  = expf(sg[i]);
        float egr = expf(gl - sg[i]);
        float a = sk[i * 128 + dv] * scv[i];
        for (int kk = 0; kk < i; kk++) a += sA2[i * 64 + kk] * sk[kk * 128 + dv];
        size_t rb = ((size_t)h * SEQ + sbase + i) * 128 + dv;
        d_kcd[rb]  = a;
        d_qg[rb]   = sq[i * 128 + dv] * eg;
        d_kbar[rb] = sk[i * 128 + dv] * egr;
    }

    // ---- scores[i][j] = (q_i . k_j) * exp(g_i - g_j), i >= j ----
    {
        float acc[4][4];
#pragma unroll
        for (int ii = 0; ii < 4; ii++)
#pragma unroll
            for (int jj = 0; jj < 4; jj++) acc[ii][jj] = 0.f;
        for (int kk = 0; kk < 128; kk += 4) {
            float4 ar[4], br[4];
#pragma unroll
            for (int ii = 0; ii < 4; ii++) {
                ar[ii] = *(const float4*)&sq[(i0 + ii) * 128 + kk];
                br[ii] = *(const float4*)&sk[(j0 + ii) * 128 + kk];
            }
#pragma unroll
            for (int ii = 0; ii < 4; ii++)
#pragma unroll
                for (int jj = 0; jj < 4; jj++)
                    acc[ii][jj] += ar[ii].x * br[jj].x + ar[ii].y * br[jj].y +
                                   ar[ii].z * br[jj].z + ar[ii].w * br[jj].w;
        }
#pragma unroll
        for (int ii = 0; ii < 4; ii++)
#pragma unroll
            for (int jj = 0; jj < 4; jj++) {
                int i = i0 + ii, j = j0 + jj;
                d_sc[((size_t)h * NCH + n) * 4096 + i * 64 + j] =
                    (i >= j) ? acc[ii][jj] * expf(sg[i] - sg[j]) : 0.f;
            }
    }
}

// ---------------- sequential inter-chunk scan (per head, per DV-slice) ---
__global__ void __launch_bounds__(512) scan_kernel() {
    float* sm = (float*)dyn_smem;
    float* st  = sm;           // 128*32 state slice
    float* skc = sm + 4096;    // 64*128 kcd
    float* sqg = sm + 12288;   // 64*128 qg
    float* skb = sm + 20480;   // 64*128 kbar
    float* ssc = sm + 28672;   // 64*64 scores
    float* svn = sm + 32768;   // 64*32 v_new
    float* su  = sm + 34816;   // 64*32 u slice

    const int h = blockIdx.x >> 2, sl = blockIdx.x & 3, t = threadIdx.x;
    const int dv0 = sl * 32;

    for (int e = t; e < 4096; e += 512) st[e] = 0.f;

    for (int n = 0; n < NCH; n++) {
        const size_t rb = ((size_t)h * SEQ + n * CHK) * 128;
        for (int e = t; e < 2048; e += 512) {
            ((float4*)skc)[e] = ((const float4*)(d_kcd + rb))[e];
            ((float4*)sqg)[e] = ((const float4*)(d_qg + rb))[e];
            ((float4*)skb)[e] = ((const float4*)(d_kbar + rb))[e];
        }
        const size_t scb = ((size_t)h * NCH + n) * 4096;
        for (int e = t; e < 1024; e += 512)
            ((float4*)ssc)[e] = ((const float4*)(d_sc + scb))[e];
        {
            int e = t;  // exactly 512 float4s
            int i = e >> 3, q4 = e & 7;
            ((float4*)su)[e] = *(const float4*)&d_u[rb + (size_t)i * 128 + dv0 + q4 * 4];
        }
        __syncthreads();

        const float egl = d_egl[h * NCH + n];

        // v_new = u - kcd @ state
#pragma unroll
        for (int r = 0; r < 2; r++) {
            int idx = t + 512 * r;
            int i = idx >> 4, dp = (idx & 15) << 1;
            u64 a = *(u64*)&su[i * 32 + dp];
            for (int dk = 0; dk < 128; dk++) {
                float kv = -skc[i * 128 + dk];
                fma2(a, pack2(kv, kv), *(u64*)&st[dk * 32 + dp]);
            }
            *(u64*)&svn[i * 32 + dp] = a;
        }
        __syncthreads();

        // o = qg @ state + scores @ v_new
#pragma unroll
        for (int r = 0; r < 2; r++) {
            int idx = t + 512 * r;
            int i = idx >> 4, dp = (idx & 15) << 1;
            u64 a = 0ull;
            for (int dk = 0; dk < 128; dk++) {
                float qv = sqg[i * 128 + dk];
                fma2(a, pack2(qv, qv), *(u64*)&st[dk * 32 + dp]);
            }
            for (int j = 0; j <= i; j++) {
                float sv_ = ssc[i * 64 + j];
                fma2(a, pack2(sv_, sv_), *(u64*)&svn[j * 32 + dp]);
            }
            float2 p = unpack2(a);
            *(float2*)&d_o[rb + (size_t)i * 128 + dv0 + dp] = p;
        }
        __syncthreads();

        // state = state*egl + kbar^T @ v_new
#pragma unroll
        for (int r = 0; r < 4; r++) {
            int idx = t + 512 * r;
            int dk = idx >> 4, dp = (idx & 15) << 1;
            u64 a = pack2(st[dk * 32 + dp] * egl, st[dk * 32 + dp + 1] * egl);
            for (int i = 0; i < 64; i++) {
                float kb = skb[i * 128 + dk];
                fma2(a, pack2(kb, kb), *(u64*)&svn[i * 32 + dp]);
            }
            float2 p = unpack2(a);
            st[dk * 32 + dp] = p.x;
            st[dk * 32 + dp + 1] = p.y;
        }
        __syncthreads();
    }
}

// ---------------- RMSNorm + z-gate epilogue -> fp16 hi/lo ----------------
__global__ void rms_kernel(const float* __restrict__ norm_w) {
    int b = blockIdx.x;
    int s = b >> 5, h = b & 31, t = threadIdx.x;   // 128 threads
    float v = d_o[((size_t)h * SEQ + s) * 128 + t];
    float ss = v * v;
#pragma unroll
    for (int o = 16; o > 0; o >>= 1) ss += __shfl_xor_sync(~0u, ss, o);
    __shared__ float ws[4];
    if ((t & 31) == 0) ws[t >> 5] = ss;
    __syncthreads();
    ss = (ws[0] + ws[1]) + (ws[2] + ws[3]);
    float r = rsqrtf(ss * (1.f / 128.f) + 1e-6f);
    float z = d_z[(size_t)s * VALD + h * 128 + t];
    float sz = z / (1.f + expf(-z));
    float val = v * r * norm_w[t] * sz;
    size_t idx = (size_t)s * VALD + h * 128 + t;
    __half hh = __float2half_rn(val);
    g_yh[idx] = hh;
    g_yl[idx] = __float2half_rn(val - __half2float(hh));
}

// ---------------- launch ---------------------------------------------------
extern "C" void kernel_launch(void* const* d_in, const int* in_sizes, int n_in,
                              void* d_out, int out_size) {
    const float* x       = (const float*)d_in[0];
    const float* W_qkv   = (const float*)d_in[1];
    const float* W_z     = (const float*)d_in[2];
    const float* W_a     = (const float*)d_in[3];
    const float* W_b     = (const float*)d_in[4];
    const float* conv_w  = (const float*)d_in[5];
    const float* dt_bias = (const float*)d_in[6];
    const float* A_log   = (const float*)d_in[7];
    const float* norm_w  = (const float*)d_in[8];
    const float* W_out   = (const float*)d_in[9];
    float* out = (float*)d_out;

    void *p_mixed, *p_z;
    cudaGetSymbolAddress(&p_mixed, d_mixed);
    cudaGetSymbolAddress(&p_z, d_z);
    void *p_xh, *p_xl, *p_qkh, *p_qkl, *p_wzh, *p_wzl, *p_woh, *p_wol, *p_yh, *p_yl;
    cudaGetSymbolAddress(&p_xh, g_xh);   cudaGetSymbolAddress(&p_xl, g_xl);
    cudaGetSymbolAddress(&p_qkh, g_qkh); cudaGetSymbolAddress(&p_qkl, g_qkl);
    cudaGetSymbolAddress(&p_wzh, g_wzh); cudaGetSymbolAddress(&p_wzl, g_wzl);
    cudaGetSymbolAddress(&p_woh, g_woh); cudaGetSymbolAddress(&p_wol, g_wol);
    cudaGetSymbolAddress(&p_yh, g_yh);   cudaGetSymbolAddress(&p_yl, g_yl);

    const int INTRA_SMEM = 33216 * 4;
    const int SCAN_SMEM  = 36864 * 4;
    cudaFuncSetAttribute(intra_kernel, cudaFuncAttributeMaxDynamicSharedMemorySize, INTRA_SMEM);
    cudaFuncSetAttribute(scan_kernel,  cudaFuncAttributeMaxDynamicSharedMemorySize, SCAN_SMEM);
    cudaFuncSetAttribute(tc_gemm<2>,   cudaFuncAttributeMaxDynamicSharedMemorySize, GEMM_SMEM2);
    cudaFuncSetAttribute(tc_gemm<3>,   cudaFuncAttributeMaxDynamicSharedMemorySize, GEMM_SMEM3);

    // launches 0-2: converts; launch index 3 = tc_gemm(qkv) -> profiled slot
    cvt_split<<<(SEQ * HIDN / 4 + 255) / 256, 256>>>(x, (__half*)p_xh, (__half*)p_xl, SEQ * HIDN / 4);
    cvt_split<<<(CDIM * HIDN / 4 + 255) / 256, 256>>>(W_qkv, (__half*)p_qkh, (__half*)p_qkl, CDIM * HIDN / 4);
    cvt_split<<<(VALD * HIDN / 4 + 255) / 256, 256>>>(W_z, (__half*)p_wzh, (__half*)p_wzl, VALD * HIDN / 4);

    tc_gemm<2><<<dim3(CDIM / 128, SEQ / 128), 256, GEMM_SMEM2>>>(
        (const __half*)p_xh, (const __half*)p_xl,
        (const __half*)p_qkh, (const __half*)p_qkl,
        (float*)p_mixed, CDIM, HIDN);
    tc_gemm<2><<<dim3(VALD / 128, SEQ / 128), 256, GEMM_SMEM2>>>(
        (const __half*)p_xh, (const __half*)p_xl,
        (const __half*)p_wzh, (const __half*)p_wzl,
        (float*)p_z, VALD, HIDN);

    cvt_split<<<(HIDN * VALD / 4 + 255) / 256, 256>>>(W_out, (__half*)p_woh, (__half*)p_wol, HIDN * VALD / 4);
    ab_gemm<<<SEQ / 64, 256>>>(x, W_a, W_b);

    // conv + silu + split
    conv_silu<<<dim3(CDIM / 256, 8), 256>>>(conv_w);

    // l2norm q (scaled) and k
    l2norm_kernel<<<dim3(SEQ * NKH, 2), 128>>>();

    // gates
    gate_kernel<<<dim3(NVH, NCH), 64>>>(dt_bias, A_log);

    // intra-chunk precompute
    intra_kernel<<<dim3(NCH, NVH), 256, INTRA_SMEM>>>();

    // sequential inter-chunk scan (32 heads x 4 DV-slices)
    scan_kernel<<<NVH * 4, 512, SCAN_SMEM>>>();

    // rmsnorm + gate epilogue -> fp16 hi/lo
    rms_kernel<<<SEQ * NVH, 128>>>(norm_w);

    // output projection (3-term fp16: error lands directly in output)
    tc_gemm<3><<<dim3(HIDN / 128, SEQ / 128), 256, GEMM_SMEM3>>>(
        (const __half*)p_yh, (const __half*)p_yl,
        (const __half*)p_woh, (const __half*)p_wol,
        out, HIDN, VALD);
}

// round 12
// speedup vs baseline: 2.3455x; 1.2166x over previous
#include <cuda_runtime.h>
#include <cuda_fp16.h>
#include <math.h>

// ---------------- problem constants ----------------
#define SEQ   2048
#define HIDN  2048
#define NKH   16
#define NVH   32
#define DKD   128
#define DVD   128
#define CDIM  8192
#define VALD  4096
#define NCH   32      // chunks
#define CHK   64      // chunk size

typedef unsigned long long u64;
typedef unsigned int u32;

// single dynamic smem symbol shared by all kernels
extern __shared__ __align__(16) char dyn_smem[];

// ---------------- scratch (device globals; no cudaMalloc allowed) -------
__device__ float d_mixed[SEQ * CDIM];
__device__ float d_z   [SEQ * VALD];
__device__ float d_ab  [SEQ * 64];
__device__ float d_q   [SEQ * 2048];
__device__ float d_k   [SEQ * 2048];
__device__ float d_v   [SEQ * VALD];
__device__ float d_g   [NVH * SEQ];
__device__ float d_beta[NVH * SEQ];
__device__ float d_egl [NVH * NCH];
__device__ float d_u   [NVH * SEQ * DVD];
__device__ float d_kcd [NVH * SEQ * DKD];
__device__ float d_qg  [NVH * SEQ * DKD];
__device__ float d_kbar[NVH * SEQ * DKD];
__device__ float d_sc  [NVH * NCH * CHK * CHK];
__device__ float d_o   [NVH * SEQ * DVD];

// fp16 split buffers for tensor-core GEMMs
__device__ __half g_xh  [SEQ * HIDN],  g_xl  [SEQ * HIDN];
__device__ __half g_qkh [CDIM * HIDN], g_qkl [CDIM * HIDN];
__device__ __half g_wzh [VALD * HIDN], g_wzl [VALD * HIDN];
__device__ __half g_woh [HIDN * VALD], g_wol [HIDN * VALD];
__device__ __half g_yh  [SEQ * VALD],  g_yl  [SEQ * VALD];

// ---------------- packed f32x2 helpers ----------------
__device__ __forceinline__ u64 pack2(float lo, float hi) {
    u64 r; asm("mov.b64 %0,{%1,%2};" : "=l"(r) : "f"(lo), "f"(hi)); return r;
}
__device__ __forceinline__ float2 unpack2(u64 v) {
    float2 r; asm("mov.b64 {%0,%1},%2;" : "=f"(r.x), "=f"(r.y) : "l"(v)); return r;
}
__device__ __forceinline__ void fma2(u64& d, u64 a, u64 b) {
    asm("fma.rn.f32x2 %0,%1,%2,%0;" : "+l"(d) : "l"(a), "l"(b));
}

// ---------------- fp32 -> fp16 hi/lo split ----------------
__global__ void __launch_bounds__(256) cvt_split(const float* __restrict__ s,
                                                 __half* __restrict__ h,
                                                 __half* __restrict__ l,
                                                 int n4) {
    int i = blockIdx.x * 256 + threadIdx.x;
    if (i >= n4) return;
    float4 v = ((const float4*)s)[i];
    __half h0 = __float2half_rn(v.x);
    __half h1 = __float2half_rn(v.y);
    __half h2 = __float2half_rn(v.z);
    __half h3 = __float2half_rn(v.w);
    __half2* hp = (__half2*)h;
    __half2* lp = (__half2*)l;
    hp[2 * i]     = __half2(h0, h1);
    hp[2 * i + 1] = __half2(h2, h3);
    lp[2 * i]     = __half2(__float2half_rn(v.x - __half2float(h0)),
                            __float2half_rn(v.y - __half2float(h1)));
    lp[2 * i + 1] = __half2(__float2half_rn(v.z - __half2float(h2)),
                            __float2half_rn(v.w - __half2float(h3)));
}

// ---------------- warp-MMA fp16 GEMM: C[M,N] = A[M,K] @ B[N,K]^T --------
// TERMS=2: C = Ah*Bh + Al*Bh (B truncated to fp16, 3 smem tiles)
#define BKC   32
#define SROW  40
#define TILE_W (128 * SROW)
#define TILE_B (TILE_W * 2)                // 10240 bytes per tile
#define GEMM_SMEM2 (2 * 3 * TILE_B)        // 61440

__device__ __forceinline__ void mma_f16(float* c, const u32* a, const u32* b) {
    asm volatile(
        "mma.sync.aligned.m16n8k16.row.col.f32.f16.f16.f32 "
        "{%0,%1,%2,%3}, {%4,%5,%6,%7}, {%8,%9}, {%0,%1,%2,%3};"
        : "+f"(c[0]), "+f"(c[1]), "+f"(c[2]), "+f"(c[3])
        : "r"(a[0]), "r"(a[1]), "r"(a[2]), "r"(a[3]), "r"(b[0]), "r"(b[1]));
}

__device__ __forceinline__ void ldsm_x4(u32& r0, u32& r1, u32& r2, u32& r3, u32 addr) {
    asm volatile("ldmatrix.sync.aligned.m8n8.x4.shared.b16 {%0,%1,%2,%3}, [%4];"
                 : "=r"(r0), "=r"(r1), "=r"(r2), "=r"(r3) : "r"(addr));
}

__global__ void __launch_bounds__(256, 2)
tc_gemm(const __half* __restrict__ Ah, const __half* __restrict__ Al,
        const __half* __restrict__ Bh,
        float* __restrict__ C, int N, int K) {
    constexpr u32 STG = 3 * TILE_B;

    __half* sm = (__half*)dyn_smem;

    const int t = threadIdx.x, lane = t & 31, wid = t >> 5;
    const int wm = wid & 3, wn = wid >> 2;
    const int bx = blockIdx.x, by = blockIdx.y;
    const int NCHUNK = K / BKC;

    u32 smem_base;
    asm("{ .reg .u64 tt; cvta.to.shared.u64 tt, %1; cvt.u32.u64 %0, tt; }"
        : "=r"(smem_base) : "l"(sm));

    const __half* srcs[3] = {
        Ah + (size_t)by * 128 * K, Al + (size_t)by * 128 * K,
        Bh + (size_t)bx * 128 * K};

    auto load_chunk = [&](int n, int s) {
        u32 sb = smem_base + (u32)s * STG;
#pragma unroll
        for (int tile = 0; tile < 3; tile++) {
#pragma unroll
            for (int j = 0; j < 2; j++) {
                int f = t + 256 * j;
                int row = f >> 2, c = f & 3;
                const __half* g = srcs[tile] + (size_t)row * K + n * BKC + c * 8;
                u32 d = sb + (u32)tile * TILE_B + (u32)(row * SROW + c * 8) * 2;
                asm volatile("cp.async.cg.shared.global [%0], [%1], 16;"
                             :: "r"(d), "l"(g));
            }
        }
        asm volatile("cp.async.commit_group;" ::: "memory");
    };

    float acc[2][8][4];
#pragma unroll
    for (int mt = 0; mt < 2; mt++)
#pragma unroll
        for (int nt = 0; nt < 8; nt++)
#pragma unroll
            for (int e = 0; e < 4; e++) acc[mt][nt][e] = 0.f;

    const int aRow = wm * 32 + (lane & 7) + ((lane >> 3) & 1) * 8;
    const u32 aOff = (u32)((aRow * SROW + (lane >> 4) * 8) * 2);
    const int bRow = wn * 64 + (lane & 7) + ((lane >> 4) & 1) * 8;
    const u32 bOff = (u32)((bRow * SROW + ((lane >> 3) & 1) * 8) * 2);

    load_chunk(0, 0);

    for (int n = 0; n < NCHUNK; n++) {
        int s = n & 1;
        asm volatile("cp.async.wait_group 0;" ::: "memory");
        __syncthreads();
        if (n + 1 < NCHUNK) load_chunk(n + 1, 1 - s);

        u32 sb = smem_base + (u32)s * STG;

#pragma unroll
        for (int k16 = 0; k16 < 2; k16++) {
            const u32 kb = (u32)(k16 * 16 * 2);
            u32 bh[8][2];
#pragma unroll
            for (int p = 0; p < 4; p++) {
                u32 base = sb + 2 * TILE_B + bOff + (u32)(p * 16 * SROW) * 2 + kb;
                ldsm_x4(bh[2 * p][0], bh[2 * p][1], bh[2 * p + 1][0], bh[2 * p + 1][1], base);
            }
#pragma unroll
            for (int mt = 0; mt < 2; mt++) {
                u32 ah[4], al[4];
                u32 base = sb + aOff + (u32)(mt * 16 * SROW) * 2 + kb;
                ldsm_x4(ah[0], ah[1], ah[2], ah[3], base);
                ldsm_x4(al[0], al[1], al[2], al[3], base + TILE_B);
#pragma unroll
                for (int nt = 0; nt < 8; nt++) {
                    mma_f16(acc[mt][nt], ah, bh[nt]);
                    mma_f16(acc[mt][nt], al, bh[nt]);
                }
            }
        }
    }

    const int gid = lane >> 2, tig = lane & 3;
#pragma unroll
    for (int mt = 0; mt < 2; mt++) {
        int rbase = by * 128 + wm * 32 + mt * 16;
#pragma unroll
        for (int nt = 0; nt < 8; nt++) {
            int cbase = bx * 128 + wn * 64 + nt * 8 + tig * 2;
            float* p0 = C + (size_t)(rbase + gid) * N + cbase;
            float* p1 = C + (size_t)(rbase + gid + 8) * N + cbase;
            p0[0] = acc[mt][nt][0]; p0[1] = acc[mt][nt][1];
            p1[0] = acc[mt][nt][2]; p1[1] = acc[mt][nt][3];
        }
    }
}

// ---------------- a/b projection ----------------------------------------
__global__ void __launch_bounds__(256) ab_gemm(const float* __restrict__ x,
                                               const float* __restrict__ Wa,
                                               const float* __restrict__ Wb) {
    __shared__ float Xs[32][64];
    __shared__ float Ws[32][64];
    const int t = threadIdx.x;
    const int s0 = blockIdx.x * 64;
    const int tx = t & 15, ty = t >> 4;
    float acc[4][4];
#pragma unroll
    for (int i = 0; i < 4; i++)
#pragma unroll
        for (int j = 0; j < 4; j++) acc[i][j] = 0.f;

    for (int k0 = 0; k0 < HIDN; k0 += 32) {
        for (int e = t; e < 2048; e += 256) {
            int r = e >> 5, c = e & 31;
            Xs[c][r] = x[(size_t)(s0 + r) * HIDN + k0 + c];
            const float* Wrow = (r < 32) ? (Wa + (size_t)r * HIDN) : (Wb + (size_t)(r - 32) * HIDN);
            Ws[c][r] = Wrow[k0 + c];
        }
        __syncthreads();
#pragma unroll
        for (int kk = 0; kk < 32; kk++) {
            float a[4], b[4];
#pragma unroll
            for (int i = 0; i < 4; i++) { a[i] = Xs[kk][ty * 4 + i]; b[i] = Ws[kk][tx * 4 + i]; }
#pragma unroll
            for (int i = 0; i < 4; i++)
#pragma unroll
                for (int j = 0; j < 4; j++) acc[i][j] += a[i] * b[j];
        }
        __syncthreads();
    }
#pragma unroll
    for (int i = 0; i < 4; i++)
#pragma unroll
        for (int j = 0; j < 4; j++)
            d_ab[(size_t)(s0 + ty * 4 + i) * 64 + tx * 4 + j] = acc[i][j];
}

// ---------------- causal conv(K=4) + SiLU, MLP-8 version ----------------
__global__ void __launch_bounds__(256) conv_silu(const float* __restrict__ cw) {
    int c  = blockIdx.x * 256 + threadIdx.x;
    int s0 = blockIdx.y * 8;
    float w0 = cw[c * 4], w1 = cw[c * 4 + 1], w2 = cw[c * 4 + 2], w3 = cw[c * 4 + 3];
    float xx[11];
#pragma unroll
    for (int j = 0; j < 11; j++) {
        int s = s0 - 3 + j;
        xx[j] = (s >= 0) ? d_mixed[(size_t)s * CDIM + c] : 0.f;
    }
#pragma unroll
    for (int i = 0; i < 8; i++) {
        float acc = w0 * xx[i] + w1 * xx[i + 1] + w2 * xx[i + 2] + w3 * xx[i + 3];
        float r = acc / (1.f + expf(-acc));
        int s = s0 + i;
        if (c < 2048)      d_q[(size_t)s * 2048 + c] = r;
        else if (c < 4096) d_k[(size_t)s * 2048 + (c - 2048)] = r;
        else               d_v[(size_t)s * 4096 + (c - 4096)] = r;
    }
}

// ---------------- l2norm on q (with DK^-0.5) and k -----------------------
__global__ void l2norm_kernel() {
    int b = blockIdx.x, t = threadIdx.x;
    float* buf = (blockIdx.y == 0) ? d_q : d_k;
    size_t idx = (size_t)b * 128 + t;
    float v = buf[idx];
    float ss = v * v;
#pragma unroll
    for (int o = 16; o > 0; o >>= 1) ss += __shfl_xor_sync(~0u, ss, o);
    __shared__ float ws[4];
    if ((t & 31) == 0) ws[t >> 5] = ss;
    __syncthreads();
    ss = (ws[0] + ws[1]) + (ws[2] + ws[3]);
    float sc = rsqrtf(ss + 1e-6f);
    if (blockIdx.y == 0) sc *= 0.08838834764831845f;
    buf[idx] = v * sc;
}

// ---------------- gate ----------------------------------------------------
__global__ void gate_kernel(const float* __restrict__ dt_bias,
                            const float* __restrict__ A_log) {
    int h = blockIdx.x, n = blockIdx.y, i = threadIdx.x;
    int s = n * CHK + i;
    float a = d_ab[(size_t)s * 64 + h];
    float b = d_ab[(size_t)s * 64 + 32 + h];
    float xx = a + dt_bias[h];
    float sp = fmaxf(xx, 0.f) + log1pf(expf(-fabsf(xx)));
    float gv = -expf(A_log[h]) * sp;
    float beta = 1.f / (1.f + expf(-b));
    int lane = i & 31;
#pragma unroll
    for (int o = 1; o < 32; o <<= 1) {
        float nv = __shfl_up_sync(~0u, gv, o);
        if (lane >= o) gv += nv;
    }
    __shared__ float carry;
    if (i == 31) carry = gv;
    __syncthreads();
    if (i >= 32) gv += carry;
    d_g[(size_t)h * SEQ + s] = gv;
    d_beta[(size_t)h * SEQ + s] = beta;
    if (i == 63) d_egl[h * NCH + n] = expf(gv);
}

// ---------------- intra-chunk (restructured: 84KB smem -> 2 blocks/SM) ---
__global__ void __launch_bounds__(256, 2) intra_kernel() {
    float* sm  = (float*)dyn_smem;
    float* sq  = sm;              // 64*128 (q, later v*beta)
    float* sk  = sm + 8192;       // 64*128 (k, later k*scv)
    float* sA  = sm + 16384;      // 64*64
    float* sg  = sm + 20480;      // 64
    float* sb  = sm + 20544;      // 64
    float* scv = sm + 20608;      // 64
    float* se  = sm + 20672;      // 64  exp(g)
    float* ser = sm + 20736;      // 64  exp(gl-g)
    float* sP  = sm + 20800;      // 256

    const int n = blockIdx.x, h = blockIdx.y, kvh = h >> 1, t = threadIdx.x;
    const int sbase = n * CHK;

    for (int e = t; e < 2048; e += 256) {
        int i = e >> 5, d = (e & 31) << 2;
        int s = sbase + i;
        *(float4*)&sq[i * 128 + d] = *(const float4*)&d_q[((size_t)s * NKH + kvh) * 128 + d];
        *(float4*)&sk[i * 128 + d] = *(const float4*)&d_k[((size_t)s * NKH + kvh) * 128 + d];
    }
    if (t < 64) {
        sg[t] = d_g[(size_t)h * SEQ + sbase + t];
        sb[t] = d_beta[(size_t)h * SEQ + sbase + t];
    }
    __syncthreads();
    if (t < 64) {
        scv[t] = sb[t] * expf(sg[t]);
        se[t]  = expf(sg[t]);
        ser[t] = expf(sg[63] - sg[t]);
    }
    __syncthreads();

    // ---- elementwise qg = q*e^g, kbar = k*e^(gl-g) ----
    for (int e = t; e < 2048; e += 256) {
        int i = e >> 5, d = (e & 31) << 2;
        size_t rb = ((size_t)h * SEQ + sbase + i) * 128 + d;
        float eg = se[i], er = ser[i];
        float4 qv = *(const float4*)&sq[i * 128 + d];
        float4 kv = *(const float4*)&sk[i * 128 + d];
        *(float4*)&d_qg[rb]   = make_float4(qv.x * eg, qv.y * eg, qv.z * eg, qv.w * eg);
        *(float4*)&d_kbar[rb] = make_float4(kv.x * er, kv.y * er, kv.z * er, kv.w * er);
    }

    const int i0 = (t >> 4) << 2, j0 = (t & 15) << 2;

    // ---- fused: A (k.k) + scores (q.k) in one pass ----
    {
        float accA[4][4], accS[4][4];
#pragma unroll
        for (int ii = 0; ii < 4; ii++)
#pragma unroll
            for (int jj = 0; jj < 4; jj++) { accA[ii][jj] = 0.f; accS[ii][jj] = 0.f; }
        for (int kk = 0; kk < 128; kk += 4) {
            float4 ak[4], aq[4], bk[4];
#pragma unroll
            for (int ii = 0; ii < 4; ii++) {
                ak[ii] = *(const float4*)&sk[(i0 + ii) * 128 + kk];
                aq[ii] = *(const float4*)&sq[(i0 + ii) * 128 + kk];
                bk[ii] = *(const float4*)&sk[(j0 + ii) * 128 + kk];
            }
#pragma unroll
            for (int ii = 0; ii < 4; ii++)
#pragma unroll
                for (int jj = 0; jj < 4; jj++) {
                    accA[ii][jj] += ak[ii].x * bk[jj].x + ak[ii].y * bk[jj].y +
                                    ak[ii].z * bk[jj].z + ak[ii].w * bk[jj].w;
                    accS[ii][jj] += aq[ii].x * bk[jj].x + aq[ii].y * bk[jj].y +
                                    aq[ii].z * bk[jj].z + aq[ii].w * bk[jj].w;
                }
        }
        const size_t scb = ((size_t)h * NCH + n) * 4096;
#pragma unroll
        for (int ii = 0; ii < 4; ii++)
#pragma unroll
            for (int jj = 0; jj < 4; jj++) {
                int i = i0 + ii, j = j0 + jj;
                float dec = expf(sg[i] - sg[j]);
                sA[i * 64 + j]      = (i > j)  ? -sb[i] * accA[ii][jj] * dec : 0.f;
                d_sc[scb + i * 64 + j] = (i >= j) ? accS[ii][jj] * dec : 0.f;
            }
    }
    __syncthreads();

    // ---- UT transform (forward substitution) ----
    {
        int j = t & 63, pt = t >> 6;
        for (int i = 1; i < 64; i++) {
            float p = 0.f;
            if (j < i)
                for (int kk = j + 1 + pt; kk < i; kk += 4)
                    p += sA[i * 64 + kk] * sA[kk * 64 + j];
            sP[t] = p;
            __syncthreads();
            if (t < i) sA[i * 64 + t] += sP[t] + sP[64 + t] + sP[128 + t] + sP[192 + t];
            __syncthreads();
        }
    }

    // ---- overwrite sq with v*beta ----
    for (int e = t; e < 2048; e += 256) {
        int i = e >> 5, d = (e & 31) << 2;
        float4 vv = *(const float4*)&d_v[((size_t)(sbase + i) * NVH + h) * 128 + d];
        float b = sb[i];
        *(float4*)&sq[i * 128 + d] = make_float4(vv.x * b, vv.y * b, vv.z * b, vv.w * b);
    }
    __syncthreads();

    const int dv = t & 127, half = t >> 7;

    // ---- u = (I + A) @ vb ----
    for (int ii = 0; ii < 32; ii++) {
        int i = half * 32 + ii;
        float a = sq[i * 128 + dv];
        for (int kk = 0; kk < i; kk++) a += sA[i * 64 + kk] * sq[kk * 128 + dv];
        d_u[((size_t)h * SEQ + sbase + i) * 128 + dv] = a;
    }
    __syncthreads();

    // ---- scale sk in place: k * beta * e^g ----
    for (int e = t; e < 8192; e += 256) sk[e] *= scv[e >> 7];
    __syncthreads();

    // ---- kcd = (I+A) @ (k*beta*e^g) ----
    for (int ii = 0; ii < 32; ii++) {
        int i = half * 32 + ii;
        float a = sk[i * 128 + dv];
        for (int kk = 0; kk < i; kk++) a += sA[i * 64 + kk] * sk[kk * 128 + dv];
        d_kcd[((size_t)h * SEQ + sbase + i) * 128 + dv] = a;
    }
}

// ---------------- sequential inter-chunk scan ----------------------------
__global__ void __launch_bounds__(512) scan_kernel() {
    float* sm = (float*)dyn_smem;
    float* st  = sm;           // 128*32 state slice
    float* skc = sm + 4096;    // 64*128 kcd (pre-negated)
    float* sqg = sm + 12288;   // 64*128 qg
    float* skb = sm + 20480;   // 64*128 kbar
    float* ssc = sm + 28672;   // 64*64 scores
    float* svn = sm + 32768;   // 64*32 v_new
    float* su  = sm + 34816;   // 64*32 u slice

    const int h = blockIdx.x >> 2, sl = blockIdx.x & 3, t = threadIdx.x;
    const int dv0 = sl * 32;

    for (int e = t; e < 4096; e += 512) st[e] = 0.f;

    for (int n = 0; n < NCH; n++) {
        const size_t rb = ((size_t)h * SEQ + n * CHK) * 128;
        for (int e = t; e < 2048; e += 512) {
            float4 kc = ((const float4*)(d_kcd + rb))[e];
            ((float4*)skc)[e] = make_float4(-kc.x, -kc.y, -kc.z, -kc.w);
            ((float4*)sqg)[e] = ((const float4*)(d_qg + rb))[e];
            ((float4*)skb)[e] = ((const float4*)(d_kbar + rb))[e];
        }
        const size_t scb = ((size_t)h * NCH + n) * 4096;
        for (int e = t; e < 1024; e += 512)
            ((float4*)ssc)[e] = ((const float4*)(d_sc + scb))[e];
        {
            int e = t;
            int i = e >> 3, q4 = e & 7;
            ((float4*)su)[e] = *(const float4*)&d_u[rb + (size_t)i * 128 + dv0 + q4 * 4];
        }
        __syncthreads();

        const float egl = d_egl[h * NCH + n];

        // v_new = u - kcd @ state  (skc pre-negated)
#pragma unroll
        for (int r = 0; r < 2; r++) {
            int idx = t + 512 * r;
            int i = idx >> 4, dp = (idx & 15) << 1;
            u64 a = *(u64*)&su[i * 32 + dp];
            for (int dk0 = 0; dk0 < 128; dk0 += 4) {
                float4 kc = *(const float4*)&skc[i * 128 + dk0];
                fma2(a, pack2(kc.x, kc.x), *(u64*)&st[(dk0    ) * 32 + dp]);
                fma2(a, pack2(kc.y, kc.y), *(u64*)&st[(dk0 + 1) * 32 + dp]);
                fma2(a, pack2(kc.z, kc.z), *(u64*)&st[(dk0 + 2) * 32 + dp]);
                fma2(a, pack2(kc.w, kc.w), *(u64*)&st[(dk0 + 3) * 32 + dp]);
            }
            *(u64*)&svn[i * 32 + dp] = a;
        }
        __syncthreads();

        // o = qg @ state + scores @ v_new
#pragma unroll
        for (int r = 0; r < 2; r++) {
            int idx = t + 512 * r;
            int i = idx >> 4, dp = (idx & 15) << 1;
            u64 a = 0ull;
            for (int dk0 = 0; dk0 < 128; dk0 += 4) {
                float4 qv = *(const float4*)&sqg[i * 128 + dk0];
                fma2(a, pack2(qv.x, qv.x), *(u64*)&st[(dk0    ) * 32 + dp]);
                fma2(a, pack2(qv.y, qv.y), *(u64*)&st[(dk0 + 1) * 32 + dp]);
                fma2(a, pack2(qv.z, qv.z), *(u64*)&st[(dk0 + 2) * 32 + dp]);
                fma2(a, pack2(qv.w, qv.w), *(u64*)&st[(dk0 + 3) * 32 + dp]);
            }
            int j = 0;
            for (; j + 4 <= i + 1; j += 4) {
                float4 s4 = *(const float4*)&ssc[i * 64 + j];
                fma2(a, pack2(s4.x, s4.x), *(u64*)&svn[(j    ) * 32 + dp]);
                fma2(a, pack2(s4.y, s4.y), *(u64*)&svn[(j + 1) * 32 + dp]);
                fma2(a, pack2(s4.z, s4.z), *(u64*)&svn[(j + 2) * 32 + dp]);
                fma2(a, pack2(s4.w, s4.w), *(u64*)&svn[(j + 3) * 32 + dp]);
            }
            for (; j <= i; j++) {
                float s_ = ssc[i * 64 + j];
                fma2(a, pack2(s_, s_), *(u64*)&svn[j * 32 + dp]);
            }
            float2 p = unpack2(a);
            *(float2*)&d_o[rb + (size_t)i * 128 + dv0 + dp] = p;
        }
        __syncthreads();

        // state = state*egl + kbar^T @ v_new   (2 dk per thread)
#pragma unroll
        for (int r = 0; r < 2; r++) {
            int idx = t + 512 * r;                  // 0..1023
            int dk0 = (idx >> 4) << 1;              // 0,2,..126
            int dp  = (idx & 15) << 1;
            u64 a0 = pack2(st[dk0 * 32 + dp] * egl,       st[dk0 * 32 + dp + 1] * egl);
            u64 a1 = pack2(st[(dk0 + 1) * 32 + dp] * egl, st[(dk0 + 1) * 32 + dp + 1] * egl);
            for (int i = 0; i < 64; i++) {
                u64 vn = *(u64*)&svn[i * 32 + dp];
                float2 kb = *(const float2*)&skb[i * 128 + dk0];
                fma2(a0, pack2(kb.x, kb.x), vn);
                fma2(a1, pack2(kb.y, kb.y), vn);
            }
            float2 p0 = unpack2(a0), p1 = unpack2(a1);
            st[dk0 * 32 + dp] = p0.x;       st[dk0 * 32 + dp + 1] = p0.y;
            st[(dk0 + 1) * 32 + dp] = p1.x; st[(dk0 + 1) * 32 + dp + 1] = p1.y;
        }
        __syncthreads();
    }
}

// ---------------- RMSNorm + z-gate epilogue -> fp16 hi/lo ----------------
__global__ void rms_kernel(const float* __restrict__ norm_w) {
    int b = blockIdx.x;
    int s = b >> 5, h = b & 31, t = threadIdx.x;
    float v = d_o[((size_t)h * SEQ + s) * 128 + t];
    float ss = v * v;
#pragma unroll
    for (int o = 16; o > 0; o >>= 1) ss += __shfl_xor_sync(~0u, ss, o);
    __shared__ float ws[4];
    if ((t & 31) == 0) ws[t >> 5] = ss;
    __syncthreads();
    ss = (ws[0] + ws[1]) + (ws[2] + ws[3]);
    float r = rsqrtf(ss * (1.f / 128.f) + 1e-6f);
    float z = d_z[(size_t)s * VALD + h * 128 + t];
    float sz = z / (1.f + expf(-z));
    float val = v * r * norm_w[t] * sz;
    size_t idx = (size_t)s * VALD + h * 128 + t;
    __half hh = __float2half_rn(val);
    g_yh[idx] = hh;
    g_yl[idx] = __float2half_rn(val - __half2float(hh));
}

// ---------------- launch ---------------------------------------------------
extern "C" void kernel_launch(void* const* d_in, const int* in_sizes, int n_in,
                              void* d_out, int out_size) {
    const float* x       = (const float*)d_in[0];
    const float* W_qkv   = (const float*)d_in[1];
    const float* W_z     = (const float*)d_in[2];
    const float* W_a     = (const float*)d_in[3];
    const float* W_b     = (const float*)d_in[4];
    const float* conv_w  = (const float*)d_in[5];
    const float* dt_bias = (const float*)d_in[6];
    const float* A_log   = (const float*)d_in[7];
    const float* norm_w  = (const float*)d_in[8];
    const float* W_out   = (const float*)d_in[9];
    float* out = (float*)d_out;

    void *p_mixed, *p_z;
    cudaGetSymbolAddress(&p_mixed, d_mixed);
    cudaGetSymbolAddress(&p_z, d_z);
    void *p_xh, *p_xl, *p_qkh, *p_qkl, *p_wzh, *p_wzl, *p_woh, *p_wol, *p_yh, *p_yl;
    cudaGetSymbolAddress(&p_xh, g_xh);   cudaGetSymbolAddress(&p_xl, g_xl);
    cudaGetSymbolAddress(&p_qkh, g_qkh); cudaGetSymbolAddress(&p_qkl, g_qkl);
    cudaGetSymbolAddress(&p_wzh, g_wzh); cudaGetSymbolAddress(&p_wzl, g_wzl);
    cudaGetSymbolAddress(&p_woh, g_woh); cudaGetSymbolAddress(&p_wol, g_wol);
    cudaGetSymbolAddress(&p_yh, g_yh);   cudaGetSymbolAddress(&p_yl, g_yl);

    const int INTRA_SMEM = 21056 * 4;     // 84224 bytes -> 2 blocks/SM
    const int SCAN_SMEM  = 36864 * 4;
    cudaFuncSetAttribute(intra_kernel, cudaFuncAttributeMaxDynamicSharedMemorySize, INTRA_SMEM);
    cudaFuncSetAttribute(scan_kernel,  cudaFuncAttributeMaxDynamicSharedMemorySize, SCAN_SMEM);
    cudaFuncSetAttribute(tc_gemm,      cudaFuncAttributeMaxDynamicSharedMemorySize, GEMM_SMEM2);

    // launches 0-2: converts; launch index 3 = tc_gemm(qkv) -> profiled slot
    cvt_split<<<(SEQ * HIDN / 4 + 255) / 256, 256>>>(x, (__half*)p_xh, (__half*)p_xl, SEQ * HIDN / 4);
    cvt_split<<<(CDIM * HIDN / 4 + 255) / 256, 256>>>(W_qkv, (__half*)p_qkh, (__half*)p_qkl, CDIM * HIDN / 4);
    cvt_split<<<(VALD * HIDN / 4 + 255) / 256, 256>>>(W_z, (__half*)p_wzh, (__half*)p_wzl, VALD * HIDN / 4);

    tc_gemm<<<dim3(CDIM / 128, SEQ / 128), 256, GEMM_SMEM2>>>(
        (const __half*)p_xh, (const __half*)p_xl, (const __half*)p_qkh,
        (float*)p_mixed, CDIM, HIDN);
    tc_gemm<<<dim3(VALD / 128, SEQ / 128), 256, GEMM_SMEM2>>>(
        (const __half*)p_xh, (const __half*)p_xl, (const __half*)p_wzh,
        (float*)p_z, VALD, HIDN);

    cvt_split<<<(HIDN * VALD / 4 + 255) / 256, 256>>>(W_out, (__half*)p_woh, (__half*)p_wol, HIDN * VALD / 4);
    ab_gemm<<<SEQ / 64, 256>>>(x, W_a, W_b);

    // conv + silu + split (MLP-8)
    conv_silu<<<dim3(CDIM / 256, SEQ / 8), 256>>>(conv_w);

    // l2norm q (scaled) and k
    l2norm_kernel<<<dim3(SEQ * NKH, 2), 128>>>();

    // gates
    gate_kernel<<<dim3(NVH, NCH), 64>>>(dt_bias, A_log);

    // intra-chunk precompute
    intra_kernel<<<dim3(NCH, NVH), 256, INTRA_SMEM>>>();

    // sequential inter-chunk scan (32 heads x 4 DV-slices)
    scan_kernel<<<NVH * 4, 512, SCAN_SMEM>>>();

    // rmsnorm + gate epilogue -> fp16 hi/lo
    rms_kernel<<<SEQ * NVH, 128>>>(norm_w);

    // output projection (2-term fp16)
    tc_gemm<<<dim3(HIDN / 128, SEQ / 128), 256, GEMM_SMEM2>>>(
        (const __half*)p_yh, (const __half*)p_yl, (const __half*)p_woh,
        out, HIDN, VALD);
}

// round 13
// speedup vs baseline: 2.4960x; 1.0642x over previous
#include <cuda_runtime.h>
#include <cuda_fp16.h>
#include <math.h>

// ---------------- problem constants ----------------
#define SEQ   2048
#define HIDN  2048
#define NKH   16
#define NVH   32
#define DKD   128
#define DVD   128
#define CDIM  8192
#define VALD  4096
#define NCH   32      // chunks
#define CHK   64      // chunk size

typedef unsigned long long u64;
typedef unsigned int u32;

// single dynamic smem symbol shared by all kernels
extern __shared__ __align__(16) char dyn_smem[];

// ---------------- scratch (device globals; no cudaMalloc allowed) -------
__device__ float d_mixed[SEQ * CDIM];
__device__ float d_z   [SEQ * VALD];
__device__ float d_ab  [SEQ * 64];
__device__ float d_q   [SEQ * 2048];
__device__ float d_k   [SEQ * 2048];
__device__ float d_v   [SEQ * VALD];
__device__ float d_g   [NVH * SEQ];
__device__ float d_beta[NVH * SEQ];
__device__ float d_egl [NVH * NCH];
__device__ float d_u   [NVH * SEQ * DVD];
__device__ float d_kcd [NVH * SEQ * DKD];
__device__ float d_qg  [NVH * SEQ * DKD];
__device__ float d_kbar[NVH * SEQ * DKD];
__device__ float d_sc  [NVH * NCH * CHK * CHK];
__device__ float d_o   [NVH * SEQ * DVD];

// fp16 split buffers for tensor-core GEMMs
__device__ __half g_xh  [SEQ * HIDN],  g_xl  [SEQ * HIDN];
__device__ __half g_qkh [CDIM * HIDN], g_qkl [CDIM * HIDN];
__device__ __half g_wzh [VALD * HIDN], g_wzl [VALD * HIDN];
__device__ __half g_woh [HIDN * VALD], g_wol [HIDN * VALD];
__device__ __half g_yh  [SEQ * VALD],  g_yl  [SEQ * VALD];

// ---------------- packed f32x2 helpers ----------------
__device__ __forceinline__ u64 pack2(float lo, float hi) {
    u64 r; asm("mov.b64 %0,{%1,%2};" : "=l"(r) : "f"(lo), "f"(hi)); return r;
}
__device__ __forceinline__ float2 unpack2(u64 v) {
    float2 r; asm("mov.b64 {%0,%1},%2;" : "=f"(r.x), "=f"(r.y) : "l"(v)); return r;
}
__device__ __forceinline__ void fma2(u64& d, u64 a, u64 b) {
    asm("fma.rn.f32x2 %0,%1,%2,%0;" : "+l"(d) : "l"(a), "l"(b));
}

// ---------------- fp32 -> fp16 hi/lo split ----------------
__global__ void __launch_bounds__(256) cvt_split(const float* __restrict__ s,
                                                 __half* __restrict__ h,
                                                 __half* __restrict__ l,
                                                 int n4) {
    int i = blockIdx.x * 256 + threadIdx.x;
    if (i >= n4) return;
    float4 v = ((const float4*)s)[i];
    __half h0 = __float2half_rn(v.x);
    __half h1 = __float2half_rn(v.y);
    __half h2 = __float2half_rn(v.z);
    __half h3 = __float2half_rn(v.w);
    __half2* hp = (__half2*)h;
    __half2* lp = (__half2*)l;
    hp[2 * i]     = __half2(h0, h1);
    hp[2 * i + 1] = __half2(h2, h3);
    lp[2 * i]     = __half2(__float2half_rn(v.x - __half2float(h0)),
                            __float2half_rn(v.y - __half2float(h1)));
    lp[2 * i + 1] = __half2(__float2half_rn(v.z - __half2float(h2)),
                            __float2half_rn(v.w - __half2float(h3)));
}

// ---------------- warp-MMA fp16 GEMM: C[M,N] = A[M,K] @ B[N,K]^T --------
// 2-term: C = Ah*Bh + Al*Bh (3 tiles/stage), 3-stage cp.async pipeline.
#define BKC   32
#define SROW  40
#define TILE_W (128 * SROW)
#define TILE_B (TILE_W * 2)                // 10240 bytes per tile
#define STG_B  (3 * TILE_B)                // 30720 per stage
#define GEMM_SMEM (3 * STG_B)              // 92160 (3 stages)

__device__ __forceinline__ void mma_f16(float* c, const u32* a, const u32* b) {
    asm volatile(
        "mma.sync.aligned.m16n8k16.row.col.f32.f16.f16.f32 "
        "{%0,%1,%2,%3}, {%4,%5,%6,%7}, {%8,%9}, {%0,%1,%2,%3};"
        : "+f"(c[0]), "+f"(c[1]), "+f"(c[2]), "+f"(c[3])
        : "r"(a[0]), "r"(a[1]), "r"(a[2]), "r"(a[3]), "r"(b[0]), "r"(b[1]));
}

__device__ __forceinline__ void ldsm_x4(u32& r0, u32& r1, u32& r2, u32& r3, u32 addr) {
    asm volatile("ldmatrix.sync.aligned.m8n8.x4.shared.b16 {%0,%1,%2,%3}, [%4];"
                 : "=r"(r0), "=r"(r1), "=r"(r2), "=r"(r3) : "r"(addr));
}

__global__ void __launch_bounds__(256, 2)
tc_gemm(const __half* __restrict__ Ah, const __half* __restrict__ Al,
        const __half* __restrict__ Bh,
        float* __restrict__ C, int N, int K) {
    __half* sm = (__half*)dyn_smem;

    const int t = threadIdx.x, lane = t & 31, wid = t >> 5;
    const int wm = wid & 3, wn = wid >> 2;
    const int bx = blockIdx.x, by = blockIdx.y;
    const int NCHUNK = K / BKC;

    u32 smem_base;
    asm("{ .reg .u64 tt; cvta.to.shared.u64 tt, %1; cvt.u32.u64 %0, tt; }"
        : "=r"(smem_base) : "l"(sm));

    const __half* srcs[3] = {
        Ah + (size_t)by * 128 * K, Al + (size_t)by * 128 * K,
        Bh + (size_t)bx * 128 * K};

    auto load_chunk = [&](int n, int s) {
        u32 sb = smem_base + (u32)s * STG_B;
#pragma unroll
        for (int tile = 0; tile < 3; tile++) {
#pragma unroll
            for (int j = 0; j < 2; j++) {
                int f = t + 256 * j;
                int row = f >> 2, c = f & 3;
                const __half* g = srcs[tile] + (size_t)row * K + n * BKC + c * 8;
                u32 d = sb + (u32)tile * TILE_B + (u32)(row * SROW + c * 8) * 2;
                asm volatile("cp.async.cg.shared.global [%0], [%1], 16;"
                             :: "r"(d), "l"(g));
            }
        }
        asm volatile("cp.async.commit_group;" ::: "memory");
    };

    float acc[2][8][4];
#pragma unroll
    for (int mt = 0; mt < 2; mt++)
#pragma unroll
        for (int nt = 0; nt < 8; nt++)
#pragma unroll
            for (int e = 0; e < 4; e++) acc[mt][nt][e] = 0.f;

    const int aRow = wm * 32 + (lane & 7) + ((lane >> 3) & 1) * 8;
    const u32 aOff = (u32)((aRow * SROW + (lane >> 4) * 8) * 2);
    const int bRow = wn * 64 + (lane & 7) + ((lane >> 4) & 1) * 8;
    const u32 bOff = (u32)((bRow * SROW + ((lane >> 3) & 1) * 8) * 2);

    load_chunk(0, 0);
    load_chunk(1, 1);

    for (int n = 0; n < NCHUNK; n++) {
        int s = n % 3;
        asm volatile("cp.async.wait_group 1;" ::: "memory");
        __syncthreads();
        if (n + 2 < NCHUNK) load_chunk(n + 2, (n + 2) % 3);

        u32 sb = smem_base + (u32)s * STG_B;

#pragma unroll
        for (int k16 = 0; k16 < 2; k16++) {
            const u32 kb = (u32)(k16 * 16 * 2);
            u32 bh[8][2];
#pragma unroll
            for (int p = 0; p < 4; p++) {
                u32 base = sb + 2 * TILE_B + bOff + (u32)(p * 16 * SROW) * 2 + kb;
                ldsm_x4(bh[2 * p][0], bh[2 * p][1], bh[2 * p + 1][0], bh[2 * p + 1][1], base);
            }
#pragma unroll
            for (int mt = 0; mt < 2; mt++) {
                u32 ah[4], al[4];
                u32 base = sb + aOff + (u32)(mt * 16 * SROW) * 2 + kb;
                ldsm_x4(ah[0], ah[1], ah[2], ah[3], base);
                ldsm_x4(al[0], al[1], al[2], al[3], base + TILE_B);
#pragma unroll
                for (int nt = 0; nt < 8; nt++) {
                    mma_f16(acc[mt][nt], ah, bh[nt]);
                    mma_f16(acc[mt][nt], al, bh[nt]);
                }
            }
        }
    }

    const int gid = lane >> 2, tig = lane & 3;
#pragma unroll
    for (int mt = 0; mt < 2; mt++) {
        int rbase = by * 128 + wm * 32 + mt * 16;
#pragma unroll
        for (int nt = 0; nt < 8; nt++) {
            int cbase = bx * 128 + wn * 64 + nt * 8 + tig * 2;
            float* p0 = C + (size_t)(rbase + gid) * N + cbase;
            float* p1 = C + (size_t)(rbase + gid + 8) * N + cbase;
            p0[0] = acc[mt][nt][0]; p0[1] = acc[mt][nt][1];
            p1[0] = acc[mt][nt][2]; p1[1] = acc[mt][nt][3];
        }
    }
}

// ---------------- a/b projection ----------------------------------------
__global__ void __launch_bounds__(256) ab_gemm(const float* __restrict__ x,
                                               const float* __restrict__ Wa,
                                               const float* __restrict__ Wb) {
    __shared__ float Xs[32][64];
    __shared__ float Ws[32][64];
    const int t = threadIdx.x;
    const int s0 = blockIdx.x * 64;
    const int tx = t & 15, ty = t >> 4;
    float acc[4][4];
#pragma unroll
    for (int i = 0; i < 4; i++)
#pragma unroll
        for (int j = 0; j < 4; j++) acc[i][j] = 0.f;

    for (int k0 = 0; k0 < HIDN; k0 += 32) {
        for (int e = t; e < 2048; e += 256) {
            int r = e >> 5, c = e & 31;
            Xs[c][r] = x[(size_t)(s0 + r) * HIDN + k0 + c];
            const float* Wrow = (r < 32) ? (Wa + (size_t)r * HIDN) : (Wb + (size_t)(r - 32) * HIDN);
            Ws[c][r] = Wrow[k0 + c];
        }
        __syncthreads();
#pragma unroll
        for (int kk = 0; kk < 32; kk++) {
            float a[4], b[4];
#pragma unroll
            for (int i = 0; i < 4; i++) { a[i] = Xs[kk][ty * 4 + i]; b[i] = Ws[kk][tx * 4 + i]; }
#pragma unroll
            for (int i = 0; i < 4; i++)
#pragma unroll
                for (int j = 0; j < 4; j++) acc[i][j] += a[i] * b[j];
        }
        __syncthreads();
    }
#pragma unroll
    for (int i = 0; i < 4; i++)
#pragma unroll
        for (int j = 0; j < 4; j++)
            d_ab[(size_t)(s0 + ty * 4 + i) * 64 + tx * 4 + j] = acc[i][j];
}

// ---------------- causal conv(K=4) + SiLU, MLP-8 version ----------------
__global__ void __launch_bounds__(256) conv_silu(const float* __restrict__ cw) {
    int c  = blockIdx.x * 256 + threadIdx.x;
    int s0 = blockIdx.y * 8;
    float w0 = cw[c * 4], w1 = cw[c * 4 + 1], w2 = cw[c * 4 + 2], w3 = cw[c * 4 + 3];
    float xx[11];
#pragma unroll
    for (int j = 0; j < 11; j++) {
        int s = s0 - 3 + j;
        xx[j] = (s >= 0) ? d_mixed[(size_t)s * CDIM + c] : 0.f;
    }
#pragma unroll
    for (int i = 0; i < 8; i++) {
        float acc = w0 * xx[i] + w1 * xx[i + 1] + w2 * xx[i + 2] + w3 * xx[i + 3];
        float r = acc / (1.f + expf(-acc));
        int s = s0 + i;
        if (c < 2048)      d_q[(size_t)s * 2048 + c] = r;
        else if (c < 4096) d_k[(size_t)s * 2048 + (c - 2048)] = r;
        else               d_v[(size_t)s * 4096 + (c - 4096)] = r;
    }
}

// ---------------- l2norm on q (with DK^-0.5) and k -----------------------
__global__ void l2norm_kernel() {
    int b = blockIdx.x, t = threadIdx.x;
    float* buf = (blockIdx.y == 0) ? d_q : d_k;
    size_t idx = (size_t)b * 128 + t;
    float v = buf[idx];
    float ss = v * v;
#pragma unroll
    for (int o = 16; o > 0; o >>= 1) ss += __shfl_xor_sync(~0u, ss, o);
    __shared__ float ws[4];
    if ((t & 31) == 0) ws[t >> 5] = ss;
    __syncthreads();
    ss = (ws[0] + ws[1]) + (ws[2] + ws[3]);
    float sc = rsqrtf(ss + 1e-6f);
    if (blockIdx.y == 0) sc *= 0.08838834764831845f;
    buf[idx] = v * sc;
}

// ---------------- gate ----------------------------------------------------
__global__ void gate_kernel(const float* __restrict__ dt_bias,
                            const float* __restrict__ A_log) {
    int h = blockIdx.x, n = blockIdx.y, i = threadIdx.x;
    int s = n * CHK + i;
    float a = d_ab[(size_t)s * 64 + h];
    float b = d_ab[(size_t)s * 64 + 32 + h];
    float xx = a + dt_bias[h];
    float sp = fmaxf(xx, 0.f) + log1pf(expf(-fabsf(xx)));
    float gv = -expf(A_log[h]) * sp;
    float beta = 1.f / (1.f + expf(-b));
    int lane = i & 31;
#pragma unroll
    for (int o = 1; o < 32; o <<= 1) {
        float nv = __shfl_up_sync(~0u, gv, o);
        if (lane >= o) gv += nv;
    }
    __shared__ float carry;
    if (i == 31) carry = gv;
    __syncthreads();
    if (i >= 32) gv += carry;
    d_g[(size_t)h * SEQ + s] = gv;
    d_beta[(size_t)h * SEQ + s] = beta;
    if (i == 63) d_egl[h * NCH + n] = expf(gv);
}

// ---------------- intra-chunk (84KB smem -> 2 blocks/SM) -----------------
__global__ void __launch_bounds__(256, 2) intra_kernel() {
    float* sm  = (float*)dyn_smem;
    float* sq  = sm;              // 64*128 (q, later v*beta)
    float* sk  = sm + 8192;       // 64*128 (k, later k*scv)
    float* sA  = sm + 16384;      // 64*64
    float* sg  = sm + 20480;      // 64
    float* sb  = sm + 20544;      // 64
    float* scv = sm + 20608;      // 64
    float* se  = sm + 20672;      // 64  exp(g)
    float* ser = sm + 20736;      // 64  exp(gl-g)
    float* sP  = sm + 20800;      // 256

    const int n = blockIdx.x, h = blockIdx.y, kvh = h >> 1, t = threadIdx.x;
    const int sbase = n * CHK;

    for (int e = t; e < 2048; e += 256) {
        int i = e >> 5, d = (e & 31) << 2;
        int s = sbase + i;
        *(float4*)&sq[i * 128 + d] = *(const float4*)&d_q[((size_t)s * NKH + kvh) * 128 + d];
        *(float4*)&sk[i * 128 + d] = *(const float4*)&d_k[((size_t)s * NKH + kvh) * 128 + d];
    }
    if (t < 64) {
        sg[t] = d_g[(size_t)h * SEQ + sbase + t];
        sb[t] = d_beta[(size_t)h * SEQ + sbase + t];
    }
    __syncthreads();
    if (t < 64) {
        scv[t] = sb[t] * expf(sg[t]);
        se[t]  = expf(sg[t]);
        ser[t] = expf(sg[63] - sg[t]);
    }
    __syncthreads();

    // ---- elementwise qg = q*e^g, kbar = k*e^(gl-g) ----
    for (int e = t; e < 2048; e += 256) {
        int i = e >> 5, d = (e & 31) << 2;
        size_t rb = ((size_t)h * SEQ + sbase + i) * 128 + d;
        float eg = se[i], er = ser[i];
        float4 qv = *(const float4*)&sq[i * 128 + d];
        float4 kv = *(const float4*)&sk[i * 128 + d];
        *(float4*)&d_qg[rb]   = make_float4(qv.x * eg, qv.y * eg, qv.z * eg, qv.w * eg);
        *(float4*)&d_kbar[rb] = make_float4(kv.x * er, kv.y * er, kv.z * er, kv.w * er);
    }

    const int i0 = (t >> 4) << 2, j0 = (t & 15) << 2;

    // ---- fused: A (k.k) + scores (q.k) in one pass ----
    {
        float accA[4][4], accS[4][4];
#pragma unroll
        for (int ii = 0; ii < 4; ii++)
#pragma unroll
            for (int jj = 0; jj < 4; jj++) { accA[ii][jj] = 0.f; accS[ii][jj] = 0.f; }
        for (int kk = 0; kk < 128; kk += 4) {
            float4 ak[4], aq[4], bk[4];
#pragma unroll
            for (int ii = 0; ii < 4; ii++) {
                ak[ii] = *(const float4*)&sk[(i0 + ii) * 128 + kk];
                aq[ii] = *(const float4*)&sq[(i0 + ii) * 128 + kk];
                bk[ii] = *(const float4*)&sk[(j0 + ii) * 128 + kk];
            }
#pragma unroll
            for (int ii = 0; ii < 4; ii++)
#pragma unroll
                for (int jj = 0; jj < 4; jj++) {
                    accA[ii][jj] += ak[ii].x * bk[jj].x + ak[ii].y * bk[jj].y +
                                    ak[ii].z * bk[jj].z + ak[ii].w * bk[jj].w;
                    accS[ii][jj] += aq[ii].x * bk[jj].x + aq[ii].y * bk[jj].y +
                                    aq[ii].z * bk[jj].z + aq[ii].w * bk[jj].w;
                }
        }
        const size_t scb = ((size_t)h * NCH + n) * 4096;
#pragma unroll
        for (int ii = 0; ii < 4; ii++)
#pragma unroll
            for (int jj = 0; jj < 4; jj++) {
                int i = i0 + ii, j = j0 + jj;
                float dec = expf(sg[i] - sg[j]);
                sA[i * 64 + j]      = (i > j)  ? -sb[i] * accA[ii][jj] * dec : 0.f;
                d_sc[scb + i * 64 + j] = (i >= j) ? accS[ii][jj] * dec : 0.f;
            }
    }
    __syncthreads();

    // ---- UT transform (forward substitution) ----
    {
        int j = t & 63, pt = t >> 6;
        for (int i = 1; i < 64; i++) {
            float p = 0.f;
            if (j < i)
                for (int kk = j + 1 + pt; kk < i; kk += 4)
                    p += sA[i * 64 + kk] * sA[kk * 64 + j];
            sP[t] = p;
            __syncthreads();
            if (t < i) sA[i * 64 + t] += sP[t] + sP[64 + t] + sP[128 + t] + sP[192 + t];
            __syncthreads();
        }
    }

    // ---- overwrite sq with v*beta ----
    for (int e = t; e < 2048; e += 256) {
        int i = e >> 5, d = (e & 31) << 2;
        float4 vv = *(const float4*)&d_v[((size_t)(sbase + i) * NVH + h) * 128 + d];
        float b = sb[i];
        *(float4*)&sq[i * 128 + d] = make_float4(vv.x * b, vv.y * b, vv.z * b, vv.w * b);
    }
    __syncthreads();

    const int dv = t & 127, half = t >> 7;

    // ---- u = (I + A) @ vb ----
    for (int ii = 0; ii < 32; ii++) {
        int i = half * 32 + ii;
        float a = sq[i * 128 + dv];
        for (int kk = 0; kk < i; kk++) a += sA[i * 64 + kk] * sq[kk * 128 + dv];
        d_u[((size_t)h * SEQ + sbase + i) * 128 + dv] = a;
    }
    __syncthreads();

    // ---- scale sk in place: k * beta * e^g ----
    for (int e = t; e < 8192; e += 256) sk[e] *= scv[e >> 7];
    __syncthreads();

    // ---- kcd = (I+A) @ (k*beta*e^g) ----
    for (int ii = 0; ii < 32; ii++) {
        int i = half * 32 + ii;
        float a = sk[i * 128 + dv];
        for (int kk = 0; kk < i; kk++) a += sA[i * 64 + kk] * sk[kk * 128 + dv];
        d_kcd[((size_t)h * SEQ + sbase + i) * 128 + dv] = a;
    }
}

// ---------------- sequential inter-chunk scan (register-blocked) ---------
__global__ void __launch_bounds__(512) scan_kernel() {
    float* sm = (float*)dyn_smem;
    float* st  = sm;           // 128*32 state slice
    float* skc = sm + 4096;    // 64*128 kcd (pre-negated)
    float* sqg = sm + 12288;   // 64*128 qg
    float* skb = sm + 20480;   // 64*128 kbar
    float* ssc = sm + 28672;   // 64*64 scores
    float* svn = sm + 32768;   // 64*32 v_new
    float* su  = sm + 34816;   // 64*32 u slice

    const int h = blockIdx.x >> 2, sl = blockIdx.x & 3, t = threadIdx.x;
    const int dv0 = sl * 32;
    const int i0 = (t >> 4) << 1;      // 2 rows per thread (v_new / o)
    const int dp = (t & 15) << 1;      // dv pair
    const int dk4 = (t >> 4) << 2;     // 4 dk per thread (state update)

    for (int e = t; e < 4096; e += 512) st[e] = 0.f;

    for (int n = 0; n < NCH; n++) {
        const size_t rb = ((size_t)h * SEQ + n * CHK) * 128;
        for (int e = t; e < 2048; e += 512) {
            float4 kc = ((const float4*)(d_kcd + rb))[e];
            ((float4*)skc)[e] = make_float4(-kc.x, -kc.y, -kc.z, -kc.w);
            ((float4*)sqg)[e] = ((const float4*)(d_qg + rb))[e];
            ((float4*)skb)[e] = ((const float4*)(d_kbar + rb))[e];
        }
        const size_t scb = ((size_t)h * NCH + n) * 4096;
        for (int e = t; e < 1024; e += 512)
            ((float4*)ssc)[e] = ((const float4*)(d_sc + scb))[e];
        {
            int e = t;
            int i = e >> 3, q4 = e & 7;
            ((float4*)su)[e] = *(const float4*)&d_u[rb + (size_t)i * 128 + dv0 + q4 * 4];
        }
        __syncthreads();

        const float egl = d_egl[h * NCH + n];

        // ---- v_new = u - kcd @ state (2 rows/thread, skc pre-negated) ----
        {
            u64 a0 = *(u64*)&su[i0 * 32 + dp];
            u64 a1 = *(u64*)&su[(i0 + 1) * 32 + dp];
            for (int dk0 = 0; dk0 < 128; dk0 += 4) {
                float4 k0 = *(const float4*)&skc[i0 * 128 + dk0];
                float4 k1 = *(const float4*)&skc[(i0 + 1) * 128 + dk0];
                u64 s0 = *(u64*)&st[(dk0    ) * 32 + dp];
                u64 s1 = *(u64*)&st[(dk0 + 1) * 32 + dp];
                u64 s2 = *(u64*)&st[(dk0 + 2) * 32 + dp];
                u64 s3 = *(u64*)&st[(dk0 + 3) * 32 + dp];
                fma2(a0, pack2(k0.x, k0.x), s0); fma2(a1, pack2(k1.x, k1.x), s0);
                fma2(a0, pack2(k0.y, k0.y), s1); fma2(a1, pack2(k1.y, k1.y), s1);
                fma2(a0, pack2(k0.z, k0.z), s2); fma2(a1, pack2(k1.z, k1.z), s2);
                fma2(a0, pack2(k0.w, k0.w), s3); fma2(a1, pack2(k1.w, k1.w), s3);
            }
            *(u64*)&svn[i0 * 32 + dp] = a0;
            *(u64*)&svn[(i0 + 1) * 32 + dp] = a1;
        }
        __syncthreads();

        // ---- o = qg @ state + scores @ v_new (2 rows/thread) ----
        {
            u64 a0 = 0ull, a1 = 0ull;
            for (int dk0 = 0; dk0 < 128; dk0 += 4) {
                float4 q0 = *(const float4*)&sqg[i0 * 128 + dk0];
                float4 q1 = *(const float4*)&sqg[(i0 + 1) * 128 + dk0];
                u64 s0 = *(u64*)&st[(dk0    ) * 32 + dp];
                u64 s1 = *(u64*)&st[(dk0 + 1) * 32 + dp];
                u64 s2 = *(u64*)&st[(dk0 + 2) * 32 + dp];
                u64 s3 = *(u64*)&st[(dk0 + 3) * 32 + dp];
                fma2(a0, pack2(q0.x, q0.x), s0); fma2(a1, pack2(q1.x, q1.x), s0);
                fma2(a0, pack2(q0.y, q0.y), s1); fma2(a1, pack2(q1.y, q1.y), s1);
                fma2(a0, pack2(q0.z, q0.z), s2); fma2(a1, pack2(q1.z, q1.z), s2);
                fma2(a0, pack2(q0.w, q0.w), s3); fma2(a1, pack2(q1.w, q1.w), s3);
            }
            for (int j = 0; j <= i0; j++) {
                u64 vn = *(u64*)&svn[j * 32 + dp];
                float sA0 = ssc[i0 * 64 + j];
                float sA1 = ssc[(i0 + 1) * 64 + j];
                fma2(a0, pack2(sA0, sA0), vn);
                fma2(a1, pack2(sA1, sA1), vn);
            }
            {
                int j = i0 + 1;
                float sA1 = ssc[j * 64 + j];
                fma2(a1, pack2(sA1, sA1), *(u64*)&svn[j * 32 + dp]);
            }
            float2 p0 = unpack2(a0), p1 = unpack2(a1);
            *(float2*)&d_o[rb + (size_t)i0 * 128 + dv0 + dp] = p0;
            *(float2*)&d_o[rb + (size_t)(i0 + 1) * 128 + dv0 + dp] = p1;
        }
        __syncthreads();

        // ---- state = state*egl + kbar^T @ v_new (4 dk/thread) ----
        {
            u64 a0 = pack2(st[(dk4    ) * 32 + dp] * egl, st[(dk4    ) * 32 + dp + 1] * egl);
            u64 a1 = pack2(st[(dk4 + 1) * 32 + dp] * egl, st[(dk4 + 1) * 32 + dp + 1] * egl);
            u64 a2 = pack2(st[(dk4 + 2) * 32 + dp] * egl, st[(dk4 + 2) * 32 + dp + 1] * egl);
            u64 a3 = pack2(st[(dk4 + 3) * 32 + dp] * egl, st[(dk4 + 3) * 32 + dp + 1] * egl);
            for (int i = 0; i < 64; i++) {
                u64 vn = *(u64*)&svn[i * 32 + dp];
                float4 kb = *(const float4*)&skb[i * 128 + dk4];
                fma2(a0, pack2(kb.x, kb.x), vn);
                fma2(a1, pack2(kb.y, kb.y), vn);
                fma2(a2, pack2(kb.z, kb.z), vn);
                fma2(a3, pack2(kb.w, kb.w), vn);
            }
            float2 p;
            p = unpack2(a0); st[(dk4    ) * 32 + dp] = p.x; st[(dk4    ) * 32 + dp + 1] = p.y;
            p = unpack2(a1); st[(dk4 + 1) * 32 + dp] = p.x; st[(dk4 + 1) * 32 + dp + 1] = p.y;
            p = unpack2(a2); st[(dk4 + 2) * 32 + dp] = p.x; st[(dk4 + 2) * 32 + dp + 1] = p.y;
            p = unpack2(a3); st[(dk4 + 3) * 32 + dp] = p.x; st[(dk4 + 3) * 32 + dp + 1] = p.y;
        }
        __syncthreads();
    }
}

// ---------------- RMSNorm + z-gate epilogue -> fp16 hi/lo ----------------
__global__ void rms_kernel(const float* __restrict__ norm_w) {
    int b = blockIdx.x;
    int s = b >> 5, h = b & 31, t = threadIdx.x;
    float v = d_o[((size_t)h * SEQ + s) * 128 + t];
    float ss = v * v;
#pragma unroll
    for (int o = 16; o > 0; o >>= 1) ss += __shfl_xor_sync(~0u, ss, o);
    __shared__ float ws[4];
    if ((t & 31) == 0) ws[t >> 5] = ss;
    __syncthreads();
    ss = (ws[0] + ws[1]) + (ws[2] + ws[3]);
    float r = rsqrtf(ss * (1.f / 128.f) + 1e-6f);
    float z = d_z[(size_t)s * VALD + h * 128 + t];
    float sz = z / (1.f + expf(-z));
    float val = v * r * norm_w[t] * sz;
    size_t idx = (size_t)s * VALD + h * 128 + t;
    __half hh = __float2half_rn(val);
    g_yh[idx] = hh;
    g_yl[idx] = __float2half_rn(val - __half2float(hh));
}

// ---------------- launch ---------------------------------------------------
extern "C" void kernel_launch(void* const* d_in, const int* in_sizes, int n_in,
                              void* d_out, int out_size) {
    const float* x       = (const float*)d_in[0];
    const float* W_qkv   = (const float*)d_in[1];
    const float* W_z     = (const float*)d_in[2];
    const float* W_a     = (const float*)d_in[3];
    const float* W_b     = (const float*)d_in[4];
    const float* conv_w  = (const float*)d_in[5];
    const float* dt_bias = (const float*)d_in[6];
    const float* A_log   = (const float*)d_in[7];
    const float* norm_w  = (const float*)d_in[8];
    const float* W_out   = (const float*)d_in[9];
    float* out = (float*)d_out;

    void *p_mixed, *p_z;
    cudaGetSymbolAddress(&p_mixed, d_mixed);
    cudaGetSymbolAddress(&p_z, d_z);
    void *p_xh, *p_xl, *p_qkh, *p_qkl, *p_wzh, *p_wzl, *p_woh, *p_wol, *p_yh, *p_yl;
    cudaGetSymbolAddress(&p_xh, g_xh);   cudaGetSymbolAddress(&p_xl, g_xl);
    cudaGetSymbolAddress(&p_qkh, g_qkh); cudaGetSymbolAddress(&p_qkl, g_qkl);
    cudaGetSymbolAddress(&p_wzh, g_wzh); cudaGetSymbolAddress(&p_wzl, g_wzl);
    cudaGetSymbolAddress(&p_woh, g_woh); cudaGetSymbolAddress(&p_wol, g_wol);
    cudaGetSymbolAddress(&p_yh, g_yh);   cudaGetSymbolAddress(&p_yl, g_yl);

    const int INTRA_SMEM = 21056 * 4;     // 84224 bytes -> 2 blocks/SM
    const int SCAN_SMEM  = 36864 * 4;
    cudaFuncSetAttribute(intra_kernel, cudaFuncAttributeMaxDynamicSharedMemorySize, INTRA_SMEM);
    cudaFuncSetAttribute(scan_kernel,  cudaFuncAttributeMaxDynamicSharedMemorySize, SCAN_SMEM);
    cudaFuncSetAttribute(tc_gemm,      cudaFuncAttributeMaxDynamicSharedMemorySize, GEMM_SMEM);

    // launches 0-2: converts; launch index 3 = tc_gemm(qkv) -> profiled slot
    cvt_split<<<(SEQ * HIDN / 4 + 255) / 256, 256>>>(x, (__half*)p_xh, (__half*)p_xl, SEQ * HIDN / 4);
    cvt_split<<<(CDIM * HIDN / 4 + 255) / 256, 256>>>(W_qkv, (__half*)p_qkh, (__half*)p_qkl, CDIM * HIDN / 4);
    cvt_split<<<(VALD * HIDN / 4 + 255) / 256, 256>>>(W_z, (__half*)p_wzh, (__half*)p_wzl, VALD * HIDN / 4);

    tc_gemm<<<dim3(CDIM / 128, SEQ / 128), 256, GEMM_SMEM>>>(
        (const __half*)p_xh, (const __half*)p_xl, (const __half*)p_qkh,
        (float*)p_mixed, CDIM, HIDN);
    tc_gemm<<<dim3(VALD / 128, SEQ / 128), 256, GEMM_SMEM>>>(
        (const __half*)p_xh, (const __half*)p_xl, (const __half*)p_wzh,
        (float*)p_z, VALD, HIDN);

    cvt_split<<<(HIDN * VALD / 4 + 255) / 256, 256>>>(W_out, (__half*)p_woh, (__half*)p_wol, HIDN * VALD / 4);
    ab_gemm<<<SEQ / 64, 256>>>(x, W_a, W_b);

    // conv + silu + split (MLP-8)
    conv_silu<<<dim3(CDIM / 256, SEQ / 8), 256>>>(conv_w);

    // l2norm q (scaled) and k
    l2norm_kernel<<<dim3(SEQ * NKH, 2), 128>>>();

    // gates
    gate_kernel<<<dim3(NVH, NCH), 64>>>(dt_bias, A_log);

    // intra-chunk precompute
    intra_kernel<<<dim3(NCH, NVH), 256, INTRA_SMEM>>>();

    // sequential inter-chunk scan (32 heads x 4 DV-slices)
    scan_kernel<<<NVH * 4, 512, SCAN_SMEM>>>();

    // rmsnorm + gate epilogue -> fp16 hi/lo
    rms_kernel<<<SEQ * NVH, 128>>>(norm_w);

    // output projection (2-term fp16)
    tc_gemm<<<dim3(HIDN / 128, SEQ / 128), 256, GEMM_SMEM>>>(
        (const __half*)p_yh, (const __half*)p_yl, (const __half*)p_woh,
        out, HIDN, VALD);
}

// round 14
// speedup vs baseline: 3.0119x; 1.2067x over previous
#include <cuda_runtime.h>
#include <cuda_fp16.h>
#include <math.h>

// ---------------- problem constants ----------------
#define SEQ   2048
#define HIDN  2048
#define NKH   16
#define NVH   32
#define DKD   128
#define DVD   128
#define CDIM  8192
#define VALD  4096
#define NCH   32      // chunks
#define CHK   64      // chunk size

typedef unsigned long long u64;
typedef unsigned int u32;

// single dynamic smem symbol shared by all kernels
extern __shared__ __align__(16) char dyn_smem[];

// ---------------- scratch (device globals; no cudaMalloc allowed) -------
__device__ float d_mixed[SEQ * CDIM];
__device__ float d_z   [SEQ * VALD];
__device__ float d_ab  [SEQ * 64];
__device__ float d_q   [SEQ * 2048];
__device__ float d_k   [SEQ * 2048];
__device__ float d_v   [SEQ * VALD];
__device__ float d_g   [NVH * SEQ];
__device__ float d_beta[NVH * SEQ];
__device__ float d_egl [NVH * NCH];
__device__ float d_u   [NVH * SEQ * DVD];
__device__ float d_kcd [NVH * SEQ * DKD];
__device__ float d_qg  [NVH * SEQ * DKD];
__device__ float d_kbar[NVH * SEQ * DKD];
__device__ float d_sc  [NVH * NCH * CHK * CHK];
__device__ float d_o   [NVH * SEQ * DVD];

// fp16 split buffers for tensor-core GEMMs
__device__ __half g_xh  [SEQ * HIDN],  g_xl  [SEQ * HIDN];
__device__ __half g_qkh [CDIM * HIDN];
__device__ __half g_wzh [VALD * HIDN];
__device__ __half g_woh [HIDN * VALD];
__device__ __half g_yh  [SEQ * VALD];

// ---------------- packed f32x2 helpers ----------------
__device__ __forceinline__ u64 pack2(float lo, float hi) {
    u64 r; asm("mov.b64 %0,{%1,%2};" : "=l"(r) : "f"(lo), "f"(hi)); return r;
}
__device__ __forceinline__ float2 unpack2(u64 v) {
    float2 r; asm("mov.b64 {%0,%1},%2;" : "=f"(r.x), "=f"(r.y) : "l"(v)); return r;
}
__device__ __forceinline__ void fma2(u64& d, u64 a, u64 b) {
    asm("fma.rn.f32x2 %0,%1,%2,%0;" : "+l"(d) : "l"(a), "l"(b));
}

// ---------------- fp32 -> fp16 hi/lo split ----------------
__global__ void __launch_bounds__(256) cvt_split(const float* __restrict__ s,
                                                 __half* __restrict__ h,
                                                 __half* __restrict__ l,
                                                 int n4) {
    int i = blockIdx.x * 256 + threadIdx.x;
    if (i >= n4) return;
    float4 v = ((const float4*)s)[i];
    __half h0 = __float2half_rn(v.x);
    __half h1 = __float2half_rn(v.y);
    __half h2 = __float2half_rn(v.z);
    __half h3 = __float2half_rn(v.w);
    __half2* hp = (__half2*)h;
    __half2* lp = (__half2*)l;
    hp[2 * i]     = __half2(h0, h1);
    hp[2 * i + 1] = __half2(h2, h3);
    lp[2 * i]     = __half2(__float2half_rn(v.x - __half2float(h0)),
                            __float2half_rn(v.y - __half2float(h1)));
    lp[2 * i + 1] = __half2(__float2half_rn(v.z - __half2float(h2)),
                            __float2half_rn(v.w - __half2float(h3)));
}

// hi-only convert (for W_out)
__global__ void __launch_bounds__(256) cvt_h(const float* __restrict__ s,
                                             __half* __restrict__ h, int n4) {
    int i = blockIdx.x * 256 + threadIdx.x;
    if (i >= n4) return;
    float4 v = ((const float4*)s)[i];
    __half2* hp = (__half2*)h;
    hp[2 * i]     = __half2(__float2half_rn(v.x), __float2half_rn(v.y));
    hp[2 * i + 1] = __half2(__float2half_rn(v.z), __float2half_rn(v.w));
}

// ---------------- warp-MMA fp16 GEMM: C[M,N] = A[M,K] @ B[N,K]^T --------
// TERMS=2: C = Ah*Bh + Al*Bh (3 tiles/stage); TERMS=1: C = Ah*Bh (2 tiles).
// 2-stage cp.async pipeline, ldmatrix fragment loads, 2 CTAs/SM.
#define BKC   32
#define SROW  40
#define TILE_W (128 * SROW)
#define TILE_B (TILE_W * 2)                // 10240 bytes per tile

__device__ __forceinline__ void mma_f16(float* c, const u32* a, const u32* b) {
    asm volatile(
        "mma.sync.aligned.m16n8k16.row.col.f32.f16.f16.f32 "
        "{%0,%1,%2,%3}, {%4,%5,%6,%7}, {%8,%9}, {%0,%1,%2,%3};"
        : "+f"(c[0]), "+f"(c[1]), "+f"(c[2]), "+f"(c[3])
        : "r"(a[0]), "r"(a[1]), "r"(a[2]), "r"(a[3]), "r"(b[0]), "r"(b[1]));
}

__device__ __forceinline__ void ldsm_x4(u32& r0, u32& r1, u32& r2, u32& r3, u32 addr) {
    asm volatile("ldmatrix.sync.aligned.m8n8.x4.shared.b16 {%0,%1,%2,%3}, [%4];"
                 : "=r"(r0), "=r"(r1), "=r"(r2), "=r"(r3) : "r"(addr));
}

template <int TERMS>
__global__ void __launch_bounds__(256, 2)
tc_gemm(const __half* __restrict__ Ah, const __half* __restrict__ Al,
        const __half* __restrict__ Bh,
        float* __restrict__ C, int N, int K) {
    constexpr int NT = TERMS + 1;          // tiles per stage (A terms + B)
    constexpr u32 STG = NT * TILE_B;

    __half* sm = (__half*)dyn_smem;

    const int t = threadIdx.x, lane = t & 31, wid = t >> 5;
    const int wm = wid & 3, wn = wid >> 2;
    const int bx = blockIdx.x, by = blockIdx.y;
    const int NCHUNK = K / BKC;

    u32 smem_base;
    asm("{ .reg .u64 tt; cvta.to.shared.u64 tt, %1; cvt.u32.u64 %0, tt; }"
        : "=r"(smem_base) : "l"(sm));

    const __half* srcs[3];
    srcs[0] = Ah + (size_t)by * 128 * K;
    if (TERMS == 2) { srcs[1] = Al + (size_t)by * 128 * K; srcs[2] = Bh + (size_t)bx * 128 * K; }
    else            { srcs[1] = Bh + (size_t)bx * 128 * K; srcs[2] = srcs[1]; }
    const u32 bTile = (u32)(TERMS) * TILE_B;   // B tile byte offset within stage

    auto load_chunk = [&](int n, int s) {
        u32 sb = smem_base + (u32)s * STG;
#pragma unroll
        for (int tile = 0; tile < NT; tile++) {
#pragma unroll
            for (int j = 0; j < 2; j++) {
                int f = t + 256 * j;
                int row = f >> 2, c = f & 3;
                const __half* g = srcs[tile] + (size_t)row * K + n * BKC + c * 8;
                u32 d = sb + (u32)tile * TILE_B + (u32)(row * SROW + c * 8) * 2;
                asm volatile("cp.async.cg.shared.global [%0], [%1], 16;"
                             :: "r"(d), "l"(g));
            }
        }
        asm volatile("cp.async.commit_group;" ::: "memory");
    };

    float acc[2][8][4];
#pragma unroll
    for (int mt = 0; mt < 2; mt++)
#pragma unroll
        for (int nt = 0; nt < 8; nt++)
#pragma unroll
            for (int e = 0; e < 4; e++) acc[mt][nt][e] = 0.f;

    const int aRow = wm * 32 + (lane & 7) + ((lane >> 3) & 1) * 8;
    const u32 aOff = (u32)((aRow * SROW + (lane >> 4) * 8) * 2);
    const int bRow = wn * 64 + (lane & 7) + ((lane >> 4) & 1) * 8;
    const u32 bOff = (u32)((bRow * SROW + ((lane >> 3) & 1) * 8) * 2);

    load_chunk(0, 0);

    for (int n = 0; n < NCHUNK; n++) {
        int s = n & 1;
        asm volatile("cp.async.wait_group 0;" ::: "memory");
        __syncthreads();
        if (n + 1 < NCHUNK) load_chunk(n + 1, 1 - s);

        u32 sb = smem_base + (u32)s * STG;

#pragma unroll
        for (int k16 = 0; k16 < 2; k16++) {
            const u32 kb = (u32)(k16 * 16 * 2);
            u32 bh[8][2];
#pragma unroll
            for (int p = 0; p < 4; p++) {
                u32 base = sb + bTile + bOff + (u32)(p * 16 * SROW) * 2 + kb;
                ldsm_x4(bh[2 * p][0], bh[2 * p][1], bh[2 * p + 1][0], bh[2 * p + 1][1], base);
            }
#pragma unroll
            for (int mt = 0; mt < 2; mt++) {
                u32 ah[4], al[4];
                u32 base = sb + aOff + (u32)(mt * 16 * SROW) * 2 + kb;
                ldsm_x4(ah[0], ah[1], ah[2], ah[3], base);
                if (TERMS == 2) ldsm_x4(al[0], al[1], al[2], al[3], base + TILE_B);
#pragma unroll
                for (int nt = 0; nt < 8; nt++) {
                    mma_f16(acc[mt][nt], ah, bh[nt]);
                    if (TERMS == 2) mma_f16(acc[mt][nt], al, bh[nt]);
                }
            }
        }
    }

    const int gid = lane >> 2, tig = lane & 3;
#pragma unroll
    for (int mt = 0; mt < 2; mt++) {
        int rbase = by * 128 + wm * 32 + mt * 16;
#pragma unroll
        for (int nt = 0; nt < 8; nt++) {
            int cbase = bx * 128 + wn * 64 + nt * 8 + tig * 2;
            float* p0 = C + (size_t)(rbase + gid) * N + cbase;
            float* p1 = C + (size_t)(rbase + gid + 8) * N + cbase;
            p0[0] = acc[mt][nt][0]; p0[1] = acc[mt][nt][1];
            p1[0] = acc[mt][nt][2]; p1[1] = acc[mt][nt][3];
        }
    }
}

// ---------------- a/b projection (K-split x8, atomicAdd) -----------------
__global__ void __launch_bounds__(256) ab_gemm(const float* __restrict__ x,
                                               const float* __restrict__ Wa,
                                               const float* __restrict__ Wb) {
    __shared__ float Xs[32][64];
    __shared__ float Ws[32][64];
    const int t = threadIdx.x;
    const int s0 = blockIdx.x * 64;
    const int kbase = blockIdx.y * 256;
    const int tx = t & 15, ty = t >> 4;
    float acc[4][4];
#pragma unroll
    for (int i = 0; i < 4; i++)
#pragma unroll
        for (int j = 0; j < 4; j++) acc[i][j] = 0.f;

    for (int k0 = kbase; k0 < kbase + 256; k0 += 32) {
        for (int e = t; e < 2048; e += 256) {
            int r = e >> 5, c = e & 31;
            Xs[c][r] = x[(size_t)(s0 + r) * HIDN + k0 + c];
            const float* Wrow = (r < 32) ? (Wa + (size_t)r * HIDN) : (Wb + (size_t)(r - 32) * HIDN);
            Ws[c][r] = Wrow[k0 + c];
        }
        __syncthreads();
#pragma unroll
        for (int kk = 0; kk < 32; kk++) {
            float a[4], b[4];
#pragma unroll
            for (int i = 0; i < 4; i++) { a[i] = Xs[kk][ty * 4 + i]; b[i] = Ws[kk][tx * 4 + i]; }
#pragma unroll
            for (int i = 0; i < 4; i++)
#pragma unroll
                for (int j = 0; j < 4; j++) acc[i][j] += a[i] * b[j];
        }
        __syncthreads();
    }
#pragma unroll
    for (int i = 0; i < 4; i++)
#pragma unroll
        for (int j = 0; j < 4; j++)
            atomicAdd(&d_ab[(size_t)(s0 + ty * 4 + i) * 64 + tx * 4 + j], acc[i][j]);
}

// ---------------- causal conv(K=4) + SiLU + fused l2norm -----------------
// Block = 256 channels x 8 seq. bx<8 -> q heads, 8..15 -> k heads, >=16 -> v.
__global__ void __launch_bounds__(256) conv_silu(const float* __restrict__ cw) {
    __shared__ float sr[8 * 256];      // squares for reduction
    __shared__ float sscale[16];       // [seq][half]
    int tc_ = threadIdx.x;
    int c  = blockIdx.x * 256 + tc_;
    int s0 = blockIdx.y * 8;
    float w0 = cw[c * 4], w1 = cw[c * 4 + 1], w2 = cw[c * 4 + 2], w3 = cw[c * 4 + 3];
    float xx[11];
#pragma unroll
    for (int j = 0; j < 11; j++) {
        int s = s0 - 3 + j;
        xx[j] = (s >= 0) ? d_mixed[(size_t)s * CDIM + c] : 0.f;
    }
    float r[8];
#pragma unroll
    for (int i = 0; i < 8; i++) {
        float a = w0 * xx[i] + w1 * xx[i + 1] + w2 * xx[i + 2] + w3 * xx[i + 3];
        r[i] = a / (1.f + expf(-a));
    }
    const bool isV = (blockIdx.x >= 16);
    if (!isV) {
        // fused l2norm over each 128-channel head half
#pragma unroll
        for (int i = 0; i < 8; i++) sr[i * 256 + tc_] = r[i] * r[i];
        __syncthreads();
        int g = tc_ >> 4, sub = tc_ & 15;      // 16 groups of 16 threads
        {
            int i = g >> 1, hf = g & 1;
            float s = 0.f;
            for (int q_ = sub; q_ < 128; q_ += 16) s += sr[i * 256 + hf * 128 + q_];
#pragma unroll
            for (int o = 8; o > 0; o >>= 1) s += __shfl_down_sync(0xffffffffu, s, o, 16);
            if (sub == 0) {
                float sc = rsqrtf(s + 1e-6f);
                if (blockIdx.x < 8) sc *= 0.08838834764831845f;   // q: DK^-0.5
                sscale[g] = sc;
            }
        }
        __syncthreads();
        int hf = tc_ >> 7;
#pragma unroll
        for (int i = 0; i < 8; i++) r[i] *= sscale[i * 2 + hf];
    }
#pragma unroll
    for (int i = 0; i < 8; i++) {
        int s = s0 + i;
        if (c < 2048)      d_q[(size_t)s * 2048 + c] = r[i];
        else if (c < 4096) d_k[(size_t)s * 2048 + (c - 2048)] = r[i];
        else               d_v[(size_t)s * 4096 + (c - 4096)] = r[i];
    }
}

// ---------------- gate ----------------------------------------------------
__global__ void gate_kernel(const float* __restrict__ dt_bias,
                            const float* __restrict__ A_log) {
    int h = blockIdx.x, n = blockIdx.y, i = threadIdx.x;
    int s = n * CHK + i;
    float a = d_ab[(size_t)s * 64 + h];
    float b = d_ab[(size_t)s * 64 + 32 + h];
    float xx = a + dt_bias[h];
    float sp = fmaxf(xx, 0.f) + log1pf(expf(-fabsf(xx)));
    float gv = -expf(A_log[h]) * sp;
    float beta = 1.f / (1.f + expf(-b));
    int lane = i & 31;
#pragma unroll
    for (int o = 1; o < 32; o <<= 1) {
        float nv = __shfl_up_sync(~0u, gv, o);
        if (lane >= o) gv += nv;
    }
    __shared__ float carry;
    if (i == 31) carry = gv;
    __syncthreads();
    if (i >= 32) gv += carry;
    d_g[(size_t)h * SEQ + s] = gv;
    d_beta[(size_t)h * SEQ + s] = beta;
    if (i == 63) d_egl[h * NCH + n] = expf(gv);
}

// ---------------- intra-chunk (84KB smem -> 2 blocks/SM) -----------------
__global__ void __launch_bounds__(256, 2) intra_kernel() {
    float* sm  = (float*)dyn_smem;
    float* sq  = sm;              // 64*128 (q, later v*beta)
    float* sk  = sm + 8192;       // 64*128 (k, later k*scv)
    float* sA  = sm + 16384;      // 64*64
    float* sg  = sm + 20480;      // 64
    float* sb  = sm + 20544;      // 64
    float* scv = sm + 20608;      // 64
    float* se  = sm + 20672;      // 64
    float* ser = sm + 20736;      // 64
    float* sP  = sm + 20800;      // 256

    const int n = blockIdx.x, h = blockIdx.y, kvh = h >> 1, t = threadIdx.x;
    const int sbase = n * CHK;

    for (int e = t; e < 2048; e += 256) {
        int i = e >> 5, d = (e & 31) << 2;
        int s = sbase + i;
        *(float4*)&sq[i * 128 + d] = *(const float4*)&d_q[((size_t)s * NKH + kvh) * 128 + d];
        *(float4*)&sk[i * 128 + d] = *(const float4*)&d_k[((size_t)s * NKH + kvh) * 128 + d];
    }
    if (t < 64) {
        sg[t] = d_g[(size_t)h * SEQ + sbase + t];
        sb[t] = d_beta[(size_t)h * SEQ + sbase + t];
    }
    __syncthreads();
    if (t < 64) {
        scv[t] = sb[t] * expf(sg[t]);
        se[t]  = expf(sg[t]);
        ser[t] = expf(sg[63] - sg[t]);
    }
    __syncthreads();

    for (int e = t; e < 2048; e += 256) {
        int i = e >> 5, d = (e & 31) << 2;
        size_t rb = ((size_t)h * SEQ + sbase + i) * 128 + d;
        float eg = se[i], er = ser[i];
        float4 qv = *(const float4*)&sq[i * 128 + d];
        float4 kv = *(const float4*)&sk[i * 128 + d];
        *(float4*)&d_qg[rb]   = make_float4(qv.x * eg, qv.y * eg, qv.z * eg, qv.w * eg);
        *(float4*)&d_kbar[rb] = make_float4(kv.x * er, kv.y * er, kv.z * er, kv.w * er);
    }

    const int i0 = (t >> 4) << 2, j0 = (t & 15) << 2;

    {
        float accA[4][4], accS[4][4];
#pragma unroll
        for (int ii = 0; ii < 4; ii++)
#pragma unroll
            for (int jj = 0; jj < 4; jj++) { accA[ii][jj] = 0.f; accS[ii][jj] = 0.f; }
        for (int kk = 0; kk < 128; kk += 4) {
            float4 ak[4], aq[4], bk[4];
#pragma unroll
            for (int ii = 0; ii < 4; ii++) {
                ak[ii] = *(const float4*)&sk[(i0 + ii) * 128 + kk];
                aq[ii] = *(const float4*)&sq[(i0 + ii) * 128 + kk];
                bk[ii] = *(const float4*)&sk[(j0 + ii) * 128 + kk];
            }
#pragma unroll
            for (int ii = 0; ii < 4; ii++)
#pragma unroll
                for (int jj = 0; jj < 4; jj++) {
                    accA[ii][jj] += ak[ii].x * bk[jj].x + ak[ii].y * bk[jj].y +
                                    ak[ii].z * bk[jj].z + ak[ii].w * bk[jj].w;
                    accS[ii][jj] += aq[ii].x * bk[jj].x + aq[ii].y * bk[jj].y +
                                    aq[ii].z * bk[jj].z + aq[ii].w * bk[jj].w;
                }
        }
        const size_t scb = ((size_t)h * NCH + n) * 4096;
#pragma unroll
        for (int ii = 0; ii < 4; ii++)
#pragma unroll
            for (int jj = 0; jj < 4; jj++) {
                int i = i0 + ii, j = j0 + jj;
                float dec = expf(sg[i] - sg[j]);
                sA[i * 64 + j]      = (i > j)  ? -sb[i] * accA[ii][jj] * dec : 0.f;
                d_sc[scb + i * 64 + j] = (i >= j) ? accS[ii][jj] * dec : 0.f;
            }
    }
    __syncthreads();

    {
        int j = t & 63, pt = t >> 6;
        for (int i = 1; i < 64; i++) {
            float p = 0.f;
            if (j < i)
                for (int kk = j + 1 + pt; kk < i; kk += 4)
                    p += sA[i * 64 + kk] * sA[kk * 64 + j];
            sP[t] = p;
            __syncthreads();
            if (t < i) sA[i * 64 + t] += sP[t] + sP[64 + t] + sP[128 + t] + sP[192 + t];
            __syncthreads();
        }
    }

    for (int e = t; e < 2048; e += 256) {
        int i = e >> 5, d = (e & 31) << 2;
        float4 vv = *(const float4*)&d_v[((size_t)(sbase + i) * NVH + h) * 128 + d];
        float b = sb[i];
        *(float4*)&sq[i * 128 + d] = make_float4(vv.x * b, vv.y * b, vv.z * b, vv.w * b);
    }
    __syncthreads();

    const int dv = t & 127, half = t >> 7;

    for (int ii = 0; ii < 32; ii++) {
        int i = half * 32 + ii;
        float a = sq[i * 128 + dv];
        for (int kk = 0; kk < i; kk++) a += sA[i * 64 + kk] * sq[kk * 128 + dv];
        d_u[((size_t)h * SEQ + sbase + i) * 128 + dv] = a;
    }
    __syncthreads();

    for (int e = t; e < 8192; e += 256) sk[e] *= scv[e >> 7];
    __syncthreads();

    for (int ii = 0; ii < 32; ii++) {
        int i = half * 32 + ii;
        float a = sk[i * 128 + dv];
        for (int kk = 0; kk < i; kk++) a += sA[i * 64 + kk] * sk[kk * 128 + dv];
        d_kcd[((size_t)h * SEQ + sbase + i) * 128 + dv] = a;
    }
}

// ---------------- sequential inter-chunk scan (register-blocked) ---------
__global__ void __launch_bounds__(512) scan_kernel() {
    float* sm = (float*)dyn_smem;
    float* st  = sm;           // 128*32 state slice
    float* skc = sm + 4096;    // 64*128 kcd (pre-negated)
    float* sqg = sm + 12288;   // 64*128 qg
    float* skb = sm + 20480;   // 64*128 kbar
    float* ssc = sm + 28672;   // 64*64 scores
    float* svn = sm + 32768;   // 64*32 v_new
    float* su  = sm + 34816;   // 64*32 u slice

    const int h = blockIdx.x >> 2, sl = blockIdx.x & 3, t = threadIdx.x;
    const int dv0 = sl * 32;
    const int i0 = (t >> 4) << 1;
    const int dp = (t & 15) << 1;
    const int dk4 = (t >> 4) << 2;

    for (int e = t; e < 4096; e += 512) st[e] = 0.f;

    for (int n = 0; n < NCH; n++) {
        const size_t rb = ((size_t)h * SEQ + n * CHK) * 128;
        for (int e = t; e < 2048; e += 512) {
            float4 kc = ((const float4*)(d_kcd + rb))[e];
            ((float4*)skc)[e] = make_float4(-kc.x, -kc.y, -kc.z, -kc.w);
            ((float4*)sqg)[e] = ((const float4*)(d_qg + rb))[e];
            ((float4*)skb)[e] = ((const float4*)(d_kbar + rb))[e];
        }
        const size_t scb = ((size_t)h * NCH + n) * 4096;
        for (int e = t; e < 1024; e += 512)
            ((float4*)ssc)[e] = ((const float4*)(d_sc + scb))[e];
        {
            int e = t;
            int i = e >> 3, q4 = e & 7;
            ((float4*)su)[e] = *(const float4*)&d_u[rb + (size_t)i * 128 + dv0 + q4 * 4];
        }
        __syncthreads();

        const float egl = d_egl[h * NCH + n];

        {
            u64 a0 = *(u64*)&su[i0 * 32 + dp];
            u64 a1 = *(u64*)&su[(i0 + 1) * 32 + dp];
            for (int dk0 = 0; dk0 < 128; dk0 += 4) {
                float4 k0 = *(const float4*)&skc[i0 * 128 + dk0];
                float4 k1 = *(const float4*)&skc[(i0 + 1) * 128 + dk0];
                u64 s0 = *(u64*)&st[(dk0    ) * 32 + dp];
                u64 s1 = *(u64*)&st[(dk0 + 1) * 32 + dp];
                u64 s2 = *(u64*)&st[(dk0 + 2) * 32 + dp];
                u64 s3 = *(u64*)&st[(dk0 + 3) * 32 + dp];
                fma2(a0, pack2(k0.x, k0.x), s0); fma2(a1, pack2(k1.x, k1.x), s0);
                fma2(a0, pack2(k0.y, k0.y), s1); fma2(a1, pack2(k1.y, k1.y), s1);
                fma2(a0, pack2(k0.z, k0.z), s2); fma2(a1, pack2(k1.z, k1.z), s2);
                fma2(a0, pack2(k0.w, k0.w), s3); fma2(a1, pack2(k1.w, k1.w), s3);
            }
            *(u64*)&svn[i0 * 32 + dp] = a0;
            *(u64*)&svn[(i0 + 1) * 32 + dp] = a1;
        }
        __syncthreads();

        {
            u64 a0 = 0ull, a1 = 0ull;
            for (int dk0 = 0; dk0 < 128; dk0 += 4) {
                float4 q0 = *(const float4*)&sqg[i0 * 128 + dk0];
                float4 q1 = *(const float4*)&sqg[(i0 + 1) * 128 + dk0];
                u64 s0 = *(u64*)&st[(dk0    ) * 32 + dp];
                u64 s1 = *(u64*)&st[(dk0 + 1) * 32 + dp];
                u64 s2 = *(u64*)&st[(dk0 + 2) * 32 + dp];
                u64 s3 = *(u64*)&st[(dk0 + 3) * 32 + dp];
                fma2(a0, pack2(q0.x, q0.x), s0); fma2(a1, pack2(q1.x, q1.x), s0);
                fma2(a0, pack2(q0.y, q0.y), s1); fma2(a1, pack2(q1.y, q1.y), s1);
                fma2(a0, pack2(q0.z, q0.z), s2); fma2(a1, pack2(q1.z, q1.z), s2);
                fma2(a0, pack2(q0.w, q0.w), s3); fma2(a1, pack2(q1.w, q1.w), s3);
            }
            for (int j = 0; j <= i0; j++) {
                u64 vn = *(u64*)&svn[j * 32 + dp];
                float sA0 = ssc[i0 * 64 + j];
                float sA1 = ssc[(i0 + 1) * 64 + j];
                fma2(a0, pack2(sA0, sA0), vn);
                fma2(a1, pack2(sA1, sA1), vn);
            }
            {
                int j = i0 + 1;
                float sA1 = ssc[j * 64 + j];
                fma2(a1, pack2(sA1, sA1), *(u64*)&svn[j * 32 + dp]);
            }
            float2 p0 = unpack2(a0), p1 = unpack2(a1);
            *(float2*)&d_o[rb + (size_t)i0 * 128 + dv0 + dp] = p0;
            *(float2*)&d_o[rb + (size_t)(i0 + 1) * 128 + dv0 + dp] = p1;
        }
        __syncthreads();

        {
            u64 a0 = pack2(st[(dk4    ) * 32 + dp] * egl, st[(dk4    ) * 32 + dp + 1] * egl);
            u64 a1 = pack2(st[(dk4 + 1) * 32 + dp] * egl, st[(dk4 + 1) * 32 + dp + 1] * egl);
            u64 a2 = pack2(st[(dk4 + 2) * 32 + dp] * egl, st[(dk4 + 2) * 32 + dp + 1] * egl);
            u64 a3 = pack2(st[(dk4 + 3) * 32 + dp] * egl, st[(dk4 + 3) * 32 + dp + 1] * egl);
            for (int i = 0; i < 64; i++) {
                u64 vn = *(u64*)&svn[i * 32 + dp];
                float4 kb = *(const float4*)&skb[i * 128 + dk4];
                fma2(a0, pack2(kb.x, kb.x), vn);
                fma2(a1, pack2(kb.y, kb.y), vn);
                fma2(a2, pack2(kb.z, kb.z), vn);
                fma2(a3, pack2(kb.w, kb.w), vn);
            }
            float2 p;
            p = unpack2(a0); st[(dk4    ) * 32 + dp] = p.x; st[(dk4    ) * 32 + dp + 1] = p.y;
            p = unpack2(a1); st[(dk4 + 1) * 32 + dp] = p.x; st[(dk4 + 1) * 32 + dp + 1] = p.y;
            p = unpack2(a2); st[(dk4 + 2) * 32 + dp] = p.x; st[(dk4 + 2) * 32 + dp + 1] = p.y;
            p = unpack2(a3); st[(dk4 + 3) * 32 + dp] = p.x; st[(dk4 + 3) * 32 + dp + 1] = p.y;
        }
        __syncthreads();
    }
}

// ---------------- RMSNorm + z-gate epilogue -> fp16 (hi only) ------------
__global__ void rms_kernel(const float* __restrict__ norm_w) {
    int b = blockIdx.x;
    int s = b >> 5, h = b & 31, t = threadIdx.x;
    float v = d_o[((size_t)h * SEQ + s) * 128 + t];
    float ss = v * v;
#pragma unroll
    for (int o = 16; o > 0; o >>= 1) ss += __shfl_xor_sync(~0u, ss, o);
    __shared__ float ws[4];
    if ((t & 31) == 0) ws[t >> 5] = ss;
    __syncthreads();
    ss = (ws[0] + ws[1]) + (ws[2] + ws[3]);
    float r = rsqrtf(ss * (1.f / 128.f) + 1e-6f);
    float z = d_z[(size_t)s * VALD + h * 128 + t];
    float sz = z / (1.f + expf(-z));
    float val = v * r * norm_w[t] * sz;
    g_yh[(size_t)s * VALD + h * 128 + t] = __float2half_rn(val);
}

// ---------------- launch ---------------------------------------------------
extern "C" void kernel_launch(void* const* d_in, const int* in_sizes, int n_in,
                              void* d_out, int out_size) {
    const float* x       = (const float*)d_in[0];
    const float* W_qkv   = (const float*)d_in[1];
    const float* W_z     = (const float*)d_in[2];
    const float* W_a     = (const float*)d_in[3];
    const float* W_b     = (const float*)d_in[4];
    const float* conv_w  = (const float*)d_in[5];
    const float* dt_bias = (const float*)d_in[6];
    const float* A_log   = (const float*)d_in[7];
    const float* norm_w  = (const float*)d_in[8];
    const float* W_out   = (const float*)d_in[9];
    float* out = (float*)d_out;

    void *p_mixed, *p_z, *p_ab;
    cudaGetSymbolAddress(&p_mixed, d_mixed);
    cudaGetSymbolAddress(&p_z, d_z);
    cudaGetSymbolAddress(&p_ab, d_ab);
    void *p_xh, *p_xl, *p_qkh, *p_wzh, *p_woh, *p_yh;
    cudaGetSymbolAddress(&p_xh, g_xh);   cudaGetSymbolAddress(&p_xl, g_xl);
    cudaGetSymbolAddress(&p_qkh, g_qkh);
    cudaGetSymbolAddress(&p_wzh, g_wzh);
    cudaGetSymbolAddress(&p_woh, g_woh);
    cudaGetSymbolAddress(&p_yh, g_yh);

    const int INTRA_SMEM = 21056 * 4;
    const int SCAN_SMEM  = 36864 * 4;
    const int GEMM_SMEM2 = 2 * 3 * TILE_B;   // 61440
    const int GEMM_SMEM1 = 2 * 2 * TILE_B;   // 40960
    cudaFuncSetAttribute(intra_kernel, cudaFuncAttributeMaxDynamicSharedMemorySize, INTRA_SMEM);
    cudaFuncSetAttribute(scan_kernel,  cudaFuncAttributeMaxDynamicSharedMemorySize, SCAN_SMEM);
    cudaFuncSetAttribute(tc_gemm<2>,   cudaFuncAttributeMaxDynamicSharedMemorySize, GEMM_SMEM2);
    cudaFuncSetAttribute(tc_gemm<1>,   cudaFuncAttributeMaxDynamicSharedMemorySize, GEMM_SMEM1);

    // launches 0-2: converts; launch index 3 = tc_gemm(qkv) -> profiled slot
    cvt_split<<<(SEQ * HIDN / 4 + 255) / 256, 256>>>(x, (__half*)p_xh, (__half*)p_xl, SEQ * HIDN / 4);
    cvt_h<<<(CDIM * HIDN / 4 + 255) / 256, 256>>>(W_qkv, (__half*)p_qkh, CDIM * HIDN / 4);
    cvt_h<<<(VALD * HIDN / 4 + 255) / 256, 256>>>(W_z, (__half*)p_wzh, VALD * HIDN / 4);

    tc_gemm<2><<<dim3(CDIM / 128, SEQ / 128), 256, GEMM_SMEM2>>>(
        (const __half*)p_xh, (const __half*)p_xl, (const __half*)p_qkh,
        (float*)p_mixed, CDIM, HIDN);
    tc_gemm<2><<<dim3(VALD / 128, SEQ / 128), 256, GEMM_SMEM2>>>(
        (const __half*)p_xh, (const __half*)p_xl, (const __half*)p_wzh,
        (float*)p_z, VALD, HIDN);

    cvt_h<<<(HIDN * VALD / 4 + 255) / 256, 256>>>(W_out, (__half*)p_woh, HIDN * VALD / 4);
    cudaMemsetAsync(p_ab, 0, SEQ * 64 * sizeof(float));
    ab_gemm<<<dim3(SEQ / 64, 8), 256>>>(x, W_a, W_b);

    // conv + silu + fused l2norm
    conv_silu<<<dim3(CDIM / 256, SEQ / 8), 256>>>(conv_w);

    // gates
    gate_kernel<<<dim3(NVH, NCH), 64>>>(dt_bias, A_log);

    // intra-chunk precompute
    intra_kernel<<<dim3(NCH, NVH), 256, INTRA_SMEM>>>();

    // sequential inter-chunk scan (32 heads x 4 DV-slices)
    scan_kernel<<<NVH * 4, 512, SCAN_SMEM>>>();

    // rmsnorm + gate epilogue -> fp16
    rms_kernel<<<SEQ * NVH, 128>>>(norm_w);

    // output projection (1-term fp16)
    tc_gemm<1><<<dim3(HIDN / 128, SEQ / 128), 256, GEMM_SMEM1>>>(
        (const __half*)p_yh, (const __half*)p_yh, (const __half*)p_woh,
        out, HIDN, VALD);
}

// round 16
// speedup vs baseline: 3.4669x; 1.1511x over previous
#include <cuda_runtime.h>
#include <cuda_fp16.h>
#include <math.h>

// ---------------- problem constants ----------------
#define SEQ   2048
#define HIDN  2048
#define NKH   16
#define NVH   32
#define DKD   128
#define DVD   128
#define CDIM  8192
#define VALD  4096
#define MZD   12288   // CDIM + VALD (fused qkv+z output width)
#define NCH   32      // chunks
#define CHK   64      // chunk size

typedef unsigned long long u64;
typedef unsigned int u32;

// single dynamic smem symbol shared by all kernels
extern __shared__ __align__(16) char dyn_smem[];

// ---------------- scratch (device globals; no cudaMalloc allowed) -------
__device__ float d_mz  [SEQ * MZD];        // [0:8192)=mixed, [8192:12288)=z
__device__ float d_ab  [SEQ * 64];
__device__ float d_q   [SEQ * 2048];
__device__ float d_k   [SEQ * 2048];
__device__ float d_v   [SEQ * VALD];
__device__ float d_g   [NVH * SEQ];
__device__ float d_beta[NVH * SEQ];
__device__ float d_egl [NVH * NCH];
__device__ float d_u   [NVH * SEQ * DVD];
__device__ float d_kcd [NVH * SEQ * DKD];
__device__ float d_qg  [NVH * SEQ * DKD];
__device__ float d_kbar[NVH * SEQ * DKD];
__device__ float d_sc  [NVH * NCH * CHK * CHK];
__device__ float d_o   [NVH * SEQ * DVD];

// fp16 buffers for tensor-core GEMMs
__device__ __half g_xh [SEQ * HIDN];
__device__ __half g_wh [MZD * HIDN];       // [0:8192) rows = W_qkv, rest = W_z
__device__ __half g_woh[HIDN * VALD];
__device__ __half g_yh [SEQ * VALD];

// ---------------- packed f32x2 helpers ----------------
__device__ __forceinline__ u64 pack2(float lo, float hi) {
    u64 r; asm("mov.b64 %0,{%1,%2};" : "=l"(r) : "f"(lo), "f"(hi)); return r;
}
__device__ __forceinline__ float2 unpack2(u64 v) {
    float2 r; asm("mov.b64 {%0,%1},%2;" : "=f"(r.x), "=f"(r.y) : "l"(v)); return r;
}
__device__ __forceinline__ void fma2(u64& d, u64 a, u64 b) {
    asm("fma.rn.f32x2 %0,%1,%2,%0;" : "+l"(d) : "l"(a), "l"(b));
}

// ---------------- fp32 -> fp16 hi-only convert ----------------
__global__ void __launch_bounds__(256) cvt_h(const float* __restrict__ s,
                                             __half* __restrict__ h, int n4) {
    int i = blockIdx.x * 256 + threadIdx.x;
    if (i >= n4) return;
    float4 v = ((const float4*)s)[i];
    __half2* hp = (__half2*)h;
    hp[2 * i]     = __half2(__float2half_rn(v.x), __float2half_rn(v.y));
    hp[2 * i + 1] = __half2(__float2half_rn(v.z), __float2half_rn(v.w));
}

// ---------------- warp-MMA fp16 GEMM: C[M,N] = A[M,K] @ B[N,K]^T --------
// 1-term: C = Ah*Bh, 2 tiles/stage, 2-stage cp.async pipeline, 2 CTAs/SM.
#define BKC   32
#define SROW  40
#define TILE_W (128 * SROW)
#define TILE_B (TILE_W * 2)                // 10240 bytes per tile
#define GEMM_SMEM (2 * 2 * TILE_B)         // 40960

__device__ __forceinline__ void mma_f16(float* c, const u32* a, const u32* b) {
    asm volatile(
        "mma.sync.aligned.m16n8k16.row.col.f32.f16.f16.f32 "
        "{%0,%1,%2,%3}, {%4,%5,%6,%7}, {%8,%9}, {%0,%1,%2,%3};"
        : "+f"(c[0]), "+f"(c[1]), "+f"(c[2]), "+f"(c[3])
        : "r"(a[0]), "r"(a[1]), "r"(a[2]), "r"(a[3]), "r"(b[0]), "r"(b[1]));
}

__device__ __forceinline__ void ldsm_x4(u32& r0, u32& r1, u32& r2, u32& r3, u32 addr) {
    asm volatile("ldmatrix.sync.aligned.m8n8.x4.shared.b16 {%0,%1,%2,%3}, [%4];"
                 : "=r"(r0), "=r"(r1), "=r"(r2), "=r"(r3) : "r"(addr));
}

__global__ void __launch_bounds__(256, 2)
tc_gemm(const __half* __restrict__ Ah, const __half* __restrict__ Bh,
        float* __restrict__ C, int N, int K) {
    constexpr u32 STG = 2 * TILE_B;

    __half* sm = (__half*)dyn_smem;

    const int t = threadIdx.x, lane = t & 31, wid = t >> 5;
    const int wm = wid & 3, wn = wid >> 2;
    const int bx = blockIdx.x, by = blockIdx.y;
    const int NCHUNK = K / BKC;

    u32 smem_base;
    asm("{ .reg .u64 tt; cvta.to.shared.u64 tt, %1; cvt.u32.u64 %0, tt; }"
        : "=r"(smem_base) : "l"(sm));

    const __half* srcs[2] = {Ah + (size_t)by * 128 * K, Bh + (size_t)bx * 128 * K};

    auto load_chunk = [&](int n, int s) {
        u32 sb = smem_base + (u32)s * STG;
#pragma unroll
        for (int tile = 0; tile < 2; tile++) {
#pragma unroll
            for (int j = 0; j < 2; j++) {
                int f = t + 256 * j;
                int row = f >> 2, c = f & 3;
                const __half* g = srcs[tile] + (size_t)row * K + n * BKC + c * 8;
                u32 d = sb + (u32)tile * TILE_B + (u32)(row * SROW + c * 8) * 2;
                asm volatile("cp.async.cg.shared.global [%0], [%1], 16;"
                             :: "r"(d), "l"(g));
            }
        }
        asm volatile("cp.async.commit_group;" ::: "memory");
    };

    float acc[2][8][4];
#pragma unroll
    for (int mt = 0; mt < 2; mt++)
#pragma unroll
        for (int nt = 0; nt < 8; nt++)
#pragma unroll
            for (int e = 0; e < 4; e++) acc[mt][nt][e] = 0.f;

    const int aRow = wm * 32 + (lane & 7) + ((lane >> 3) & 1) * 8;
    const u32 aOff = (u32)((aRow * SROW + (lane >> 4) * 8) * 2);
    const int bRow = wn * 64 + (lane & 7) + ((lane >> 4) & 1) * 8;
    const u32 bOff = (u32)((bRow * SROW + ((lane >> 3) & 1) * 8) * 2);

    load_chunk(0, 0);

    for (int n = 0; n < NCHUNK; n++) {
        int s = n & 1;
        asm volatile("cp.async.wait_group 0;" ::: "memory");
        __syncthreads();
        if (n + 1 < NCHUNK) load_chunk(n + 1, 1 - s);

        u32 sb = smem_base + (u32)s * STG;

#pragma unroll
        for (int k16 = 0; k16 < 2; k16++) {
            const u32 kb = (u32)(k16 * 16 * 2);
            u32 bh[8][2];
#pragma unroll
            for (int p = 0; p < 4; p++) {
                u32 base = sb + TILE_B + bOff + (u32)(p * 16 * SROW) * 2 + kb;
                ldsm_x4(bh[2 * p][0], bh[2 * p][1], bh[2 * p + 1][0], bh[2 * p + 1][1], base);
            }
#pragma unroll
            for (int mt = 0; mt < 2; mt++) {
                u32 ah[4];
                u32 base = sb + aOff + (u32)(mt * 16 * SROW) * 2 + kb;
                ldsm_x4(ah[0], ah[1], ah[2], ah[3], base);
#pragma unroll
                for (int nt = 0; nt < 8; nt++)
                    mma_f16(acc[mt][nt], ah, bh[nt]);
            }
        }
    }

    const int gid = lane >> 2, tig = lane & 3;
#pragma unroll
    for (int mt = 0; mt < 2; mt++) {
        int rbase = by * 128 + wm * 32 + mt * 16;
#pragma unroll
        for (int nt = 0; nt < 8; nt++) {
            int cbase = bx * 128 + wn * 64 + nt * 8 + tig * 2;
            float* p0 = C + (size_t)(rbase + gid) * N + cbase;
            float* p1 = C + (size_t)(rbase + gid + 8) * N + cbase;
            p0[0] = acc[mt][nt][0]; p0[1] = acc[mt][nt][1];
            p1[0] = acc[mt][nt][2]; p1[1] = acc[mt][nt][3];
        }
    }
}

// ---------------- a/b projection (K-split x8, atomicAdd) -----------------
__global__ void __launch_bounds__(256) ab_gemm(const float* __restrict__ x,
                                               const float* __restrict__ Wa,
                                               const float* __restrict__ Wb) {
    __shared__ float Xs[32][64];
    __shared__ float Ws[32][64];
    const int t = threadIdx.x;
    const int s0 = blockIdx.x * 64;
    const int kbase = blockIdx.y * 256;
    const int tx = t & 15, ty = t >> 4;
    float acc[4][4];
#pragma unroll
    for (int i = 0; i < 4; i++)
#pragma unroll
        for (int j = 0; j < 4; j++) acc[i][j] = 0.f;

    for (int k0 = kbase; k0 < kbase + 256; k0 += 32) {
        for (int e = t; e < 2048; e += 256) {
            int r = e >> 5, c = e & 31;
            Xs[c][r] = x[(size_t)(s0 + r) * HIDN + k0 + c];
            const float* Wrow = (r < 32) ? (Wa + (size_t)r * HIDN) : (Wb + (size_t)(r - 32) * HIDN);
            Ws[c][r] = Wrow[k0 + c];
        }
        __syncthreads();
#pragma unroll
        for (int kk = 0; kk < 32; kk++) {
            float a[4], b[4];
#pragma unroll
            for (int i = 0; i < 4; i++) { a[i] = Xs[kk][ty * 4 + i]; b[i] = Ws[kk][tx * 4 + i]; }
#pragma unroll
            for (int i = 0; i < 4; i++)
#pragma unroll
                for (int j = 0; j < 4; j++) acc[i][j] += a[i] * b[j];
        }
        __syncthreads();
    }
#pragma unroll
    for (int i = 0; i < 4; i++)
#pragma unroll
        for (int j = 0; j < 4; j++)
            atomicAdd(&d_ab[(size_t)(s0 + ty * 4 + i) * 64 + tx * 4 + j], acc[i][j]);
}

// ---------------- causal conv(K=4) + SiLU + fused l2norm -----------------
// Block = 256 channels x 8 seq (reads d_mz cols 0..8191, stride MZD).
__global__ void __launch_bounds__(256) conv_silu(const float* __restrict__ cw) {
    __shared__ float sr[8 * 256];
    __shared__ float sscale[16];
    int tc_ = threadIdx.x;
    int c  = blockIdx.x * 256 + tc_;
    int s0 = blockIdx.y * 8;
    float w0 = cw[c * 4], w1 = cw[c * 4 + 1], w2 = cw[c * 4 + 2], w3 = cw[c * 4 + 3];
    float xx[11];
#pragma unroll
    for (int j = 0; j < 11; j++) {
        int s = s0 - 3 + j;
        xx[j] = (s >= 0) ? d_mz[(size_t)s * MZD + c] : 0.f;
    }
    float r[8];
#pragma unroll
    for (int i = 0; i < 8; i++) {
        float a = w0 * xx[i] + w1 * xx[i + 1] + w2 * xx[i + 2] + w3 * xx[i + 3];
        r[i] = a / (1.f + expf(-a));
    }
    const bool isV = (blockIdx.x >= 16);
    if (!isV) {
#pragma unroll
        for (int i = 0; i < 8; i++) sr[i * 256 + tc_] = r[i] * r[i];
        __syncthreads();
        int g = tc_ >> 4, sub = tc_ & 15;
        {
            int i = g >> 1, hf = g & 1;
            float s = 0.f;
            for (int q_ = sub; q_ < 128; q_ += 16) s += sr[i * 256 + hf * 128 + q_];
#pragma unroll
            for (int o = 8; o > 0; o >>= 1) s += __shfl_down_sync(0xffffffffu, s, o, 16);
            if (sub == 0) {
                float sc = rsqrtf(s + 1e-6f);
                if (blockIdx.x < 8) sc *= 0.08838834764831845f;
                sscale[g] = sc;
            }
        }
        __syncthreads();
        int hf = tc_ >> 7;
#pragma unroll
        for (int i = 0; i < 8; i++) r[i] *= sscale[i * 2 + hf];
    }
#pragma unroll
    for (int i = 0; i < 8; i++) {
        int s = s0 + i;
        if (c < 2048)      d_q[(size_t)s * 2048 + c] = r[i];
        else if (c < 4096) d_k[(size_t)s * 2048 + (c - 2048)] = r[i];
        else               d_v[(size_t)s * 4096 + (c - 4096)] = r[i];
    }
}

// ---------------- gate ----------------------------------------------------
__global__ void gate_kernel(const float* __restrict__ dt_bias,
                            const float* __restrict__ A_log) {
    int h = blockIdx.x, n = blockIdx.y, i = threadIdx.x;
    int s = n * CHK + i;
    float a = d_ab[(size_t)s * 64 + h];
    float b = d_ab[(size_t)s * 64 + 32 + h];
    float xx = a + dt_bias[h];
    float sp = fmaxf(xx, 0.f) + log1pf(expf(-fabsf(xx)));
    float gv = -expf(A_log[h]) * sp;
    float beta = 1.f / (1.f + expf(-b));
    int lane = i & 31;
#pragma unroll
    for (int o = 1; o < 32; o <<= 1) {
        float nv = __shfl_up_sync(~0u, gv, o);
        if (lane >= o) gv += nv;
    }
    __shared__ float carry;
    if (i == 31) carry = gv;
    __syncthreads();
    if (i >= 32) gv += carry;
    d_g[(size_t)h * SEQ + s] = gv;
    d_beta[(size_t)h * SEQ + s] = beta;
    if (i == 63) d_egl[h * NCH + n] = expf(gv);
}

// ---------------- intra-chunk (84KB smem -> 2 blocks/SM) -----------------
__global__ void __launch_bounds__(256, 2) intra_kernel() {
    float* sm  = (float*)dyn_smem;
    float* sq  = sm;              // 64*128 (q, later v*beta)
    float* sk  = sm + 8192;       // 64*128 (k, later k*scv)
    float* sA  = sm + 16384;      // 64*64
    float* sg  = sm + 20480;      // 64
    float* sb  = sm + 20544;      // 64
    float* scv = sm + 20608;      // 64
    float* se  = sm + 20672;      // 64
    float* ser = sm + 20736;      // 64
    float* sP  = sm + 20800;      // 256

    const int n = blockIdx.x, h = blockIdx.y, kvh = h >> 1, t = threadIdx.x;
    const int sbase = n * CHK;

    for (int e = t; e < 2048; e += 256) {
        int i = e >> 5, d = (e & 31) << 2;
        int s = sbase + i;
        *(float4*)&sq[i * 128 + d] = *(const float4*)&d_q[((size_t)s * NKH + kvh) * 128 + d];
        *(float4*)&sk[i * 128 + d] = *(const float4*)&d_k[((size_t)s * NKH + kvh) * 128 + d];
    }
    if (t < 64) {
        sg[t] = d_g[(size_t)h * SEQ + sbase + t];
        sb[t] = d_beta[(size_t)h * SEQ + sbase + t];
    }
    __syncthreads();
    if (t < 64) {
        scv[t] = sb[t] * expf(sg[t]);
        se[t]  = expf(sg[t]);
        ser[t] = expf(sg[63] - sg[t]);
    }
    __syncthreads();

    for (int e = t; e < 2048; e += 256) {
        int i = e >> 5, d = (e & 31) << 2;
        size_t rb = ((size_t)h * SEQ + sbase + i) * 128 + d;
        float eg = se[i], er = ser[i];
        float4 qv = *(const float4*)&sq[i * 128 + d];
        float4 kv = *(const float4*)&sk[i * 128 + d];
        *(float4*)&d_qg[rb]   = make_float4(qv.x * eg, qv.y * eg, qv.z * eg, qv.w * eg);
        *(float4*)&d_kbar[rb] = make_float4(kv.x * er, kv.y * er, kv.z * er, kv.w * er);
    }

    const int i0 = (t >> 4) << 2, j0 = (t & 15) << 2;

    {
        float accA[4][4], accS[4][4];
#pragma unroll
        for (int ii = 0; ii < 4; ii++)
#pragma unroll
            for (int jj = 0; jj < 4; jj++) { accA[ii][jj] = 0.f; accS[ii][jj] = 0.f; }
        for (int kk = 0; kk < 128; kk += 4) {
            float4 ak[4], aq[4], bk[4];
#pragma unroll
            for (int ii = 0; ii < 4; ii++) {
                ak[ii] = *(const float4*)&sk[(i0 + ii) * 128 + kk];
                aq[ii] = *(const float4*)&sq[(i0 + ii) * 128 + kk];
                bk[ii] = *(const float4*)&sk[(j0 + ii) * 128 + kk];
            }
#pragma unroll
            for (int ii = 0; ii < 4; ii++)
#pragma unroll
                for (int jj = 0; jj < 4; jj++) {
                    accA[ii][jj] += ak[ii].x * bk[jj].x + ak[ii].y * bk[jj].y +
                                    ak[ii].z * bk[jj].z + ak[ii].w * bk[jj].w;
                    accS[ii][jj] += aq[ii].x * bk[jj].x + aq[ii].y * bk[jj].y +
                                    aq[ii].z * bk[jj].z + aq[ii].w * bk[jj].w;
                }
        }
        const size_t scb = ((size_t)h * NCH + n) * 4096;
#pragma unroll
        for (int ii = 0; ii < 4; ii++)
#pragma unroll
            for (int jj = 0; jj < 4; jj++) {
                int i = i0 + ii, j = j0 + jj;
                float dec = expf(sg[i] - sg[j]);
                sA[i * 64 + j]      = (i > j)  ? -sb[i] * accA[ii][jj] * dec : 0.f;
                d_sc[scb + i * 64 + j] = (i >= j) ? accS[ii][jj] * dec : 0.f;
            }
    }
    __syncthreads();

    {
        int j = t & 63, pt = t >> 6;
        for (int i = 1; i < 64; i++) {
            float p = 0.f;
            if (j < i)
                for (int kk = j + 1 + pt; kk < i; kk += 4)
                    p += sA[i * 64 + kk] * sA[kk * 64 + j];
            sP[t] = p;
            __syncthreads();
            if (t < i) sA[i * 64 + t] += sP[t] + sP[64 + t] + sP[128 + t] + sP[192 + t];
            __syncthreads();
        }
    }

    for (int e = t; e < 2048; e += 256) {
        int i = e >> 5, d = (e & 31) << 2;
        float4 vv = *(const float4*)&d_v[((size_t)(sbase + i) * NVH + h) * 128 + d];
        float b = sb[i];
        *(float4*)&sq[i * 128 + d] = make_float4(vv.x * b, vv.y * b, vv.z * b, vv.w * b);
    }
    __syncthreads();

    const int dv = t & 127, half = t >> 7;

    for (int ii = 0; ii < 32; ii++) {
        int i = half * 32 + ii;
        float a = sq[i * 128 + dv];
        for (int kk = 0; kk < i; kk++) a += sA[i * 64 + kk] * sq[kk * 128 + dv];
        d_u[((size_t)h * SEQ + sbase + i) * 128 + dv] = a;
    }
    __syncthreads();

    for (int e = t; e < 8192; e += 256) sk[e] *= scv[e >> 7];
    __syncthreads();

    for (int ii = 0; ii < 32; ii++) {
        int i = half * 32 + ii;
        float a = sk[i * 128 + dv];
        for (int kk = 0; kk < i; kk++) a += sA[i * 64 + kk] * sk[kk * 128 + dv];
        d_kcd[((size_t)h * SEQ + sbase + i) * 128 + dv] = a;
    }
}

// ---------------- sequential inter-chunk scan (register-blocked) ---------
__global__ void __launch_bounds__(512) scan_kernel() {
    float* sm = (float*)dyn_smem;
    float* st  = sm;           // 128*32 state slice
    float* skc = sm + 4096;    // 64*128 kcd (pre-negated)
    float* sqg = sm + 12288;   // 64*128 qg
    float* skb = sm + 20480;   // 64*128 kbar
    float* ssc = sm + 28672;   // 64*64 scores
    float* svn = sm + 32768;   // 64*32 v_new
    float* su  = sm + 34816;   // 64*32 u slice

    const int h = blockIdx.x >> 2, sl = blockIdx.x & 3, t = threadIdx.x;
    const int dv0 = sl * 32;
    const int i0 = (t >> 4) << 1;
    const int dp = (t & 15) << 1;
    const int dk4 = (t >> 4) << 2;

    for (int e = t; e < 4096; e += 512) st[e] = 0.f;

    for (int n = 0; n < NCH; n++) {
        const size_t rb = ((size_t)h * SEQ + n * CHK) * 128;
        for (int e = t; e < 2048; e += 512) {
            float4 kc = ((const float4*)(d_kcd + rb))[e];
            ((float4*)skc)[e] = make_float4(-kc.x, -kc.y, -kc.z, -kc.w);
            ((float4*)sqg)[e] = ((const float4*)(d_qg + rb))[e];
            ((float4*)skb)[e] = ((const float4*)(d_kbar + rb))[e];
        }
        const size_t scb = ((size_t)h * NCH + n) * 4096;
        for (int e = t; e < 1024; e += 512)
            ((float4*)ssc)[e] = ((const float4*)(d_sc + scb))[e];
        {
            int e = t;
            int i = e >> 3, q4 = e & 7;
            ((float4*)su)[e] = *(const float4*)&d_u[rb + (size_t)i * 128 + dv0 + q4 * 4];
        }
        __syncthreads();

        const float egl = d_egl[h * NCH + n];

        {
            u64 a0 = *(u64*)&su[i0 * 32 + dp];
            u64 a1 = *(u64*)&su[(i0 + 1) * 32 + dp];
            for (int dk0 = 0; dk0 < 128; dk0 += 4) {
                float4 k0 = *(const float4*)&skc[i0 * 128 + dk0];
                float4 k1 = *(const float4*)&skc[(i0 + 1) * 128 + dk0];
                u64 s0 = *(u64*)&st[(dk0    ) * 32 + dp];
                u64 s1 = *(u64*)&st[(dk0 + 1) * 32 + dp];
                u64 s2 = *(u64*)&st[(dk0 + 2) * 32 + dp];
                u64 s3 = *(u64*)&st[(dk0 + 3) * 32 + dp];
                fma2(a0, pack2(k0.x, k0.x), s0); fma2(a1, pack2(k1.x, k1.x), s0);
                fma2(a0, pack2(k0.y, k0.y), s1); fma2(a1, pack2(k1.y, k1.y), s1);
                fma2(a0, pack2(k0.z, k0.z), s2); fma2(a1, pack2(k1.z, k1.z), s2);
                fma2(a0, pack2(k0.w, k0.w), s3); fma2(a1, pack2(k1.w, k1.w), s3);
            }
            *(u64*)&svn[i0 * 32 + dp] = a0;
            *(u64*)&svn[(i0 + 1) * 32 + dp] = a1;
        }
        __syncthreads();

        {
            u64 a0 = 0ull, a1 = 0ull;
            for (int dk0 = 0; dk0 < 128; dk0 += 4) {
                float4 q0 = *(const float4*)&sqg[i0 * 128 + dk0];
                float4 q1 = *(const float4*)&sqg[(i0 + 1) * 128 + dk0];
                u64 s0 = *(u64*)&st[(dk0    ) * 32 + dp];
                u64 s1 = *(u64*)&st[(dk0 + 1) * 32 + dp];
                u64 s2 = *(u64*)&st[(dk0 + 2) * 32 + dp];
                u64 s3 = *(u64*)&st[(dk0 + 3) * 32 + dp];
                fma2(a0, pack2(q0.x, q0.x), s0); fma2(a1, pack2(q1.x, q1.x), s0);
                fma2(a0, pack2(q0.y, q0.y), s1); fma2(a1, pack2(q1.y, q1.y), s1);
                fma2(a0, pack2(q0.z, q0.z), s2); fma2(a1, pack2(q1.z, q1.z), s2);
                fma2(a0, pack2(q0.w, q0.w), s3); fma2(a1, pack2(q1.w, q1.w), s3);
            }
            for (int j = 0; j <= i0; j++) {
                u64 vn = *(u64*)&svn[j * 32 + dp];
                float sA0 = ssc[i0 * 64 + j];
                float sA1 = ssc[(i0 + 1) * 64 + j];
                fma2(a0, pack2(sA0, sA0), vn);
                fma2(a1, pack2(sA1, sA1), vn);
            }
            {
                int j = i0 + 1;
                float sA1 = ssc[j * 64 + j];
                fma2(a1, pack2(sA1, sA1), *(u64*)&svn[j * 32 + dp]);
            }
            float2 p0 = unpack2(a0), p1 = unpack2(a1);
            *(float2*)&d_o[rb + (size_t)i0 * 128 + dv0 + dp] = p0;
            *(float2*)&d_o[rb + (size_t)(i0 + 1) * 128 + dv0 + dp] = p1;
        }
        __syncthreads();

        {
            u64 a0 = pack2(st[(dk4    ) * 32 + dp] * egl, st[(dk4    ) * 32 + dp + 1] * egl);
            u64 a1 = pack2(st[(dk4 + 1) * 32 + dp] * egl, st[(dk4 + 1) * 32 + dp + 1] * egl);
            u64 a2 = pack2(st[(dk4 + 2) * 32 + dp] * egl, st[(dk4 + 2) * 32 + dp + 1] * egl);
            u64 a3 = pack2(st[(dk4 + 3) * 32 + dp] * egl, st[(dk4 + 3) * 32 + dp + 1] * egl);
            for (int i = 0; i < 64; i++) {
                u64 vn = *(u64*)&svn[i * 32 + dp];
                float4 kb = *(const float4*)&skb[i * 128 + dk4];
                fma2(a0, pack2(kb.x, kb.x), vn);
                fma2(a1, pack2(kb.y, kb.y), vn);
                fma2(a2, pack2(kb.z, kb.z), vn);
                fma2(a3, pack2(kb.w, kb.w), vn);
            }
            float2 p;
            p = unpack2(a0); st[(dk4    ) * 32 + dp] = p.x; st[(dk4    ) * 32 + dp + 1] = p.y;
            p = unpack2(a1); st[(dk4 + 1) * 32 + dp] = p.x; st[(dk4 + 1) * 32 + dp + 1] = p.y;
            p = unpack2(a2); st[(dk4 + 2) * 32 + dp] = p.x; st[(dk4 + 2) * 32 + dp + 1] = p.y;
            p = unpack2(a3); st[(dk4 + 3) * 32 + dp] = p.x; st[(dk4 + 3) * 32 + dp + 1] = p.y;
        }
        __syncthreads();
    }
}

// ---------------- RMSNorm + z-gate epilogue -> fp16 ----------------------
__global__ void rms_kernel(const float* __restrict__ norm_w) {
    int b = blockIdx.x;
    int s = b >> 5, h = b & 31, t = threadIdx.x;
    float v = d_o[((size_t)h * SEQ + s) * 128 + t];
    float ss = v * v;
#pragma unroll
    for (int o = 16; o > 0; o >>= 1) ss += __shfl_xor_sync(~0u, ss, o);
    __shared__ float ws[4];
    if ((t & 31) == 0) ws[t >> 5] = ss;
    __syncthreads();
    ss = (ws[0] + ws[1]) + (ws[2] + ws[3]);
    float r = rsqrtf(ss * (1.f / 128.f) + 1e-6f);
    float z = d_mz[(size_t)s * MZD + CDIM + h * 128 + t];
    float sz = z / (1.f + expf(-z));
    float val = v * r * norm_w[t] * sz;
    g_yh[(size_t)s * VALD + h * 128 + t] = __float2half_rn(val);
}

// ---------------- launch ---------------------------------------------------
extern "C" void kernel_launch(void* const* d_in, const int* in_sizes, int n_in,
                              void* d_out, int out_size) {
    const float* x       = (const float*)d_in[0];
    const float* W_qkv   = (const float*)d_in[1];
    const float* W_z     = (const float*)d_in[2];
    const float* W_a     = (const float*)d_in[3];
    const float* W_b     = (const float*)d_in[4];
    const float* conv_w  = (const float*)d_in[5];
    const float* dt_bias = (const float*)d_in[6];
    const float* A_log   = (const float*)d_in[7];
    const float* norm_w  = (const float*)d_in[8];
    const float* W_out   = (const float*)d_in[9];
    float* out = (float*)d_out;

    void *p_mz, *p_ab, *p_xh, *p_wh, *p_woh, *p_yh;
    cudaGetSymbolAddress(&p_mz, d_mz);
    cudaGetSymbolAddress(&p_ab, d_ab);
    cudaGetSymbolAddress(&p_xh, g_xh);
    cudaGetSymbolAddress(&p_wh, g_wh);
    cudaGetSymbolAddress(&p_woh, g_woh);
    cudaGetSymbolAddress(&p_yh, g_yh);

    const int INTRA_SMEM = 21056 * 4;
    const int SCAN_SMEM  = 36864 * 4;
    cudaFuncSetAttribute(intra_kernel, cudaFuncAttributeMaxDynamicSharedMemorySize, INTRA_SMEM);
    cudaFuncSetAttribute(scan_kernel,  cudaFuncAttributeMaxDynamicSharedMemorySize, SCAN_SMEM);
    cudaFuncSetAttribute(tc_gemm,      cudaFuncAttributeMaxDynamicSharedMemorySize, GEMM_SMEM);

    // launches 0-2: converts; launch index 3 = fused qkv+z GEMM -> profiled
    cvt_h<<<(SEQ * HIDN / 4 + 255) / 256, 256>>>(x, (__half*)p_xh, SEQ * HIDN / 4);
    cvt_h<<<(CDIM * HIDN / 4 + 255) / 256, 256>>>(W_qkv, (__half*)p_wh, CDIM * HIDN / 4);
    // NOTE: offset in __half ELEMENTS (bug fixed from previous round)
    cvt_h<<<(VALD * HIDN / 4 + 255) / 256, 256>>>(W_z, (__half*)p_wh + (size_t)CDIM * HIDN, VALD * HIDN / 4);

    // fused qkv+z projection (1-term fp16), N = 12288
    tc_gemm<<<dim3(MZD / 128, SEQ / 128), 256, GEMM_SMEM>>>(
        (const __half*)p_xh, (const __half*)p_wh, (float*)p_mz, MZD, HIDN);

    cvt_h<<<(HIDN * VALD / 4 + 255) / 256, 256>>>(W_out, (__half*)p_woh, HIDN * VALD / 4);
    cudaMemsetAsync(p_ab, 0, SEQ * 64 * sizeof(float));
    ab_gemm<<<dim3(SEQ / 64, 8), 256>>>(x, W_a, W_b);

    // conv + silu + fused l2norm
    conv_silu<<<dim3(CDIM / 256, SEQ / 8), 256>>>(conv_w);

    // gates
    gate_kernel<<<dim3(NVH, NCH), 64>>>(dt_bias, A_log);

    // intra-chunk precompute
    intra_kernel<<<dim3(NCH, NVH), 256, INTRA_SMEM>>>();

    // sequential inter-chunk scan (32 heads x 4 DV-slices)
    scan_kernel<<<NVH * 4, 512, SCAN_SMEM>>>();

    // rmsnorm + gate epilogue -> fp16
    rms_kernel<<<SEQ * NVH, 128>>>(norm_w);

    // output projection (1-term fp16)
    tc_gemm<<<dim3(HIDN / 128, SEQ / 128), 256, GEMM_SMEM>>>(
        (const __half*)p_yh, (const __half*)p_woh, out, HIDN, VALD);
}

// round 17
// speedup vs baseline: 3.5993x; 1.0382x over previous
#include <cuda_runtime.h>
#include <cuda_fp16.h>
#include <math.h>

// ---------------- problem constants ----------------
#define SEQ   2048
#define HIDN  2048
#define NKH   16
#define NVH   32
#define DKD   128
#define DVD   128
#define CDIM  8192
#define VALD  4096
#define MZD   12288   // CDIM + VALD (fused qkv+z output width)
#define NCH   32      // chunks
#define CHK   64      // chunk size

typedef unsigned long long u64;
typedef unsigned int u32;

// single dynamic smem symbol shared by all kernels
extern __shared__ __align__(16) char dyn_smem[];

// ---------------- scratch (device globals; no cudaMalloc allowed) -------
__device__ float d_mz  [SEQ * MZD];        // [0:8192)=mixed, [8192:12288)=z
__device__ float d_ab  [SEQ * 64];
__device__ float d_q   [SEQ * 2048];
__device__ float d_k   [SEQ * 2048];
__device__ float d_v   [SEQ * VALD];
__device__ float d_g   [NVH * SEQ];
__device__ float d_beta[NVH * SEQ];
__device__ float d_egl [NVH * NCH];
__device__ float d_u   [NVH * SEQ * DVD];
__device__ float d_kcd [NVH * SEQ * DKD];
__device__ float d_qg  [NVH * SEQ * DKD];
__device__ float d_kbar[NVH * SEQ * DKD];
__device__ float d_sc  [NVH * NCH * CHK * CHK];
__device__ float d_o   [NVH * SEQ * DVD];

// fp16 buffers for tensor-core GEMMs
__device__ __half g_xh [SEQ * HIDN];
__device__ __half g_wh [MZD * HIDN];       // [0:8192) rows = W_qkv, rest = W_z
__device__ __half g_woh[HIDN * VALD];
__device__ __half g_yh [SEQ * VALD];

// ---------------- packed f32x2 helpers ----------------
__device__ __forceinline__ u64 pack2(float lo, float hi) {
    u64 r; asm("mov.b64 %0,{%1,%2};" : "=l"(r) : "f"(lo), "f"(hi)); return r;
}
__device__ __forceinline__ float2 unpack2(u64 v) {
    float2 r; asm("mov.b64 {%0,%1},%2;" : "=f"(r.x), "=f"(r.y) : "l"(v)); return r;
}
__device__ __forceinline__ void fma2(u64& d, u64 a, u64 b) {
    asm("fma.rn.f32x2 %0,%1,%2,%0;" : "+l"(d) : "l"(a), "l"(b));
}

// ---------------- fp32 -> fp16 hi-only convert ----------------
__global__ void __launch_bounds__(256) cvt_h(const float* __restrict__ s,
                                             __half* __restrict__ h, int n4) {
    int i = blockIdx.x * 256 + threadIdx.x;
    if (i >= n4) return;
    float4 v = ((const float4*)s)[i];
    __half2* hp = (__half2*)h;
    hp[2 * i]     = __half2(__float2half_rn(v.x), __float2half_rn(v.y));
    hp[2 * i + 1] = __half2(__float2half_rn(v.z), __float2half_rn(v.w));
}

// ---------------- warp-MMA fp16 GEMM: C[M,N] = A[M,K] @ B[N,K]^T --------
// 1-term: C = Ah*Bh, 2 tiles/stage, 4-stage cp.async pipeline, 2 CTAs/SM.
#define BKC   32
#define SROW  40
#define TILE_W (128 * SROW)
#define TILE_B (TILE_W * 2)                // 10240 bytes per tile
#define NSTG  4
#define GEMM_SMEM (NSTG * 2 * TILE_B)      // 81920

__device__ __forceinline__ void mma_f16(float* c, const u32* a, const u32* b) {
    asm volatile(
        "mma.sync.aligned.m16n8k16.row.col.f32.f16.f16.f32 "
        "{%0,%1,%2,%3}, {%4,%5,%6,%7}, {%8,%9}, {%0,%1,%2,%3};"
        : "+f"(c[0]), "+f"(c[1]), "+f"(c[2]), "+f"(c[3])
        : "r"(a[0]), "r"(a[1]), "r"(a[2]), "r"(a[3]), "r"(b[0]), "r"(b[1]));
}

__device__ __forceinline__ void ldsm_x4(u32& r0, u32& r1, u32& r2, u32& r3, u32 addr) {
    asm volatile("ldmatrix.sync.aligned.m8n8.x4.shared.b16 {%0,%1,%2,%3}, [%4];"
                 : "=r"(r0), "=r"(r1), "=r"(r2), "=r"(r3) : "r"(addr));
}

__global__ void __launch_bounds__(256, 2)
tc_gemm(const __half* __restrict__ Ah, const __half* __restrict__ Bh,
        float* __restrict__ C, int N, int K) {
    constexpr u32 STG = 2 * TILE_B;

    __half* sm = (__half*)dyn_smem;

    const int t = threadIdx.x, lane = t & 31, wid = t >> 5;
    const int wm = wid & 3, wn = wid >> 2;
    const int bx = blockIdx.x, by = blockIdx.y;
    const int NCHUNK = K / BKC;

    u32 smem_base;
    asm("{ .reg .u64 tt; cvta.to.shared.u64 tt, %1; cvt.u32.u64 %0, tt; }"
        : "=r"(smem_base) : "l"(sm));

    const __half* srcs[2] = {Ah + (size_t)by * 128 * K, Bh + (size_t)bx * 128 * K};

    auto load_chunk = [&](int n, int s) {
        u32 sb = smem_base + (u32)s * STG;
#pragma unroll
        for (int tile = 0; tile < 2; tile++) {
#pragma unroll
            for (int j = 0; j < 2; j++) {
                int f = t + 256 * j;
                int row = f >> 2, c = f & 3;
                const __half* g = srcs[tile] + (size_t)row * K + n * BKC + c * 8;
                u32 d = sb + (u32)tile * TILE_B + (u32)(row * SROW + c * 8) * 2;
                asm volatile("cp.async.cg.shared.global [%0], [%1], 16;"
                             :: "r"(d), "l"(g));
            }
        }
        asm volatile("cp.async.commit_group;" ::: "memory");
    };

    float acc[2][8][4];
#pragma unroll
    for (int mt = 0; mt < 2; mt++)
#pragma unroll
        for (int nt = 0; nt < 8; nt++)
#pragma unroll
            for (int e = 0; e < 4; e++) acc[mt][nt][e] = 0.f;

    const int aRow = wm * 32 + (lane & 7) + ((lane >> 3) & 1) * 8;
    const u32 aOff = (u32)((aRow * SROW + (lane >> 4) * 8) * 2);
    const int bRow = wn * 64 + (lane & 7) + ((lane >> 4) & 1) * 8;
    const u32 bOff = (u32)((bRow * SROW + ((lane >> 3) & 1) * 8) * 2);

    load_chunk(0, 0);
    load_chunk(1, 1);
    load_chunk(2, 2);

    for (int n = 0; n < NCHUNK; n++) {
        int s = n & 3;
        asm volatile("cp.async.wait_group 2;" ::: "memory");
        __syncthreads();
        if (n + 3 < NCHUNK) load_chunk(n + 3, (n + 3) & 3);

        u32 sb = smem_base + (u32)s * STG;

#pragma unroll
        for (int k16 = 0; k16 < 2; k16++) {
            const u32 kb = (u32)(k16 * 16 * 2);
            u32 bh[8][2];
#pragma unroll
            for (int p = 0; p < 4; p++) {
                u32 base = sb + TILE_B + bOff + (u32)(p * 16 * SROW) * 2 + kb;
                ldsm_x4(bh[2 * p][0], bh[2 * p][1], bh[2 * p + 1][0], bh[2 * p + 1][1], base);
            }
#pragma unroll
            for (int mt = 0; mt < 2; mt++) {
                u32 ah[4];
                u32 base = sb + aOff + (u32)(mt * 16 * SROW) * 2 + kb;
                ldsm_x4(ah[0], ah[1], ah[2], ah[3], base);
#pragma unroll
                for (int nt = 0; nt < 8; nt++)
                    mma_f16(acc[mt][nt], ah, bh[nt]);
            }
        }
    }

    const int gid = lane >> 2, tig = lane & 3;
#pragma unroll
    for (int mt = 0; mt < 2; mt++) {
        int rbase = by * 128 + wm * 32 + mt * 16;
#pragma unroll
        for (int nt = 0; nt < 8; nt++) {
            int cbase = bx * 128 + wn * 64 + nt * 8 + tig * 2;
            float* p0 = C + (size_t)(rbase + gid) * N + cbase;
            float* p1 = C + (size_t)(rbase + gid + 8) * N + cbase;
            p0[0] = acc[mt][nt][0]; p0[1] = acc[mt][nt][1];
            p1[0] = acc[mt][nt][2]; p1[1] = acc[mt][nt][3];
        }
    }
}

// ---------------- a/b projection (K-split x8, atomicAdd) -----------------
__global__ void __launch_bounds__(256) ab_gemm(const float* __restrict__ x,
                                               const float* __restrict__ Wa,
                                               const float* __restrict__ Wb) {
    __shared__ float Xs[32][64];
    __shared__ float Ws[32][64];
    const int t = threadIdx.x;
    const int s0 = blockIdx.x * 64;
    const int kbase = blockIdx.y * 256;
    const int tx = t & 15, ty = t >> 4;
    float acc[4][4];
#pragma unroll
    for (int i = 0; i < 4; i++)
#pragma unroll
        for (int j = 0; j < 4; j++) acc[i][j] = 0.f;

    for (int k0 = kbase; k0 < kbase + 256; k0 += 32) {
        for (int e = t; e < 2048; e += 256) {
            int r = e >> 5, c = e & 31;
            Xs[c][r] = x[(size_t)(s0 + r) * HIDN + k0 + c];
            const float* Wrow = (r < 32) ? (Wa + (size_t)r * HIDN) : (Wb + (size_t)(r - 32) * HIDN);
            Ws[c][r] = Wrow[k0 + c];
        }
        __syncthreads();
#pragma unroll
        for (int kk = 0; kk < 32; kk++) {
            float a[4], b[4];
#pragma unroll
            for (int i = 0; i < 4; i++) { a[i] = Xs[kk][ty * 4 + i]; b[i] = Ws[kk][tx * 4 + i]; }
#pragma unroll
            for (int i = 0; i < 4; i++)
#pragma unroll
                for (int j = 0; j < 4; j++) acc[i][j] += a[i] * b[j];
        }
        __syncthreads();
    }
#pragma unroll
    for (int i = 0; i < 4; i++)
#pragma unroll
        for (int j = 0; j < 4; j++)
            atomicAdd(&d_ab[(size_t)(s0 + ty * 4 + i) * 64 + tx * 4 + j], acc[i][j]);
}

// ---------------- causal conv(K=4) + SiLU + fused l2norm -----------------
__global__ void __launch_bounds__(256) conv_silu(const float* __restrict__ cw) {
    __shared__ float sr[8 * 256];
    __shared__ float sscale[16];
    int tc_ = threadIdx.x;
    int c  = blockIdx.x * 256 + tc_;
    int s0 = blockIdx.y * 8;
    float w0 = cw[c * 4], w1 = cw[c * 4 + 1], w2 = cw[c * 4 + 2], w3 = cw[c * 4 + 3];
    float xx[11];
#pragma unroll
    for (int j = 0; j < 11; j++) {
        int s = s0 - 3 + j;
        xx[j] = (s >= 0) ? d_mz[(size_t)s * MZD + c] : 0.f;
    }
    float r[8];
#pragma unroll
    for (int i = 0; i < 8; i++) {
        float a = w0 * xx[i] + w1 * xx[i + 1] + w2 * xx[i + 2] + w3 * xx[i + 3];
        r[i] = a / (1.f + expf(-a));
    }
    const bool isV = (blockIdx.x >= 16);
    if (!isV) {
#pragma unroll
        for (int i = 0; i < 8; i++) sr[i * 256 + tc_] = r[i] * r[i];
        __syncthreads();
        int g = tc_ >> 4, sub = tc_ & 15;
        {
            int i = g >> 1, hf = g & 1;
            float s = 0.f;
            for (int q_ = sub; q_ < 128; q_ += 16) s += sr[i * 256 + hf * 128 + q_];
#pragma unroll
            for (int o = 8; o > 0; o >>= 1) s += __shfl_down_sync(0xffffffffu, s, o, 16);
            if (sub == 0) {
                float sc = rsqrtf(s + 1e-6f);
                if (blockIdx.x < 8) sc *= 0.08838834764831845f;
                sscale[g] = sc;
            }
        }
        __syncthreads();
        int hf = tc_ >> 7;
#pragma unroll
        for (int i = 0; i < 8; i++) r[i] *= sscale[i * 2 + hf];
    }
#pragma unroll
    for (int i = 0; i < 8; i++) {
        int s = s0 + i;
        if (c < 2048)      d_q[(size_t)s * 2048 + c] = r[i];
        else if (c < 4096) d_k[(size_t)s * 2048 + (c - 2048)] = r[i];
        else               d_v[(size_t)s * 4096 + (c - 4096)] = r[i];
    }
}

// ---------------- gate ----------------------------------------------------
__global__ void gate_kernel(const float* __restrict__ dt_bias,
                            const float* __restrict__ A_log) {
    int h = blockIdx.x, n = blockIdx.y, i = threadIdx.x;
    int s = n * CHK + i;
    float a = d_ab[(size_t)s * 64 + h];
    float b = d_ab[(size_t)s * 64 + 32 + h];
    float xx = a + dt_bias[h];
    float sp = fmaxf(xx, 0.f) + log1pf(expf(-fabsf(xx)));
    float gv = -expf(A_log[h]) * sp;
    float beta = 1.f / (1.f + expf(-b));
    int lane = i & 31;
#pragma unroll
    for (int o = 1; o < 32; o <<= 1) {
        float nv = __shfl_up_sync(~0u, gv, o);
        if (lane >= o) gv += nv;
    }
    __shared__ float carry;
    if (i == 31) carry = gv;
    __syncthreads();
    if (i >= 32) gv += carry;
    d_g[(size_t)h * SEQ + s] = gv;
    d_beta[(size_t)h * SEQ + s] = beta;
    if (i == 63) d_egl[h * NCH + n] = expf(gv);
}

// ---------------- intra-chunk (84KB smem -> 2 blocks/SM) -----------------
__global__ void __launch_bounds__(256, 2) intra_kernel() {
    float* sm  = (float*)dyn_smem;
    float* sq  = sm;              // 64*128 (q, later v*beta)
    float* sk  = sm + 8192;       // 64*128 (k, later k*scv)
    float* sA  = sm + 16384;      // 64*64
    float* sg  = sm + 20480;      // 64
    float* sb  = sm + 20544;      // 64
    float* scv = sm + 20608;      // 64
    float* se  = sm + 20672;      // 64
    float* ser = sm + 20736;      // 64
    float* sP  = sm + 20800;      // 256

    const int n = blockIdx.x, h = blockIdx.y, kvh = h >> 1, t = threadIdx.x;
    const int sbase = n * CHK;

    for (int e = t; e < 2048; e += 256) {
        int i = e >> 5, d = (e & 31) << 2;
        int s = sbase + i;
        *(float4*)&sq[i * 128 + d] = *(const float4*)&d_q[((size_t)s * NKH + kvh) * 128 + d];
        *(float4*)&sk[i * 128 + d] = *(const float4*)&d_k[((size_t)s * NKH + kvh) * 128 + d];
    }
    if (t < 64) {
        sg[t] = d_g[(size_t)h * SEQ + sbase + t];
        sb[t] = d_beta[(size_t)h * SEQ + sbase + t];
    }
    __syncthreads();
    if (t < 64) {
        scv[t] = sb[t] * expf(sg[t]);
        se[t]  = expf(sg[t]);
        ser[t] = expf(sg[63] - sg[t]);
    }
    __syncthreads();

    for (int e = t; e < 2048; e += 256) {
        int i = e >> 5, d = (e & 31) << 2;
        size_t rb = ((size_t)h * SEQ + sbase + i) * 128 + d;
        float eg = se[i], er = ser[i];
        float4 qv = *(const float4*)&sq[i * 128 + d];
        float4 kv = *(const float4*)&sk[i * 128 + d];
        *(float4*)&d_qg[rb]   = make_float4(qv.x * eg, qv.y * eg, qv.z * eg, qv.w * eg);
        *(float4*)&d_kbar[rb] = make_float4(kv.x * er, kv.y * er, kv.z * er, kv.w * er);
    }

    const int i0 = (t >> 4) << 2, j0 = (t & 15) << 2;

    {
        float accA[4][4], accS[4][4];
#pragma unroll
        for (int ii = 0; ii < 4; ii++)
#pragma unroll
            for (int jj = 0; jj < 4; jj++) { accA[ii][jj] = 0.f; accS[ii][jj] = 0.f; }
        for (int kk = 0; kk < 128; kk += 4) {
            float4 ak[4], aq[4], bk[4];
#pragma unroll
            for (int ii = 0; ii < 4; ii++) {
                ak[ii] = *(const float4*)&sk[(i0 + ii) * 128 + kk];
                aq[ii] = *(const float4*)&sq[(i0 + ii) * 128 + kk];
                bk[ii] = *(const float4*)&sk[(j0 + ii) * 128 + kk];
            }
#pragma unroll
            for (int ii = 0; ii < 4; ii++)
#pragma unroll
                for (int jj = 0; jj < 4; jj++) {
                    accA[ii][jj] += ak[ii].x * bk[jj].x + ak[ii].y * bk[jj].y +
                                    ak[ii].z * bk[jj].z + ak[ii].w * bk[jj].w;
                    accS[ii][jj] += aq[ii].x * bk[jj].x + aq[ii].y * bk[jj].y +
                                    aq[ii].z * bk[jj].z + aq[ii].w * bk[jj].w;
                }
        }
        const size_t scb = ((size_t)h * NCH + n) * 4096;
#pragma unroll
        for (int ii = 0; ii < 4; ii++)
#pragma unroll
            for (int jj = 0; jj < 4; jj++) {
                int i = i0 + ii, j = j0 + jj;
                float dec = expf(sg[i] - sg[j]);
                sA[i * 64 + j]      = (i > j)  ? -sb[i] * accA[ii][jj] * dec : 0.f;
                d_sc[scb + i * 64 + j] = (i >= j) ? accS[ii][jj] * dec : 0.f;
            }
    }
    __syncthreads();

    {
        int j = t & 63, pt = t >> 6;
        for (int i = 1; i < 64; i++) {
            float p = 0.f;
            if (j < i)
                for (int kk = j + 1 + pt; kk < i; kk += 4)
                    p += sA[i * 64 + kk] * sA[kk * 64 + j];
            sP[t] = p;
            __syncthreads();
            if (t < i) sA[i * 64 + t] += sP[t] + sP[64 + t] + sP[128 + t] + sP[192 + t];
            __syncthreads();
        }
    }

    // ---- prepare operands: sq <- v*beta, sk <- k*beta*e^g ----
    for (int e = t; e < 2048; e += 256) {
        int i = e >> 5, d = (e & 31) << 2;
        float4 vv = *(const float4*)&d_v[((size_t)(sbase + i) * NVH + h) * 128 + d];
        float b = sb[i];
        *(float4*)&sq[i * 128 + d] = make_float4(vv.x * b, vv.y * b, vv.z * b, vv.w * b);
    }
    for (int e = t; e < 8192; e += 256) sk[e] *= scv[e >> 7];
    __syncthreads();

    // ---- merged u = (I+A)@vb and kcd = (I+A)@(k*beta*e^g), f32x2-packed --
    {
        const int dp2 = (t & 63) << 1;     // dv pair 0..126
        const int rg  = t >> 6;            // 0..3 (interleaved rows)
        for (int ii = 0; ii < 16; ii++) {
            int i = ii * 4 + rg;
            u64 au = *(u64*)&sq[i * 128 + dp2];
            u64 ak = *(u64*)&sk[i * 128 + dp2];
            for (int kk = 0; kk < i; kk++) {
                float a = sA[i * 64 + kk];
                u64 ap = pack2(a, a);
                fma2(au, ap, *(u64*)&sq[kk * 128 + dp2]);
                fma2(ak, ap, *(u64*)&sk[kk * 128 + dp2]);
            }
            size_t rb = ((size_t)h * SEQ + sbase + i) * 128 + dp2;
            float2 pu = unpack2(au), pk = unpack2(ak);
            *(float2*)&d_u[rb]   = pu;
            *(float2*)&d_kcd[rb] = pk;
        }
    }
}

// ---------------- sequential inter-chunk scan (register-blocked) ---------
__global__ void __launch_bounds__(512) scan_kernel() {
    float* sm = (float*)dyn_smem;
    float* st  = sm;           // 128*32 state slice
    float* skc = sm + 4096;    // 64*128 kcd (pre-negated)
    float* sqg = sm + 12288;   // 64*128 qg
    float* skb = sm + 20480;   // 64*128 kbar
    float* ssc = sm + 28672;   // 64*64 scores
    float* svn = sm + 32768;   // 64*32 v_new
    float* su  = sm + 34816;   // 64*32 u slice

    const int h = blockIdx.x >> 2, sl = blockIdx.x & 3, t = threadIdx.x;
    const int dv0 = sl * 32;
    const int i0 = (t >> 4) << 1;
    const int dp = (t & 15) << 1;
    const int dk4 = (t >> 4) << 2;

    for (int e = t; e < 4096; e += 512) st[e] = 0.f;

    for (int n = 0; n < NCH; n++) {
        const size_t rb = ((size_t)h * SEQ + n * CHK) * 128;
        for (int e = t; e < 2048; e += 512) {
            float4 kc = ((const float4*)(d_kcd + rb))[e];
            ((float4*)skc)[e] = make_float4(-kc.x, -kc.y, -kc.z, -kc.w);
            ((float4*)sqg)[e] = ((const float4*)(d_qg + rb))[e];
            ((float4*)skb)[e] = ((const float4*)(d_kbar + rb))[e];
        }
        const size_t scb = ((size_t)h * NCH + n) * 4096;
        for (int e = t; e < 1024; e += 512)
            ((float4*)ssc)[e] = ((const float4*)(d_sc + scb))[e];
        {
            int e = t;
            int i = e >> 3, q4 = e & 7;
            ((float4*)su)[e] = *(const float4*)&d_u[rb + (size_t)i * 128 + dv0 + q4 * 4];
        }
        __syncthreads();

        const float egl = d_egl[h * NCH + n];

        {
            u64 a0 = *(u64*)&su[i0 * 32 + dp];
            u64 a1 = *(u64*)&su[(i0 + 1) * 32 + dp];
            for (int dk0 = 0; dk0 < 128; dk0 += 4) {
                float4 k0 = *(const float4*)&skc[i0 * 128 + dk0];
                float4 k1 = *(const float4*)&skc[(i0 + 1) * 128 + dk0];
                u64 s0 = *(u64*)&st[(dk0    ) * 32 + dp];
                u64 s1 = *(u64*)&st[(dk0 + 1) * 32 + dp];
                u64 s2 = *(u64*)&st[(dk0 + 2) * 32 + dp];
                u64 s3 = *(u64*)&st[(dk0 + 3) * 32 + dp];
                fma2(a0, pack2(k0.x, k0.x), s0); fma2(a1, pack2(k1.x, k1.x), s0);
                fma2(a0, pack2(k0.y, k0.y), s1); fma2(a1, pack2(k1.y, k1.y), s1);
                fma2(a0, pack2(k0.z, k0.z), s2); fma2(a1, pack2(k1.z, k1.z), s2);
                fma2(a0, pack2(k0.w, k0.w), s3); fma2(a1, pack2(k1.w, k1.w), s3);
            }
            *(u64*)&svn[i0 * 32 + dp] = a0;
            *(u64*)&svn[(i0 + 1) * 32 + dp] = a1;
        }
        __syncthreads();

        {
            u64 a0 = 0ull, a1 = 0ull;
            for (int dk0 = 0; dk0 < 128; dk0 += 4) {
                float4 q0 = *(const float4*)&sqg[i0 * 128 + dk0];
                float4 q1 = *(const float4*)&sqg[(i0 + 1) * 128 + dk0];
                u64 s0 = *(u64*)&st[(dk0    ) * 32 + dp];
                u64 s1 = *(u64*)&st[(dk0 + 1) * 32 + dp];
                u64 s2 = *(u64*)&st[(dk0 + 2) * 32 + dp];
                u64 s3 = *(u64*)&st[(dk0 + 3) * 32 + dp];
                fma2(a0, pack2(q0.x, q0.x), s0); fma2(a1, pack2(q1.x, q1.x), s0);
                fma2(a0, pack2(q0.y, q0.y), s1); fma2(a1, pack2(q1.y, q1.y), s1);
                fma2(a0, pack2(q0.z, q0.z), s2); fma2(a1, pack2(q1.z, q1.z), s2);
                fma2(a0, pack2(q0.w, q0.w), s3); fma2(a1, pack2(q1.w, q1.w), s3);
            }
            for (int j = 0; j <= i0; j++) {
                u64 vn = *(u64*)&svn[j * 32 + dp];
                float sA0 = ssc[i0 * 64 + j];
                float sA1 = ssc[(i0 + 1) * 64 + j];
                fma2(a0, pack2(sA0, sA0), vn);
                fma2(a1, pack2(sA1, sA1), vn);
            }
            {
                int j = i0 + 1;
                float sA1 = ssc[j * 64 + j];
                fma2(a1, pack2(sA1, sA1), *(u64*)&svn[j * 32 + dp]);
            }
            float2 p0 = unpack2(a0), p1 = unpack2(a1);
            *(float2*)&d_o[rb + (size_t)i0 * 128 + dv0 + dp] = p0;
            *(float2*)&d_o[rb + (size_t)(i0 + 1) * 128 + dv0 + dp] = p1;
        }
        __syncthreads();

        {
            u64 a0 = pack2(st[(dk4    ) * 32 + dp] * egl, st[(dk4    ) * 32 + dp + 1] * egl);
            u64 a1 = pack2(st[(dk4 + 1) * 32 + dp] * egl, st[(dk4 + 1) * 32 + dp + 1] * egl);
            u64 a2 = pack2(st[(dk4 + 2) * 32 + dp] * egl, st[(dk4 + 2) * 32 + dp + 1] * egl);
            u64 a3 = pack2(st[(dk4 + 3) * 32 + dp] * egl, st[(dk4 + 3) * 32 + dp + 1] * egl);
            for (int i = 0; i < 64; i++) {
                u64 vn = *(u64*)&svn[i * 32 + dp];
                float4 kb = *(const float4*)&skb[i * 128 + dk4];
                fma2(a0, pack2(kb.x, kb.x), vn);
                fma2(a1, pack2(kb.y, kb.y), vn);
                fma2(a2, pack2(kb.z, kb.z), vn);
                fma2(a3, pack2(kb.w, kb.w), vn);
            }
            float2 p;
            p = unpack2(a0); st[(dk4    ) * 32 + dp] = p.x; st[(dk4    ) * 32 + dp + 1] = p.y;
            p = unpack2(a1); st[(dk4 + 1) * 32 + dp] = p.x; st[(dk4 + 1) * 32 + dp + 1] = p.y;
            p = unpack2(a2); st[(dk4 + 2) * 32 + dp] = p.x; st[(dk4 + 2) * 32 + dp + 1] = p.y;
            p = unpack2(a3); st[(dk4 + 3) * 32 + dp] = p.x; st[(dk4 + 3) * 32 + dp + 1] = p.y;
        }
        __syncthreads();
    }
}

// ---------------- RMSNorm + z-gate epilogue -> fp16 ----------------------
__global__ void rms_kernel(const float* __restrict__ norm_w) {
    int b = blockIdx.x;
    int s = b >> 5, h = b & 31, t = threadIdx.x;
    float v = d_o[((size_t)h * SEQ + s) * 128 + t];
    float ss = v * v;
#pragma unroll
    for (int o = 16; o > 0; o >>= 1) ss += __shfl_xor_sync(~0u, ss, o);
    __shared__ float ws[4];
    if ((t & 31) == 0) ws[t >> 5] = ss;
    __syncthreads();
    ss = (ws[0] + ws[1]) + (ws[2] + ws[3]);
    float r = rsqrtf(ss * (1.f / 128.f) + 1e-6f);
    float z = d_mz[(size_t)s * MZD + CDIM + h * 128 + t];
    float sz = z / (1.f + expf(-z));
    float val = v * r * norm_w[t] * sz;
    g_yh[(size_t)s * VALD + h * 128 + t] = __float2half_rn(val);
}

// ---------------- launch ---------------------------------------------------
extern "C" void kernel_launch(void* const* d_in, const int* in_sizes, int n_in,
                              void* d_out, int out_size) {
    const float* x       = (const float*)d_in[0];
    const float* W_qkv   = (const float*)d_in[1];
    const float* W_z     = (const float*)d_in[2];
    const float* W_a     = (const float*)d_in[3];
    const float* W_b     = (const float*)d_in[4];
    const float* conv_w  = (const float*)d_in[5];
    const float* dt_bias = (const float*)d_in[6];
    const float* A_log   = (const float*)d_in[7];
    const float* norm_w  = (const float*)d_in[8];
    const float* W_out   = (const float*)d_in[9];
    float* out = (float*)d_out;

    void *p_mz, *p_ab, *p_xh, *p_wh, *p_woh, *p_yh;
    cudaGetSymbolAddress(&p_mz, d_mz);
    cudaGetSymbolAddress(&p_ab, d_ab);
    cudaGetSymbolAddress(&p_xh, g_xh);
    cudaGetSymbolAddress(&p_wh, g_wh);
    cudaGetSymbolAddress(&p_woh, g_woh);
    cudaGetSymbolAddress(&p_yh, g_yh);

    const int INTRA_SMEM = 21056 * 4;
    const int SCAN_SMEM  = 36864 * 4;
    cudaFuncSetAttribute(intra_kernel, cudaFuncAttributeMaxDynamicSharedMemorySize, INTRA_SMEM);
    cudaFuncSetAttribute(scan_kernel,  cudaFuncAttributeMaxDynamicSharedMemorySize, SCAN_SMEM);
    cudaFuncSetAttribute(tc_gemm,      cudaFuncAttributeMaxDynamicSharedMemorySize, GEMM_SMEM);

    // launches 0-2: converts; launch index 3 = fused qkv+z GEMM -> profiled
    cvt_h<<<(SEQ * HIDN / 4 + 255) / 256, 256>>>(x, (__half*)p_xh, SEQ * HIDN / 4);
    cvt_h<<<(CDIM * HIDN / 4 + 255) / 256, 256>>>(W_qkv, (__half*)p_wh, CDIM * HIDN / 4);
    cvt_h<<<(VALD * HIDN / 4 + 255) / 256, 256>>>(W_z, (__half*)p_wh + (size_t)CDIM * HIDN, VALD * HIDN / 4);

    // fused qkv+z projection (1-term fp16), N = 12288
    tc_gemm<<<dim3(MZD / 128, SEQ / 128), 256, GEMM_SMEM>>>(
        (const __half*)p_xh, (const __half*)p_wh, (float*)p_mz, MZD, HIDN);

    cvt_h<<<(HIDN * VALD / 4 + 255) / 256, 256>>>(W_out, (__half*)p_woh, HIDN * VALD / 4);
    cudaMemsetAsync(p_ab, 0, SEQ * 64 * sizeof(float));
    ab_gemm<<<dim3(SEQ / 64, 8), 256>>>(x, W_a, W_b);

    // conv + silu + fused l2norm
    conv_silu<<<dim3(CDIM / 256, SEQ / 8), 256>>>(conv_w);

    // gates
    gate_kernel<<<dim3(NVH, NCH), 64>>>(dt_bias, A_log);

    // intra-chunk precompute
    intra_kernel<<<dim3(NCH, NVH), 256, INTRA_SMEM>>>();

    // sequential inter-chunk scan (32 heads x 4 DV-slices)
    scan_kernel<<<NVH * 4, 512, SCAN_SMEM>>>();

    // rmsnorm + gate epilogue -> fp16
    rms_kernel<<<SEQ * NVH, 128>>>(norm_w);

    // output projection (1-term fp16)
    tc_gemm<<<dim3(HIDN / 128, SEQ / 128), 256, GEMM_SMEM>>>(
        (const __half*)p_yh, (const __half*)p_woh, out, HIDN, VALD);
}